// round 5
// baseline (speedup 1.0000x reference)
#include <cuda_runtime.h>
#include <math.h>

// Problem constants
#define VN   10000
#define VOUT 10001
#define EE   256
#define HH   512
#define G3   1536
#define BB   64
#define TT   128
#define NR   8192            // BB*TT
#define K_LOC_ELEMS ((size_t)NR * VN)   // 81,920,000 floats of location logits

// Persistent recurrence config
#define NCTA   128           // 32 gate-tiles x 4 K-chunks
#define GTILE  48            // gates per tile (1536/32)
#define KCHUNK 128           // K per chunk (512/4)

// Scratch (device globals; no allocations allowed)
__device__ float g_xp[(size_t)NR * G3];     // input-gate projections for current layer
__device__ float g_h [(size_t)NR * HH];     // layer output sequence (h1, then h2)
__device__ float g_state[BB * HH];          // recurrent state h_{t-1}
__device__ float g_ghp[4][BB * G3];         // split-K partials of h @ W_hh^T
__device__ unsigned g_bar_count;
__device__ unsigned g_bar_phase;

// ---------------------------------------------------------------------------
// Zero recurrent state + barrier bookkeeping (runs before each persistent launch)
// ---------------------------------------------------------------------------
__global__ void k_zero_state() {
    int i = blockIdx.x * blockDim.x + threadIdx.x;
    if (i < BB * HH) g_state[i] = 0.0f;
    if (i == 0) { g_bar_count = 0; g_bar_phase = 0; }
}

// ---------------------------------------------------------------------------
// Grid-wide sense barrier. All NCTA CTAs must be co-resident (128 <= 148 SMs).
// ---------------------------------------------------------------------------
__device__ __forceinline__ void grid_bar(unsigned gen) {
    __syncthreads();
    if (threadIdx.x == 0) {
        __threadfence();
        unsigned arr = atomicAdd(&g_bar_count, 1);
        if (arr == NCTA - 1) {
            atomicExch(&g_bar_count, 0);
            __threadfence();
            atomicExch(&g_bar_phase, gen + 1);
        } else {
            while (atomicAdd(&g_bar_phase, 0) < gen + 1) {}
        }
        __threadfence();
    }
    __syncthreads();
}

// ---------------------------------------------------------------------------
// Persistent GRU layer: all TT timesteps in one kernel.
// CTA (ntile, kc): GEMM partial over gates [ntile*48, +48), K chunk [kc*128, +128).
// Combine phase: thread (blockIdx*256+tid) owns exactly one state element.
// Dynamic smem: Ws[128][48] (whh tile, loaded once) + Ss[128][64] (state chunk).
// ---------------------------------------------------------------------------
__global__ void __launch_bounds__(256)
k_gru(const float* __restrict__ whh, const float* __restrict__ bhh)
{
    extern __shared__ float smem[];
    float* Ws = smem;                    // [128][48]  k-major
    float* Ss = smem + KCHUNK * GTILE;   // [128][64]  k-major

    const int tid   = threadIdx.x;
    const int ntile = blockIdx.x & 31;
    const int kc    = blockIdx.x >> 5;
    const int gbase = ntile * GTILE;
    const int kbase = kc * KCHUNK;

    // Cache whh tile once for all timesteps
    for (int i = tid; i < KCHUNK * GTILE; i += 256) {
        int k = i / GTILE, g = i % GTILE;
        Ws[k * GTILE + g] = whh[(size_t)(gbase + g) * HH + kbase + k];
    }

    const int ty = tid >> 4;     // 0..15 -> m base = ty*4
    const int tx = tid & 15;     // 0..15 -> n base = tx*3

    // combine-phase coordinates (1 element per thread)
    const int cidx = blockIdx.x * 256 + tid;    // 0..32767
    const int cb = cidx >> 9;                   // batch
    const int cj = cidx & 511;                  // hidden index

    unsigned gen = 0;

    for (int t = 0; t < TT; ++t) {
        // Load state chunk (written by combine of prev step, or zeroed) into smem
        for (int i = tid; i < KCHUNK * BB; i += 256) {
            int k = i >> 6, b = i & 63;
            Ss[k * BB + b] = __ldcg(&g_state[b * HH + kbase + k]);
        }
        __syncthreads();

        // GEMM partial: acc[m 4][n 3]
        float acc00=0,acc01=0,acc02=0, acc10=0,acc11=0,acc12=0,
              acc20=0,acc21=0,acc22=0, acc30=0,acc31=0,acc32=0;
        #pragma unroll 8
        for (int k = 0; k < KCHUNK; ++k) {
            float4 a = *reinterpret_cast<const float4*>(&Ss[k * BB + (ty << 2)]);
            float w0 = Ws[k * GTILE + tx * 3 + 0];
            float w1 = Ws[k * GTILE + tx * 3 + 1];
            float w2 = Ws[k * GTILE + tx * 3 + 2];
            acc00 += a.x * w0; acc01 += a.x * w1; acc02 += a.x * w2;
            acc10 += a.y * w0; acc11 += a.y * w1; acc12 += a.y * w2;
            acc20 += a.z * w0; acc21 += a.z * w1; acc22 += a.z * w2;
            acc30 += a.w * w0; acc31 += a.w * w1; acc32 += a.w * w2;
        }

        // Write partials
        {
            float* p0 = &g_ghp[kc][((ty << 2) + 0) * G3 + gbase + tx * 3];
            float* p1 = &g_ghp[kc][((ty << 2) + 1) * G3 + gbase + tx * 3];
            float* p2 = &g_ghp[kc][((ty << 2) + 2) * G3 + gbase + tx * 3];
            float* p3 = &g_ghp[kc][((ty << 2) + 3) * G3 + gbase + tx * 3];
            p0[0]=acc00; p0[1]=acc01; p0[2]=acc02;
            p1[0]=acc10; p1[1]=acc11; p1[2]=acc12;
            p2[0]=acc20; p2[1]=acc21; p2[2]=acc22;
            p3[0]=acc30; p3[1]=acc31; p3[2]=acc32;
        }

        grid_bar(gen); ++gen;

        // Combine + gate math + state update (1 element/thread)
        {
            const int base = cb * G3 + cj;
            float sr = __ldcg(&g_ghp[0][base])        + __ldcg(&g_ghp[1][base])
                     + __ldcg(&g_ghp[2][base])        + __ldcg(&g_ghp[3][base])        + bhh[cj];
            float sz = __ldcg(&g_ghp[0][base + 512])  + __ldcg(&g_ghp[1][base + 512])
                     + __ldcg(&g_ghp[2][base + 512])  + __ldcg(&g_ghp[3][base + 512])  + bhh[512 + cj];
            float sn = __ldcg(&g_ghp[0][base + 1024]) + __ldcg(&g_ghp[1][base + 1024])
                     + __ldcg(&g_ghp[2][base + 1024]) + __ldcg(&g_ghp[3][base + 1024]) + bhh[1024 + cj];

            const float* xp = g_xp + (size_t)(cb * TT + t) * G3;
            float r  = 1.0f / (1.0f + expf(-(xp[cj] + sr)));
            float z  = 1.0f / (1.0f + expf(-(xp[512 + cj] + sz)));
            float nn = tanhf(xp[1024 + cj] + r * sn);

            float hold = __ldcg(&g_state[cidx]);
            float hnew = (1.0f - z) * nn + z * hold;
            g_state[cidx] = hnew;
            g_h[(size_t)(cb * TT + t) * HH + cj] = hnew;
        }

        grid_bar(gen); ++gen;
    }
}

// ---------------------------------------------------------------------------
// proj0: g_xp[n,g] = sum_e emb[loc[n],e]*w0[g,e] + times[n]*w0[g,256] + b0[g]
// ---------------------------------------------------------------------------
__global__ void __launch_bounds__(256)
k_proj0(const int* __restrict__ loc, const float* __restrict__ times,
        const float* __restrict__ emb, const float* __restrict__ w0,
        const float* __restrict__ b0)
{
    __shared__ float As[16][64];
    __shared__ float Ws[16][64];
    __shared__ int   locs[64];
    __shared__ float ts[64];

    const int tid   = threadIdx.x;
    const int mtile = blockIdx.y * 64;
    const int ntile = blockIdx.x * 64;
    if (tid < 64) { locs[tid] = loc[mtile + tid]; ts[tid] = times[mtile + tid]; }
    __syncthreads();

    const int tx = tid & 15, ty = tid >> 4;
    const int lm = tid >> 2;
    const int lk = (tid & 3) << 2;
    const int arow = locs[lm];
    const float* wrowp = w0 + (size_t)(ntile + lm) * 257;

    float acc[4][4] = {};

    for (int kk = 0; kk < 256; kk += 16) {
        float4 av = *reinterpret_cast<const float4*>(emb + (size_t)arow * EE + kk + lk);
        float wv0 = wrowp[kk + lk + 0];
        float wv1 = wrowp[kk + lk + 1];
        float wv2 = wrowp[kk + lk + 2];
        float wv3 = wrowp[kk + lk + 3];
        __syncthreads();
        As[lk + 0][lm] = av.x; As[lk + 1][lm] = av.y; As[lk + 2][lm] = av.z; As[lk + 3][lm] = av.w;
        Ws[lk + 0][lm] = wv0;  Ws[lk + 1][lm] = wv1;  Ws[lk + 2][lm] = wv2;  Ws[lk + 3][lm] = wv3;
        __syncthreads();
        #pragma unroll
        for (int k = 0; k < 16; ++k) {
            float a[4], w[4];
            #pragma unroll
            for (int i = 0; i < 4; ++i) { a[i] = As[k][(ty << 2) + i]; w[i] = Ws[k][(tx << 2) + i]; }
            #pragma unroll
            for (int i = 0; i < 4; ++i)
                #pragma unroll
                for (int j = 0; j < 4; ++j) acc[i][j] += a[i] * w[j];
        }
    }

    #pragma unroll
    for (int i = 0; i < 4; ++i) {
        const int m = mtile + (ty << 2) + i;
        const float tm = ts[(ty << 2) + i];
        #pragma unroll
        for (int j = 0; j < 4; ++j) {
            const int g = ntile + (tx << 2) + j;
            g_xp[(size_t)m * G3 + g] = acc[i][j] + tm * w0[(size_t)g * 257 + 256] + b0[g];
        }
    }
}

// ---------------------------------------------------------------------------
// proj1: g_xp[n,g] = sum_k g_h[n,k]*w1[g,k] + b1[g]      (K = 512)
// ---------------------------------------------------------------------------
__global__ void __launch_bounds__(256)
k_proj1(const float* __restrict__ w1, const float* __restrict__ b1)
{
    __shared__ float As[16][64];
    __shared__ float Ws[16][64];

    const int tid   = threadIdx.x;
    const int mtile = blockIdx.y * 64;
    const int ntile = blockIdx.x * 64;
    const int tx = tid & 15, ty = tid >> 4;
    const int lm = tid >> 2;
    const int lk = (tid & 3) << 2;

    const float* arow = g_h + (size_t)(mtile + lm) * HH;
    const float* wrow = w1  + (size_t)(ntile + lm) * HH;

    float acc[4][4] = {};

    for (int kk = 0; kk < HH; kk += 16) {
        float4 av = *reinterpret_cast<const float4*>(arow + kk + lk);
        float4 wv = *reinterpret_cast<const float4*>(wrow + kk + lk);
        __syncthreads();
        As[lk + 0][lm] = av.x; As[lk + 1][lm] = av.y; As[lk + 2][lm] = av.z; As[lk + 3][lm] = av.w;
        Ws[lk + 0][lm] = wv.x; Ws[lk + 1][lm] = wv.y; Ws[lk + 2][lm] = wv.z; Ws[lk + 3][lm] = wv.w;
        __syncthreads();
        #pragma unroll
        for (int k = 0; k < 16; ++k) {
            float a[4], w[4];
            #pragma unroll
            for (int i = 0; i < 4; ++i) { a[i] = As[k][(ty << 2) + i]; w[i] = Ws[k][(tx << 2) + i]; }
            #pragma unroll
            for (int i = 0; i < 4; ++i)
                #pragma unroll
                for (int j = 0; j < 4; ++j) acc[i][j] += a[i] * w[j];
        }
    }

    #pragma unroll
    for (int i = 0; i < 4; ++i) {
        const int m = mtile + (ty << 2) + i;
        #pragma unroll
        for (int j = 0; j < 4; ++j) {
            const int g = ntile + (tx << 2) + j;
            g_xp[(size_t)m * G3 + g] = acc[i][j] + b1[g];
        }
    }
}

// ---------------------------------------------------------------------------
// FC: out[n,g] = relu(g_h[n,:]) . fc_w[g,:] + fc_b[g]
// ---------------------------------------------------------------------------
__global__ void __launch_bounds__(256)
k_fc(const float* __restrict__ fw, const float* __restrict__ fb,
     float* __restrict__ out)
{
    __shared__ float As[8][128];
    __shared__ float Ws[8][128];

    const int tid   = threadIdx.x;
    const int mtile = blockIdx.y * 128;
    const int ntile = blockIdx.x * 128;
    const int tx = tid & 15, ty = tid >> 4;
    const int lm = tid >> 1;
    const int lk = (tid & 1) << 2;

    const float* arow = g_h + (size_t)(mtile + lm) * HH;
    const int gl = ntile + lm;
    const bool wok = (gl < VOUT);
    const float* wrow = fw + (size_t)(wok ? gl : 0) * HH;

    float acc[8][8] = {};

    for (int kk = 0; kk < HH; kk += 8) {
        float4 av = *reinterpret_cast<const float4*>(arow + kk + lk);
        float4 wv = *reinterpret_cast<const float4*>(wrow + kk + lk);
        if (!wok) { wv.x = 0.f; wv.y = 0.f; wv.z = 0.f; wv.w = 0.f; }
        __syncthreads();
        As[lk + 0][lm] = fmaxf(av.x, 0.f);
        As[lk + 1][lm] = fmaxf(av.y, 0.f);
        As[lk + 2][lm] = fmaxf(av.z, 0.f);
        As[lk + 3][lm] = fmaxf(av.w, 0.f);
        Ws[lk + 0][lm] = wv.x; Ws[lk + 1][lm] = wv.y; Ws[lk + 2][lm] = wv.z; Ws[lk + 3][lm] = wv.w;
        __syncthreads();
        #pragma unroll
        for (int k = 0; k < 8; ++k) {
            float a[8], w[8];
            #pragma unroll
            for (int i = 0; i < 8; ++i) a[i] = As[k][(ty << 3) + i];
            #pragma unroll
            for (int j = 0; j < 8; ++j) w[j] = Ws[k][(tx << 3) + j];
            #pragma unroll
            for (int i = 0; i < 8; ++i)
                #pragma unroll
                for (int j = 0; j < 8; ++j) acc[i][j] += a[i] * w[j];
        }
    }

    #pragma unroll
    for (int i = 0; i < 8; ++i) {
        const int m = mtile + (ty << 3) + i;
        #pragma unroll
        for (int j = 0; j < 8; ++j) {
            const int g = ntile + (tx << 3) + j;
            if (g < VOUT) {
                float c = acc[i][j] + fb[g];
                if (g < VN) out[(size_t)m * VN + g] = c;
                else        out[K_LOC_ELEMS + m] = c;    // raw time logit
            }
        }
    }
}

// ---------------------------------------------------------------------------
// Softmax: per-row log_softmax (row cached in smem) + time sigmoid.
// ---------------------------------------------------------------------------
__global__ void __launch_bounds__(256)
k_softmax(float* __restrict__ out)
{
    extern __shared__ float row[];       // VN floats
    __shared__ float red[256];

    const int n = blockIdx.x;
    const int tid = threadIdx.x;
    float* base = out + (size_t)n * VN;

    float mx = -1e30f;
    for (int i = tid; i < VN; i += 256) { float v = base[i]; row[i] = v; mx = fmaxf(mx, v); }
    red[tid] = mx; __syncthreads();
    for (int s = 128; s > 0; s >>= 1) { if (tid < s) red[tid] = fmaxf(red[tid], red[tid + s]); __syncthreads(); }
    mx = red[0];
    __syncthreads();

    float sum = 0.f;
    for (int i = tid; i < VN; i += 256) sum += expf(row[i] - mx);
    red[tid] = sum; __syncthreads();
    for (int s = 128; s > 0; s >>= 1) { if (tid < s) red[tid] += red[tid + s]; __syncthreads(); }
    float lse = mx + logf(red[0]);

    for (int i = tid; i < VN; i += 256) base[i] = row[i] - lse;

    if (tid == 0) {
        float tl = out[K_LOC_ELEMS + n];
        out[K_LOC_ELEMS + n] = 1.0f / (1.0f + expf(-tl));
    }
}

// ---------------------------------------------------------------------------
// Launch
// ---------------------------------------------------------------------------
extern "C" void kernel_launch(void* const* d_in, const int* in_sizes, int n_in,
                              void* d_out, int out_size)
{
    const int*   loc   = (const int*)  d_in[0];
    const float* times = (const float*)d_in[1];
    const float* emb   = (const float*)d_in[2];
    const float* w_ih0 = (const float*)d_in[3];
    const float* w_hh0 = (const float*)d_in[4];
    const float* b_ih0 = (const float*)d_in[5];
    const float* b_hh0 = (const float*)d_in[6];
    const float* w_ih1 = (const float*)d_in[7];
    const float* w_hh1 = (const float*)d_in[8];
    const float* b_ih1 = (const float*)d_in[9];
    const float* b_hh1 = (const float*)d_in[10];
    const float* fc_w  = (const float*)d_in[11];
    const float* fc_b  = (const float*)d_in[12];
    float* out = (float*)d_out;

    const int gru_smem = (KCHUNK * GTILE + KCHUNK * BB) * sizeof(float);  // 56 KB
    static int attr_done = 0;
    if (!attr_done) {
        cudaFuncSetAttribute(k_gru, cudaFuncAttributeMaxDynamicSharedMemorySize, gru_smem);
        attr_done = 1;
    }

    // Layer 0
    k_proj0<<<dim3(G3 / 64, NR / 64), 256>>>(loc, times, emb, w_ih0, b_ih0);
    k_zero_state<<<(BB * HH + 255) / 256, 256>>>();
    k_gru<<<NCTA, 256, gru_smem>>>(w_hh0, b_hh0);

    // Layer 1
    k_proj1<<<dim3(G3 / 64, NR / 64), 256>>>(w_ih1, b_ih1);
    k_zero_state<<<(BB * HH + 255) / 256, 256>>>();
    k_gru<<<NCTA, 256, gru_smem>>>(w_hh1, b_hh1);

    // FC -> logits straight into d_out
    k_fc<<<dim3((VOUT + 127) / 128, NR / 128), 256>>>(fc_w, fc_b, out);

    // log_softmax + time sigmoid
    k_softmax<<<NR, 256, VN * sizeof(float)>>>(out);
}

// round 6
// speedup vs baseline: 1.0213x; 1.0213x over previous
#include <cuda_runtime.h>
#include <math.h>

// Problem constants
#define VN   10000
#define VOUT 10001
#define EE   256
#define HH   512
#define G3   1536
#define BB   64
#define TT   128
#define NR   8192            // BB*TT
#define K_LOC_ELEMS ((size_t)NR * VN)   // 81,920,000 floats of location logits

// Persistent recurrence config
#define NCTA   128           // 32 gate-tiles x 4 K-chunks
#define GTILE  48            // gates per tile (1536/32)
#define KCHUNK 128           // K per chunk (512/4)

// Scratch (device globals; no allocations allowed)
__device__ float g_xp[(size_t)NR * G3];     // input-gate projections for current layer
__device__ float g_h [(size_t)NR * HH];     // layer output sequence (h1, then h2)
__device__ float g_state[BB * HH];          // recurrent state h_{t-1}
__device__ float g_ghp[4][BB * G3];         // split-K partials of h @ W_hh^T
__device__ unsigned g_bar_count;
__device__ volatile unsigned g_bar_phase;

// ---------------------------------------------------------------------------
// Zero recurrent state + barrier bookkeeping (runs before each persistent launch)
// ---------------------------------------------------------------------------
__global__ void k_zero_state() {
    int i = blockIdx.x * blockDim.x + threadIdx.x;
    if (i < BB * HH) g_state[i] = 0.0f;
    if (i == 0) { g_bar_count = 0; g_bar_phase = 0; }
}

// ---------------------------------------------------------------------------
// Grid-wide barrier: arrive = single atomicAdd per CTA; wait = PLAIN LOAD poll
// (no atomic-RMW polling -> no LTS atomic-ALU serialization). All NCTA CTAs
// are co-resident (128 CTAs, 56KB smem, 1/SM on a 148-SM part).
// ---------------------------------------------------------------------------
__device__ __forceinline__ void grid_bar(unsigned gen) {
    __syncthreads();
    if (threadIdx.x == 0) {
        __threadfence();                               // flush my writes to L2
        unsigned arr = atomicAdd(&g_bar_count, 1);
        if (arr == NCTA - 1) {
            atomicExch(&g_bar_count, 0);               // reset before release
            __threadfence();
            g_bar_phase = gen + 1;                     // plain release store
        } else {
            while (g_bar_phase < gen + 1) { }          // read-only poll (L2 hit)
        }
        __threadfence();                               // order subsequent reads
    }
    __syncthreads();
}

// ---------------------------------------------------------------------------
// Persistent GRU layer: all TT timesteps in one kernel.
// CTA (ntile, kc): GEMM partial over gates [ntile*48, +48), K chunk [kc*128, +128).
// Combine phase: thread (blockIdx*256+tid) owns exactly one state element.
// Dynamic smem: Ws[128][48] (whh tile, loaded once) + Ss[128][64] (state chunk).
// ---------------------------------------------------------------------------
__global__ void __launch_bounds__(256)
k_gru(const float* __restrict__ whh, const float* __restrict__ bhh)
{
    extern __shared__ float smem[];
    float* Ws = smem;                    // [128][48]  k-major
    float* Ss = smem + KCHUNK * GTILE;   // [128][64]  k-major

    const int tid   = threadIdx.x;
    const int ntile = blockIdx.x & 31;
    const int kc    = blockIdx.x >> 5;
    const int gbase = ntile * GTILE;
    const int kbase = kc * KCHUNK;

    // Cache whh tile once for all timesteps
    for (int i = tid; i < KCHUNK * GTILE; i += 256) {
        int k = i / GTILE, g = i % GTILE;
        Ws[k * GTILE + g] = whh[(size_t)(gbase + g) * HH + kbase + k];
    }

    const int ty = tid >> 4;     // 0..15 -> m base = ty*4
    const int tx = tid & 15;     // 0..15 -> n base = tx*3

    // combine-phase coordinates (1 element per thread)
    const int cidx = blockIdx.x * 256 + tid;    // 0..32767
    const int cb = cidx >> 9;                   // batch
    const int cj = cidx & 511;                  // hidden index

    unsigned gen = 0;

    for (int t = 0; t < TT; ++t) {
        // Load state chunk (written by combine of prev step, or zeroed) into smem
        for (int i = tid; i < KCHUNK * BB; i += 256) {
            int k = i >> 6, b = i & 63;
            Ss[k * BB + b] = __ldcg(&g_state[b * HH + kbase + k]);
        }
        __syncthreads();

        // GEMM partial: acc[m 4][n 3]
        float acc00=0,acc01=0,acc02=0, acc10=0,acc11=0,acc12=0,
              acc20=0,acc21=0,acc22=0, acc30=0,acc31=0,acc32=0;
        #pragma unroll 8
        for (int k = 0; k < KCHUNK; ++k) {
            float4 a = *reinterpret_cast<const float4*>(&Ss[k * BB + (ty << 2)]);
            float w0 = Ws[k * GTILE + tx * 3 + 0];
            float w1 = Ws[k * GTILE + tx * 3 + 1];
            float w2 = Ws[k * GTILE + tx * 3 + 2];
            acc00 += a.x * w0; acc01 += a.x * w1; acc02 += a.x * w2;
            acc10 += a.y * w0; acc11 += a.y * w1; acc12 += a.y * w2;
            acc20 += a.z * w0; acc21 += a.z * w1; acc22 += a.z * w2;
            acc30 += a.w * w0; acc31 += a.w * w1; acc32 += a.w * w2;
        }

        // Write partials
        {
            float* p0 = &g_ghp[kc][((ty << 2) + 0) * G3 + gbase + tx * 3];
            float* p1 = &g_ghp[kc][((ty << 2) + 1) * G3 + gbase + tx * 3];
            float* p2 = &g_ghp[kc][((ty << 2) + 2) * G3 + gbase + tx * 3];
            float* p3 = &g_ghp[kc][((ty << 2) + 3) * G3 + gbase + tx * 3];
            p0[0]=acc00; p0[1]=acc01; p0[2]=acc02;
            p1[0]=acc10; p1[1]=acc11; p1[2]=acc12;
            p2[0]=acc20; p2[1]=acc21; p2[2]=acc22;
            p3[0]=acc30; p3[1]=acc31; p3[2]=acc32;
        }

        grid_bar(gen); ++gen;

        // Combine + gate math + state update (1 element/thread)
        {
            const int base = cb * G3 + cj;
            float sr = __ldcg(&g_ghp[0][base])        + __ldcg(&g_ghp[1][base])
                     + __ldcg(&g_ghp[2][base])        + __ldcg(&g_ghp[3][base])        + bhh[cj];
            float sz = __ldcg(&g_ghp[0][base + 512])  + __ldcg(&g_ghp[1][base + 512])
                     + __ldcg(&g_ghp[2][base + 512])  + __ldcg(&g_ghp[3][base + 512])  + bhh[512 + cj];
            float sn = __ldcg(&g_ghp[0][base + 1024]) + __ldcg(&g_ghp[1][base + 1024])
                     + __ldcg(&g_ghp[2][base + 1024]) + __ldcg(&g_ghp[3][base + 1024]) + bhh[1024 + cj];

            const float* xp = g_xp + (size_t)(cb * TT + t) * G3;
            float r  = 1.0f / (1.0f + expf(-(xp[cj] + sr)));
            float z  = 1.0f / (1.0f + expf(-(xp[512 + cj] + sz)));
            float nn = tanhf(xp[1024 + cj] + r * sn);

            float hold = __ldcg(&g_state[cidx]);
            float hnew = (1.0f - z) * nn + z * hold;
            g_state[cidx] = hnew;
            g_h[(size_t)(cb * TT + t) * HH + cj] = hnew;
        }

        grid_bar(gen); ++gen;
    }
}

// ---------------------------------------------------------------------------
// proj0: g_xp[n,g] = sum_e emb[loc[n],e]*w0[g,e] + times[n]*w0[g,256] + b0[g]
// ---------------------------------------------------------------------------
__global__ void __launch_bounds__(256)
k_proj0(const int* __restrict__ loc, const float* __restrict__ times,
        const float* __restrict__ emb, const float* __restrict__ w0,
        const float* __restrict__ b0)
{
    __shared__ float As[16][64];
    __shared__ float Ws[16][64];
    __shared__ int   locs[64];
    __shared__ float ts[64];

    const int tid   = threadIdx.x;
    const int mtile = blockIdx.y * 64;
    const int ntile = blockIdx.x * 64;
    if (tid < 64) { locs[tid] = loc[mtile + tid]; ts[tid] = times[mtile + tid]; }
    __syncthreads();

    const int tx = tid & 15, ty = tid >> 4;
    const int lm = tid >> 2;
    const int lk = (tid & 3) << 2;
    const int arow = locs[lm];
    const float* wrowp = w0 + (size_t)(ntile + lm) * 257;

    float acc[4][4] = {};

    for (int kk = 0; kk < 256; kk += 16) {
        float4 av = *reinterpret_cast<const float4*>(emb + (size_t)arow * EE + kk + lk);
        float wv0 = wrowp[kk + lk + 0];
        float wv1 = wrowp[kk + lk + 1];
        float wv2 = wrowp[kk + lk + 2];
        float wv3 = wrowp[kk + lk + 3];
        __syncthreads();
        As[lk + 0][lm] = av.x; As[lk + 1][lm] = av.y; As[lk + 2][lm] = av.z; As[lk + 3][lm] = av.w;
        Ws[lk + 0][lm] = wv0;  Ws[lk + 1][lm] = wv1;  Ws[lk + 2][lm] = wv2;  Ws[lk + 3][lm] = wv3;
        __syncthreads();
        #pragma unroll
        for (int k = 0; k < 16; ++k) {
            float a[4], w[4];
            #pragma unroll
            for (int i = 0; i < 4; ++i) { a[i] = As[k][(ty << 2) + i]; w[i] = Ws[k][(tx << 2) + i]; }
            #pragma unroll
            for (int i = 0; i < 4; ++i)
                #pragma unroll
                for (int j = 0; j < 4; ++j) acc[i][j] += a[i] * w[j];
        }
    }

    #pragma unroll
    for (int i = 0; i < 4; ++i) {
        const int m = mtile + (ty << 2) + i;
        const float tm = ts[(ty << 2) + i];
        #pragma unroll
        for (int j = 0; j < 4; ++j) {
            const int g = ntile + (tx << 2) + j;
            g_xp[(size_t)m * G3 + g] = acc[i][j] + tm * w0[(size_t)g * 257 + 256] + b0[g];
        }
    }
}

// ---------------------------------------------------------------------------
// proj1: g_xp[n,g] = sum_k g_h[n,k]*w1[g,k] + b1[g]      (K = 512)
// ---------------------------------------------------------------------------
__global__ void __launch_bounds__(256)
k_proj1(const float* __restrict__ w1, const float* __restrict__ b1)
{
    __shared__ float As[16][64];
    __shared__ float Ws[16][64];

    const int tid   = threadIdx.x;
    const int mtile = blockIdx.y * 64;
    const int ntile = blockIdx.x * 64;
    const int tx = tid & 15, ty = tid >> 4;
    const int lm = tid >> 2;
    const int lk = (tid & 3) << 2;

    const float* arow = g_h + (size_t)(mtile + lm) * HH;
    const float* wrow = w1  + (size_t)(ntile + lm) * HH;

    float acc[4][4] = {};

    for (int kk = 0; kk < HH; kk += 16) {
        float4 av = *reinterpret_cast<const float4*>(arow + kk + lk);
        float4 wv = *reinterpret_cast<const float4*>(wrow + kk + lk);
        __syncthreads();
        As[lk + 0][lm] = av.x; As[lk + 1][lm] = av.y; As[lk + 2][lm] = av.z; As[lk + 3][lm] = av.w;
        Ws[lk + 0][lm] = wv.x; Ws[lk + 1][lm] = wv.y; Ws[lk + 2][lm] = wv.z; Ws[lk + 3][lm] = wv.w;
        __syncthreads();
        #pragma unroll
        for (int k = 0; k < 16; ++k) {
            float a[4], w[4];
            #pragma unroll
            for (int i = 0; i < 4; ++i) { a[i] = As[k][(ty << 2) + i]; w[i] = Ws[k][(tx << 2) + i]; }
            #pragma unroll
            for (int i = 0; i < 4; ++i)
                #pragma unroll
                for (int j = 0; j < 4; ++j) acc[i][j] += a[i] * w[j];
        }
    }

    #pragma unroll
    for (int i = 0; i < 4; ++i) {
        const int m = mtile + (ty << 2) + i;
        #pragma unroll
        for (int j = 0; j < 4; ++j) {
            const int g = ntile + (tx << 2) + j;
            g_xp[(size_t)m * G3 + g] = acc[i][j] + b1[g];
        }
    }
}

// ---------------------------------------------------------------------------
// FC: out[n,g] = relu(g_h[n,:]) . fc_w[g,:] + fc_b[g]
// ---------------------------------------------------------------------------
__global__ void __launch_bounds__(256)
k_fc(const float* __restrict__ fw, const float* __restrict__ fb,
     float* __restrict__ out)
{
    __shared__ float As[8][128];
    __shared__ float Ws[8][128];

    const int tid   = threadIdx.x;
    const int mtile = blockIdx.y * 128;
    const int ntile = blockIdx.x * 128;
    const int tx = tid & 15, ty = tid >> 4;
    const int lm = tid >> 1;
    const int lk = (tid & 1) << 2;

    const float* arow = g_h + (size_t)(mtile + lm) * HH;
    const int gl = ntile + lm;
    const bool wok = (gl < VOUT);
    const float* wrow = fw + (size_t)(wok ? gl : 0) * HH;

    float acc[8][8] = {};

    for (int kk = 0; kk < HH; kk += 8) {
        float4 av = *reinterpret_cast<const float4*>(arow + kk + lk);
        float4 wv = *reinterpret_cast<const float4*>(wrow + kk + lk);
        if (!wok) { wv.x = 0.f; wv.y = 0.f; wv.z = 0.f; wv.w = 0.f; }
        __syncthreads();
        As[lk + 0][lm] = fmaxf(av.x, 0.f);
        As[lk + 1][lm] = fmaxf(av.y, 0.f);
        As[lk + 2][lm] = fmaxf(av.z, 0.f);
        As[lk + 3][lm] = fmaxf(av.w, 0.f);
        Ws[lk + 0][lm] = wv.x; Ws[lk + 1][lm] = wv.y; Ws[lk + 2][lm] = wv.z; Ws[lk + 3][lm] = wv.w;
        __syncthreads();
        #pragma unroll
        for (int k = 0; k < 8; ++k) {
            float a[8], w[8];
            #pragma unroll
            for (int i = 0; i < 8; ++i) a[i] = As[k][(ty << 3) + i];
            #pragma unroll
            for (int j = 0; j < 8; ++j) w[j] = Ws[k][(tx << 3) + j];
            #pragma unroll
            for (int i = 0; i < 8; ++i)
                #pragma unroll
                for (int j = 0; j < 8; ++j) acc[i][j] += a[i] * w[j];
        }
    }

    #pragma unroll
    for (int i = 0; i < 8; ++i) {
        const int m = mtile + (ty << 3) + i;
        #pragma unroll
        for (int j = 0; j < 8; ++j) {
            const int g = ntile + (tx << 3) + j;
            if (g < VOUT) {
                float c = acc[i][j] + fb[g];
                if (g < VN) out[(size_t)m * VN + g] = c;
                else        out[K_LOC_ELEMS + m] = c;    // raw time logit
            }
        }
    }
}

// ---------------------------------------------------------------------------
// Softmax: per-row log_softmax (row cached in smem) + time sigmoid.
// ---------------------------------------------------------------------------
__global__ void __launch_bounds__(256)
k_softmax(float* __restrict__ out)
{
    extern __shared__ float row[];       // VN floats
    __shared__ float red[256];

    const int n = blockIdx.x;
    const int tid = threadIdx.x;
    float* base = out + (size_t)n * VN;

    float mx = -1e30f;
    for (int i = tid; i < VN; i += 256) { float v = base[i]; row[i] = v; mx = fmaxf(mx, v); }
    red[tid] = mx; __syncthreads();
    for (int s = 128; s > 0; s >>= 1) { if (tid < s) red[tid] = fmaxf(red[tid], red[tid + s]); __syncthreads(); }
    mx = red[0];
    __syncthreads();

    float sum = 0.f;
    for (int i = tid; i < VN; i += 256) sum += expf(row[i] - mx);
    red[tid] = sum; __syncthreads();
    for (int s = 128; s > 0; s >>= 1) { if (tid < s) red[tid] += red[tid + s]; __syncthreads(); }
    float lse = mx + logf(red[0]);

    for (int i = tid; i < VN; i += 256) base[i] = row[i] - lse;

    if (tid == 0) {
        float tl = out[K_LOC_ELEMS + n];
        out[K_LOC_ELEMS + n] = 1.0f / (1.0f + expf(-tl));
    }
}

// ---------------------------------------------------------------------------
// Launch
// ---------------------------------------------------------------------------
extern "C" void kernel_launch(void* const* d_in, const int* in_sizes, int n_in,
                              void* d_out, int out_size)
{
    const int*   loc   = (const int*)  d_in[0];
    const float* times = (const float*)d_in[1];
    const float* emb   = (const float*)d_in[2];
    const float* w_ih0 = (const float*)d_in[3];
    const float* w_hh0 = (const float*)d_in[4];
    const float* b_ih0 = (const float*)d_in[5];
    const float* b_hh0 = (const float*)d_in[6];
    const float* w_ih1 = (const float*)d_in[7];
    const float* w_hh1 = (const float*)d_in[8];
    const float* b_ih1 = (const float*)d_in[9];
    const float* b_hh1 = (const float*)d_in[10];
    const float* fc_w  = (const float*)d_in[11];
    const float* fc_b  = (const float*)d_in[12];
    float* out = (float*)d_out;

    const int gru_smem = (KCHUNK * GTILE + KCHUNK * BB) * sizeof(float);  // 56 KB
    static int attr_done = 0;
    if (!attr_done) {
        cudaFuncSetAttribute(k_gru, cudaFuncAttributeMaxDynamicSharedMemorySize, gru_smem);
        attr_done = 1;
    }

    // Layer 0
    k_proj0<<<dim3(G3 / 64, NR / 64), 256>>>(loc, times, emb, w_ih0, b_ih0);
    k_zero_state<<<(BB * HH + 255) / 256, 256>>>();
    k_gru<<<NCTA, 256, gru_smem>>>(w_hh0, b_hh0);

    // Layer 1
    k_proj1<<<dim3(G3 / 64, NR / 64), 256>>>(w_ih1, b_ih1);
    k_zero_state<<<(BB * HH + 255) / 256, 256>>>();
    k_gru<<<NCTA, 256, gru_smem>>>(w_hh1, b_hh1);

    // FC -> logits straight into d_out
    k_fc<<<dim3((VOUT + 127) / 128, NR / 128), 256>>>(fc_w, fc_b, out);

    // log_softmax + time sigmoid
    k_softmax<<<NR, 256, VN * sizeof(float)>>>(out);
}

// round 7
// speedup vs baseline: 1.4803x; 1.4493x over previous
#include <cuda_runtime.h>
#include <math.h>

// Problem constants
#define VN   10000
#define VOUT 10001
#define EE   256
#define HH   512
#define G3   1536
#define BB   64
#define TT   128
#define NR   8192            // BB*TT
#define K_LOC_ELEMS ((size_t)NR * VN)   // 81,920,000 floats of location logits

// Persistent recurrence config
#define NCTA 128             // one CTA per 4 hidden dims
#define JH   4               // hidden dims per CTA
#define NG   12              // gate rows per CTA (r,z,n per hidden dim)

// Scratch (device globals; no allocations allowed)
__device__ float g_xp[(size_t)NR * G3];     // input-gate projections for current layer
__device__ float g_h [(size_t)NR * HH];     // layer output sequence (h1, then h2)
__device__ float g_stateT[HH * BB];         // recurrent state, TRANSPOSED [j][b]
__device__ __align__(128) unsigned g_epoch[32];   // [0] = barrier epoch counter

// ---------------------------------------------------------------------------
// Zero recurrent state + barrier epoch (runs before each persistent launch)
// ---------------------------------------------------------------------------
__global__ void k_zero_state() {
    int i = blockIdx.x * blockDim.x + threadIdx.x;
    if (i < HH * BB) g_stateT[i] = 0.0f;
    if (i == 0) g_epoch[0] = 0;
}

// ---------------------------------------------------------------------------
// Grid-wide barrier, monotonic epoch: arrive once, poll with plain volatile
// load. All NCTA CTAs co-resident (1/SM, 164KB smem).
// ---------------------------------------------------------------------------
__device__ __forceinline__ void grid_epoch_bar(unsigned target) {
    __syncthreads();
    if (threadIdx.x == 0) {
        __threadfence();                               // my CTA's stores -> visible
        atomicAdd(&g_epoch[0], 1u);
        while (*((volatile unsigned*)&g_epoch[0]) < target) { }
        __threadfence();
    }
    __syncthreads();
}

// ---------------------------------------------------------------------------
// Persistent GRU layer, ONE grid barrier per timestep.
// CTA c owns hidden dims [c*4, c*4+4) -> 12 gate rows over full K=512.
// Smem: Ss[512][64] full state (128KB), Ws[12][512] weights (24KB, loaded
// once), Rs[4][12][64] k-chunk partials (12KB). Total 164KB.
// ---------------------------------------------------------------------------
__global__ void __launch_bounds__(256)
k_gru(const float* __restrict__ whh, const float* __restrict__ bhh)
{
    extern __shared__ float smem[];
    float* Ss = smem;                      // [512][64]  state, k-major rows of 64
    float* Ws = Ss + HH * BB;              // [12][512]
    float* Rs = Ws + NG * HH;              // [4][12][64]

    const int tid = threadIdx.x;
    const int cta = blockIdx.x;
    const int j0  = cta * JH;              // global hidden base

    // Load weight tile once: row g -> (j = j0 + g/3, gate = g%3)
    for (int i = tid; i < NG * HH; i += 256) {
        const int g = i >> 9, k = i & 511;
        const int jg = j0 + g / 3;
        const int gate = g - (g / 3) * 3;
        Ws[i] = whh[(size_t)(gate * 512 + jg) * HH + k];
    }

    // GEMM thread coords: kc (K chunk), gt (gate triple), bq (batch quad)
    const int kc = tid >> 6;               // 0..3
    const int gt = (tid >> 4) & 3;         // 0..3
    const int bq = tid & 15;               // 0..15

    // Gate-phase coords: one (j, b) element per thread
    const int gj = tid >> 6;               // 0..3   local hidden dim
    const int gb = tid & 63;               // 0..63  batch
    const int gjg = j0 + gj;

    unsigned target = NCTA;

    for (int t = 0; t < TT; ++t) {
        // --- Gather full transposed state into smem (coalesced float4) ---
        for (int i = tid; i < (HH * BB) / 4; i += 256) {
            float4 v = __ldcg((const float4*)g_stateT + i);
            ((float4*)Ss)[i] = v;
        }
        __syncthreads();

        // --- GEMM partial: (3 gates x 4 batches) over K chunk of 128 ---
        float a00=0,a01=0,a02=0,a03=0,
              a10=0,a11=0,a12=0,a13=0,
              a20=0,a21=0,a22=0,a23=0;
        {
            const float* w0p = &Ws[(gt * 3 + 0) * HH + kc * 128];
            const float* w1p = &Ws[(gt * 3 + 1) * HH + kc * 128];
            const float* w2p = &Ws[(gt * 3 + 2) * HH + kc * 128];
            const float* sp  = &Ss[(kc * 128) * BB + bq * 4];
            #pragma unroll 8
            for (int kk = 0; kk < 128; ++kk) {
                float4 a = *reinterpret_cast<const float4*>(sp + kk * BB);
                float w0 = w0p[kk], w1 = w1p[kk], w2 = w2p[kk];
                a00 += w0 * a.x; a01 += w0 * a.y; a02 += w0 * a.z; a03 += w0 * a.w;
                a10 += w1 * a.x; a11 += w1 * a.y; a12 += w1 * a.z; a13 += w1 * a.w;
                a20 += w2 * a.x; a21 += w2 * a.y; a22 += w2 * a.z; a23 += w2 * a.w;
            }
        }
        // store partials
        {
            float* r0 = &Rs[(kc * NG + gt * 3 + 0) * BB + bq * 4];
            float* r1 = &Rs[(kc * NG + gt * 3 + 1) * BB + bq * 4];
            float* r2 = &Rs[(kc * NG + gt * 3 + 2) * BB + bq * 4];
            r0[0]=a00; r0[1]=a01; r0[2]=a02; r0[3]=a03;
            r1[0]=a10; r1[1]=a11; r1[2]=a12; r1[3]=a13;
            r2[0]=a20; r2[1]=a21; r2[2]=a22; r2[3]=a23;
        }
        __syncthreads();

        // --- Gate math: one state element (gjg, gb) per thread ---
        {
            float sr = Rs[(0*NG + gj*3 + 0)*BB + gb] + Rs[(1*NG + gj*3 + 0)*BB + gb]
                     + Rs[(2*NG + gj*3 + 0)*BB + gb] + Rs[(3*NG + gj*3 + 0)*BB + gb]
                     + bhh[gjg];
            float sz = Rs[(0*NG + gj*3 + 1)*BB + gb] + Rs[(1*NG + gj*3 + 1)*BB + gb]
                     + Rs[(2*NG + gj*3 + 1)*BB + gb] + Rs[(3*NG + gj*3 + 1)*BB + gb]
                     + bhh[512 + gjg];
            float sn = Rs[(0*NG + gj*3 + 2)*BB + gb] + Rs[(1*NG + gj*3 + 2)*BB + gb]
                     + Rs[(2*NG + gj*3 + 2)*BB + gb] + Rs[(3*NG + gj*3 + 2)*BB + gb]
                     + bhh[1024 + gjg];

            const float* xp = g_xp + (size_t)(gb * TT + t) * G3;
            float r  = 1.0f / (1.0f + expf(-(__ldg(&xp[gjg])        + sr)));
            float z  = 1.0f / (1.0f + expf(-(__ldg(&xp[512 + gjg])  + sz)));
            float nn = tanhf(__ldg(&xp[1024 + gjg]) + r * sn);

            float hold = Ss[gjg * BB + gb];          // old state, already in smem
            float hnew = (1.0f - z) * nn + z * hold;
            g_stateT[cta * 256 + tid] = hnew;        // == [gjg][gb], coalesced
            g_h[(size_t)(gb * TT + t) * HH + gjg] = hnew;
        }

        grid_epoch_bar(target);
        target += NCTA;
    }
}

// ---------------------------------------------------------------------------
// proj0: g_xp[n,g] = sum_e emb[loc[n],e]*w0[g,e] + times[n]*w0[g,256] + b0[g]
// ---------------------------------------------------------------------------
__global__ void __launch_bounds__(256)
k_proj0(const int* __restrict__ loc, const float* __restrict__ times,
        const float* __restrict__ emb, const float* __restrict__ w0,
        const float* __restrict__ b0)
{
    __shared__ float As[16][64];
    __shared__ float Ws[16][64];
    __shared__ int   locs[64];
    __shared__ float ts[64];

    const int tid   = threadIdx.x;
    const int mtile = blockIdx.y * 64;
    const int ntile = blockIdx.x * 64;
    if (tid < 64) { locs[tid] = loc[mtile + tid]; ts[tid] = times[mtile + tid]; }
    __syncthreads();

    const int tx = tid & 15, ty = tid >> 4;
    const int lm = tid >> 2;
    const int lk = (tid & 3) << 2;
    const int arow = locs[lm];
    const float* wrowp = w0 + (size_t)(ntile + lm) * 257;

    float acc[4][4] = {};

    for (int kk = 0; kk < 256; kk += 16) {
        float4 av = *reinterpret_cast<const float4*>(emb + (size_t)arow * EE + kk + lk);
        float wv0 = wrowp[kk + lk + 0];
        float wv1 = wrowp[kk + lk + 1];
        float wv2 = wrowp[kk + lk + 2];
        float wv3 = wrowp[kk + lk + 3];
        __syncthreads();
        As[lk + 0][lm] = av.x; As[lk + 1][lm] = av.y; As[lk + 2][lm] = av.z; As[lk + 3][lm] = av.w;
        Ws[lk + 0][lm] = wv0;  Ws[lk + 1][lm] = wv1;  Ws[lk + 2][lm] = wv2;  Ws[lk + 3][lm] = wv3;
        __syncthreads();
        #pragma unroll
        for (int k = 0; k < 16; ++k) {
            float a[4], w[4];
            #pragma unroll
            for (int i = 0; i < 4; ++i) { a[i] = As[k][(ty << 2) + i]; w[i] = Ws[k][(tx << 2) + i]; }
            #pragma unroll
            for (int i = 0; i < 4; ++i)
                #pragma unroll
                for (int j = 0; j < 4; ++j) acc[i][j] += a[i] * w[j];
        }
    }

    #pragma unroll
    for (int i = 0; i < 4; ++i) {
        const int m = mtile + (ty << 2) + i;
        const float tm = ts[(ty << 2) + i];
        #pragma unroll
        for (int j = 0; j < 4; ++j) {
            const int g = ntile + (tx << 2) + j;
            g_xp[(size_t)m * G3 + g] = acc[i][j] + tm * w0[(size_t)g * 257 + 256] + b0[g];
        }
    }
}

// ---------------------------------------------------------------------------
// proj1: g_xp[n,g] = sum_k g_h[n,k]*w1[g,k] + b1[g]      (K = 512)
// ---------------------------------------------------------------------------
__global__ void __launch_bounds__(256)
k_proj1(const float* __restrict__ w1, const float* __restrict__ b1)
{
    __shared__ float As[16][64];
    __shared__ float Ws[16][64];

    const int tid   = threadIdx.x;
    const int mtile = blockIdx.y * 64;
    const int ntile = blockIdx.x * 64;
    const int tx = tid & 15, ty = tid >> 4;
    const int lm = tid >> 2;
    const int lk = (tid & 3) << 2;

    const float* arow = g_h + (size_t)(mtile + lm) * HH;
    const float* wrow = w1  + (size_t)(ntile + lm) * HH;

    float acc[4][4] = {};

    for (int kk = 0; kk < HH; kk += 16) {
        float4 av = *reinterpret_cast<const float4*>(arow + kk + lk);
        float4 wv = *reinterpret_cast<const float4*>(wrow + kk + lk);
        __syncthreads();
        As[lk + 0][lm] = av.x; As[lk + 1][lm] = av.y; As[lk + 2][lm] = av.z; As[lk + 3][lm] = av.w;
        Ws[lk + 0][lm] = wv.x; Ws[lk + 1][lm] = wv.y; Ws[lk + 2][lm] = wv.z; Ws[lk + 3][lm] = wv.w;
        __syncthreads();
        #pragma unroll
        for (int k = 0; k < 16; ++k) {
            float a[4], w[4];
            #pragma unroll
            for (int i = 0; i < 4; ++i) { a[i] = As[k][(ty << 2) + i]; w[i] = Ws[k][(tx << 2) + i]; }
            #pragma unroll
            for (int i = 0; i < 4; ++i)
                #pragma unroll
                for (int j = 0; j < 4; ++j) acc[i][j] += a[i] * w[j];
        }
    }

    #pragma unroll
    for (int i = 0; i < 4; ++i) {
        const int m = mtile + (ty << 2) + i;
        #pragma unroll
        for (int j = 0; j < 4; ++j) {
            const int g = ntile + (tx << 2) + j;
            g_xp[(size_t)m * G3 + g] = acc[i][j] + b1[g];
        }
    }
}

// ---------------------------------------------------------------------------
// FC: out[n,g] = relu(g_h[n,:]) . fc_w[g,:] + fc_b[g]
// ---------------------------------------------------------------------------
__global__ void __launch_bounds__(256)
k_fc(const float* __restrict__ fw, const float* __restrict__ fb,
     float* __restrict__ out)
{
    __shared__ float As[8][128];
    __shared__ float Ws[8][128];

    const int tid   = threadIdx.x;
    const int mtile = blockIdx.y * 128;
    const int ntile = blockIdx.x * 128;
    const int tx = tid & 15, ty = tid >> 4;
    const int lm = tid >> 1;
    const int lk = (tid & 1) << 2;

    const float* arow = g_h + (size_t)(mtile + lm) * HH;
    const int gl = ntile + lm;
    const bool wok = (gl < VOUT);
    const float* wrow = fw + (size_t)(wok ? gl : 0) * HH;

    float acc[8][8] = {};

    for (int kk = 0; kk < HH; kk += 8) {
        float4 av = *reinterpret_cast<const float4*>(arow + kk + lk);
        float4 wv = *reinterpret_cast<const float4*>(wrow + kk + lk);
        if (!wok) { wv.x = 0.f; wv.y = 0.f; wv.z = 0.f; wv.w = 0.f; }
        __syncthreads();
        As[lk + 0][lm] = fmaxf(av.x, 0.f);
        As[lk + 1][lm] = fmaxf(av.y, 0.f);
        As[lk + 2][lm] = fmaxf(av.z, 0.f);
        As[lk + 3][lm] = fmaxf(av.w, 0.f);
        Ws[lk + 0][lm] = wv.x; Ws[lk + 1][lm] = wv.y; Ws[lk + 2][lm] = wv.z; Ws[lk + 3][lm] = wv.w;
        __syncthreads();
        #pragma unroll
        for (int k = 0; k < 8; ++k) {
            float a[8], w[8];
            #pragma unroll
            for (int i = 0; i < 8; ++i) a[i] = As[k][(ty << 3) + i];
            #pragma unroll
            for (int j = 0; j < 8; ++j) w[j] = Ws[k][(tx << 3) + j];
            #pragma unroll
            for (int i = 0; i < 8; ++i)
                #pragma unroll
                for (int j = 0; j < 8; ++j) acc[i][j] += a[i] * w[j];
        }
    }

    #pragma unroll
    for (int i = 0; i < 8; ++i) {
        const int m = mtile + (ty << 3) + i;
        #pragma unroll
        for (int j = 0; j < 8; ++j) {
            const int g = ntile + (tx << 3) + j;
            if (g < VOUT) {
                float c = acc[i][j] + fb[g];
                if (g < VN) out[(size_t)m * VN + g] = c;
                else        out[K_LOC_ELEMS + m] = c;    // raw time logit
            }
        }
    }
}

// ---------------------------------------------------------------------------
// Softmax: per-row log_softmax (row cached in smem) + time sigmoid.
// ---------------------------------------------------------------------------
__global__ void __launch_bounds__(256)
k_softmax(float* __restrict__ out)
{
    extern __shared__ float row[];       // VN floats
    __shared__ float red[256];

    const int n = blockIdx.x;
    const int tid = threadIdx.x;
    float* base = out + (size_t)n * VN;

    float mx = -1e30f;
    for (int i = tid; i < VN; i += 256) { float v = base[i]; row[i] = v; mx = fmaxf(mx, v); }
    red[tid] = mx; __syncthreads();
    for (int s = 128; s > 0; s >>= 1) { if (tid < s) red[tid] = fmaxf(red[tid], red[tid + s]); __syncthreads(); }
    mx = red[0];
    __syncthreads();

    float sum = 0.f;
    for (int i = tid; i < VN; i += 256) sum += expf(row[i] - mx);
    red[tid] = sum; __syncthreads();
    for (int s = 128; s > 0; s >>= 1) { if (tid < s) red[tid] += red[tid + s]; __syncthreads(); }
    float lse = mx + logf(red[0]);

    for (int i = tid; i < VN; i += 256) base[i] = row[i] - lse;

    if (tid == 0) {
        float tl = out[K_LOC_ELEMS + n];
        out[K_LOC_ELEMS + n] = 1.0f / (1.0f + expf(-tl));
    }
}

// ---------------------------------------------------------------------------
// Launch
// ---------------------------------------------------------------------------
extern "C" void kernel_launch(void* const* d_in, const int* in_sizes, int n_in,
                              void* d_out, int out_size)
{
    const int*   loc   = (const int*)  d_in[0];
    const float* times = (const float*)d_in[1];
    const float* emb   = (const float*)d_in[2];
    const float* w_ih0 = (const float*)d_in[3];
    const float* w_hh0 = (const float*)d_in[4];
    const float* b_ih0 = (const float*)d_in[5];
    const float* b_hh0 = (const float*)d_in[6];
    const float* w_ih1 = (const float*)d_in[7];
    const float* w_hh1 = (const float*)d_in[8];
    const float* b_ih1 = (const float*)d_in[9];
    const float* b_hh1 = (const float*)d_in[10];
    const float* fc_w  = (const float*)d_in[11];
    const float* fc_b  = (const float*)d_in[12];
    float* out = (float*)d_out;

    const int gru_smem = (HH * BB + NG * HH + 4 * NG * BB) * sizeof(float);  // 164 KB
    static int attr_done = 0;
    if (!attr_done) {
        cudaFuncSetAttribute(k_gru, cudaFuncAttributeMaxDynamicSharedMemorySize, gru_smem);
        attr_done = 1;
    }

    // Layer 0
    k_proj0<<<dim3(G3 / 64, NR / 64), 256>>>(loc, times, emb, w_ih0, b_ih0);
    k_zero_state<<<(HH * BB + 255) / 256, 256>>>();
    k_gru<<<NCTA, 256, gru_smem>>>(w_hh0, b_hh0);

    // Layer 1
    k_proj1<<<dim3(G3 / 64, NR / 64), 256>>>(w_ih1, b_ih1);
    k_zero_state<<<(HH * BB + 255) / 256, 256>>>();
    k_gru<<<NCTA, 256, gru_smem>>>(w_hh1, b_hh1);

    // FC -> logits straight into d_out
    k_fc<<<dim3((VOUT + 127) / 128, NR / 128), 256>>>(fc_w, fc_b, out);

    // log_softmax + time sigmoid
    k_softmax<<<NR, 256, VN * sizeof(float)>>>(out);
}

// round 8
// speedup vs baseline: 1.9940x; 1.3471x over previous
#include <cuda_runtime.h>
#include <math.h>

// Problem constants
#define VN   10000
#define VOUT 10001
#define EE   256
#define HH   512
#define G3   1536
#define BB   64
#define TT   128
#define NR   8192            // BB*TT
#define K_LOC_ELEMS ((size_t)NR * VN)   // 81,920,000 floats of location logits

// Persistent recurrence config
#define NCTA 128             // one CTA per 4 hidden dims
#define JH   4               // hidden dims per CTA
#define NG   12              // gate rows per CTA (r,z,n per hidden dim)

// FC tensor-core config
#define FBM 128
#define FBN 128
#define FBK 16
#define FNT (HH / FBK)       // 32 k-tiles
#define SROW 20              // padded smem row (floats) -> conflict-free frags

// Scratch (device globals; no allocations allowed)
__device__ float g_xp[(size_t)NR * G3];     // input-gate projections for current layer
__device__ float g_h [(size_t)NR * HH];     // layer output sequence (h1, then h2)
__device__ float g_stateT[HH * BB];         // recurrent state, TRANSPOSED [j][b]
__device__ __align__(128) unsigned g_epoch[32];   // [0] = barrier epoch counter

// ---------------------------------------------------------------------------
// Zero recurrent state + barrier epoch (runs before each persistent launch)
// ---------------------------------------------------------------------------
__global__ void k_zero_state() {
    int i = blockIdx.x * blockDim.x + threadIdx.x;
    if (i < HH * BB) g_stateT[i] = 0.0f;
    if (i == 0) g_epoch[0] = 0;
}

// ---------------------------------------------------------------------------
// Grid-wide barrier, monotonic epoch: arrive once, poll with plain volatile
// load. All NCTA CTAs co-resident (1/SM, 164KB smem).
// ---------------------------------------------------------------------------
__device__ __forceinline__ void grid_epoch_bar(unsigned target) {
    __syncthreads();
    if (threadIdx.x == 0) {
        __threadfence();                               // my CTA's stores -> visible
        atomicAdd(&g_epoch[0], 1u);
        while (*((volatile unsigned*)&g_epoch[0]) < target) { }
        __threadfence();
    }
    __syncthreads();
}

// ---------------------------------------------------------------------------
// Persistent GRU layer, ONE grid barrier per timestep.
// ---------------------------------------------------------------------------
__global__ void __launch_bounds__(256)
k_gru(const float* __restrict__ whh, const float* __restrict__ bhh)
{
    extern __shared__ float smem[];
    float* Ss = smem;                      // [512][64]  state, k-major rows of 64
    float* Ws = Ss + HH * BB;              // [12][512]
    float* Rs = Ws + NG * HH;              // [4][12][64]

    const int tid = threadIdx.x;
    const int cta = blockIdx.x;
    const int j0  = cta * JH;              // global hidden base

    // Load weight tile once: row g -> (j = j0 + g/3, gate = g%3)
    for (int i = tid; i < NG * HH; i += 256) {
        const int g = i >> 9, k = i & 511;
        const int jg = j0 + g / 3;
        const int gate = g - (g / 3) * 3;
        Ws[i] = whh[(size_t)(gate * 512 + jg) * HH + k];
    }

    const int kc = tid >> 6;               // 0..3
    const int gt = (tid >> 4) & 3;         // 0..3
    const int bq = tid & 15;               // 0..15

    const int gj = tid >> 6;               // 0..3   local hidden dim
    const int gb = tid & 63;               // 0..63  batch
    const int gjg = j0 + gj;

    unsigned target = NCTA;

    for (int t = 0; t < TT; ++t) {
        for (int i = tid; i < (HH * BB) / 4; i += 256) {
            float4 v = __ldcg((const float4*)g_stateT + i);
            ((float4*)Ss)[i] = v;
        }
        __syncthreads();

        float a00=0,a01=0,a02=0,a03=0,
              a10=0,a11=0,a12=0,a13=0,
              a20=0,a21=0,a22=0,a23=0;
        {
            const float* w0p = &Ws[(gt * 3 + 0) * HH + kc * 128];
            const float* w1p = &Ws[(gt * 3 + 1) * HH + kc * 128];
            const float* w2p = &Ws[(gt * 3 + 2) * HH + kc * 128];
            const float* sp  = &Ss[(kc * 128) * BB + bq * 4];
            #pragma unroll 8
            for (int kk = 0; kk < 128; ++kk) {
                float4 a = *reinterpret_cast<const float4*>(sp + kk * BB);
                float w0 = w0p[kk], w1 = w1p[kk], w2 = w2p[kk];
                a00 += w0 * a.x; a01 += w0 * a.y; a02 += w0 * a.z; a03 += w0 * a.w;
                a10 += w1 * a.x; a11 += w1 * a.y; a12 += w1 * a.z; a13 += w1 * a.w;
                a20 += w2 * a.x; a21 += w2 * a.y; a22 += w2 * a.z; a23 += w2 * a.w;
            }
        }
        {
            float* r0 = &Rs[(kc * NG + gt * 3 + 0) * BB + bq * 4];
            float* r1 = &Rs[(kc * NG + gt * 3 + 1) * BB + bq * 4];
            float* r2 = &Rs[(kc * NG + gt * 3 + 2) * BB + bq * 4];
            r0[0]=a00; r0[1]=a01; r0[2]=a02; r0[3]=a03;
            r1[0]=a10; r1[1]=a11; r1[2]=a12; r1[3]=a13;
            r2[0]=a20; r2[1]=a21; r2[2]=a22; r2[3]=a23;
        }
        __syncthreads();

        {
            float sr = Rs[(0*NG + gj*3 + 0)*BB + gb] + Rs[(1*NG + gj*3 + 0)*BB + gb]
                     + Rs[(2*NG + gj*3 + 0)*BB + gb] + Rs[(3*NG + gj*3 + 0)*BB + gb]
                     + bhh[gjg];
            float sz = Rs[(0*NG + gj*3 + 1)*BB + gb] + Rs[(1*NG + gj*3 + 1)*BB + gb]
                     + Rs[(2*NG + gj*3 + 1)*BB + gb] + Rs[(3*NG + gj*3 + 1)*BB + gb]
                     + bhh[512 + gjg];
            float sn = Rs[(0*NG + gj*3 + 2)*BB + gb] + Rs[(1*NG + gj*3 + 2)*BB + gb]
                     + Rs[(2*NG + gj*3 + 2)*BB + gb] + Rs[(3*NG + gj*3 + 2)*BB + gb]
                     + bhh[1024 + gjg];

            const float* xp = g_xp + (size_t)(gb * TT + t) * G3;
            float r  = 1.0f / (1.0f + expf(-(__ldg(&xp[gjg])        + sr)));
            float z  = 1.0f / (1.0f + expf(-(__ldg(&xp[512 + gjg])  + sz)));
            float nn = tanhf(__ldg(&xp[1024 + gjg]) + r * sn);

            float hold = Ss[gjg * BB + gb];          // old state, already in smem
            float hnew = (1.0f - z) * nn + z * hold;
            g_stateT[cta * 256 + tid] = hnew;        // == [gjg][gb], coalesced
            g_h[(size_t)(gb * TT + t) * HH + gjg] = hnew;
        }

        grid_epoch_bar(target);
        target += NCTA;
    }
}

// ---------------------------------------------------------------------------
// proj0: g_xp[n,g] = sum_e emb[loc[n],e]*w0[g,e] + times[n]*w0[g,256] + b0[g]
// ---------------------------------------------------------------------------
__global__ void __launch_bounds__(256)
k_proj0(const int* __restrict__ loc, const float* __restrict__ times,
        const float* __restrict__ emb, const float* __restrict__ w0,
        const float* __restrict__ b0)
{
    __shared__ float As[16][64];
    __shared__ float Ws[16][64];
    __shared__ int   locs[64];
    __shared__ float ts[64];

    const int tid   = threadIdx.x;
    const int mtile = blockIdx.y * 64;
    const int ntile = blockIdx.x * 64;
    if (tid < 64) { locs[tid] = loc[mtile + tid]; ts[tid] = times[mtile + tid]; }
    __syncthreads();

    const int tx = tid & 15, ty = tid >> 4;
    const int lm = tid >> 2;
    const int lk = (tid & 3) << 2;
    const int arow = locs[lm];
    const float* wrowp = w0 + (size_t)(ntile + lm) * 257;

    float acc[4][4] = {};

    for (int kk = 0; kk < 256; kk += 16) {
        float4 av = *reinterpret_cast<const float4*>(emb + (size_t)arow * EE + kk + lk);
        float wv0 = wrowp[kk + lk + 0];
        float wv1 = wrowp[kk + lk + 1];
        float wv2 = wrowp[kk + lk + 2];
        float wv3 = wrowp[kk + lk + 3];
        __syncthreads();
        As[lk + 0][lm] = av.x; As[lk + 1][lm] = av.y; As[lk + 2][lm] = av.z; As[lk + 3][lm] = av.w;
        Ws[lk + 0][lm] = wv0;  Ws[lk + 1][lm] = wv1;  Ws[lk + 2][lm] = wv2;  Ws[lk + 3][lm] = wv3;
        __syncthreads();
        #pragma unroll
        for (int k = 0; k < 16; ++k) {
            float a[4], w[4];
            #pragma unroll
            for (int i = 0; i < 4; ++i) { a[i] = As[k][(ty << 2) + i]; w[i] = Ws[k][(tx << 2) + i]; }
            #pragma unroll
            for (int i = 0; i < 4; ++i)
                #pragma unroll
                for (int j = 0; j < 4; ++j) acc[i][j] += a[i] * w[j];
        }
    }

    #pragma unroll
    for (int i = 0; i < 4; ++i) {
        const int m = mtile + (ty << 2) + i;
        const float tm = ts[(ty << 2) + i];
        #pragma unroll
        for (int j = 0; j < 4; ++j) {
            const int g = ntile + (tx << 2) + j;
            g_xp[(size_t)m * G3 + g] = acc[i][j] + tm * w0[(size_t)g * 257 + 256] + b0[g];
        }
    }
}

// ---------------------------------------------------------------------------
// proj1: g_xp[n,g] = sum_k g_h[n,k]*w1[g,k] + b1[g]      (K = 512)
// ---------------------------------------------------------------------------
__global__ void __launch_bounds__(256)
k_proj1(const float* __restrict__ w1, const float* __restrict__ b1)
{
    __shared__ float As[16][64];
    __shared__ float Ws[16][64];

    const int tid   = threadIdx.x;
    const int mtile = blockIdx.y * 64;
    const int ntile = blockIdx.x * 64;
    const int tx = tid & 15, ty = tid >> 4;
    const int lm = tid >> 2;
    const int lk = (tid & 3) << 2;

    const float* arow = g_h + (size_t)(mtile + lm) * HH;
    const float* wrow = w1  + (size_t)(ntile + lm) * HH;

    float acc[4][4] = {};

    for (int kk = 0; kk < HH; kk += 16) {
        float4 av = *reinterpret_cast<const float4*>(arow + kk + lk);
        float4 wv = *reinterpret_cast<const float4*>(wrow + kk + lk);
        __syncthreads();
        As[lk + 0][lm] = av.x; As[lk + 1][lm] = av.y; As[lk + 2][lm] = av.z; As[lk + 3][lm] = av.w;
        Ws[lk + 0][lm] = wv.x; Ws[lk + 1][lm] = wv.y; Ws[lk + 2][lm] = wv.z; Ws[lk + 3][lm] = wv.w;
        __syncthreads();
        #pragma unroll
        for (int k = 0; k < 16; ++k) {
            float a[4], w[4];
            #pragma unroll
            for (int i = 0; i < 4; ++i) { a[i] = As[k][(ty << 2) + i]; w[i] = Ws[k][(tx << 2) + i]; }
            #pragma unroll
            for (int i = 0; i < 4; ++i)
                #pragma unroll
                for (int j = 0; j < 4; ++j) acc[i][j] += a[i] * w[j];
        }
    }

    #pragma unroll
    for (int i = 0; i < 4; ++i) {
        const int m = mtile + (ty << 2) + i;
        #pragma unroll
        for (int j = 0; j < 4; ++j) {
            const int g = ntile + (tx << 2) + j;
            g_xp[(size_t)m * G3 + g] = acc[i][j] + b1[g];
        }
    }
}

// ---------------------------------------------------------------------------
// FC via tf32 tensor cores: out[n,g] = relu(g_h[n,:]) . fc_w[g,:] + fc_b[g]
// BM=128, BN=128, BK=16, 256 threads = 2x4 warps, warp tile 64x32,
// mma.sync.m16n8k8 tf32, fp32 accumulate. Double-buffered smem, pad 20.
// ---------------------------------------------------------------------------
__device__ __forceinline__ unsigned f2tf(float x) {
    unsigned u;
    asm("cvt.rna.tf32.f32 %0, %1;" : "=r"(u) : "f"(x));
    return u;
}

__global__ void __launch_bounds__(256)
k_fc_tc(const float* __restrict__ fw, const float* __restrict__ fb,
        float* __restrict__ out)
{
    __shared__ unsigned As[2][FBM * SROW];
    __shared__ unsigned Bs[2][FBN * SROW];

    const int tid  = threadIdx.x;
    const int lane = tid & 31;
    const int warp = tid >> 5;
    const int wm = warp >> 2;            // 0..1 -> 64 rows each
    const int wn = warp & 3;             // 0..3 -> 32 cols each
    const int qg = lane >> 2;            // group 0..7
    const int qt = lane & 3;             // 0..3

    const int mtile = blockIdx.y * FBM;
    const int ntile = blockIdx.x * FBN;

    float acc[4][4][4];
    #pragma unroll
    for (int mi = 0; mi < 4; ++mi)
        #pragma unroll
        for (int ni = 0; ni < 4; ++ni)
            #pragma unroll
            for (int q = 0; q < 4; ++q) acc[mi][ni][q] = 0.0f;

    // staging registers
    float4 ar[2], br[2];

    // f = tid + i*256 -> m = f>>2 (0..127), kq = f&3 (float4 within 16-k row)
    const int sm0 = tid >> 2, skq = (tid & 3) * 4;
    const int sm1 = (tid + 256) >> 2;

    const int brow0 = (ntile + sm0 > VN) ? VN : ntile + sm0;
    const int brow1 = (ntile + sm1 > VN) ? VN : ntile + sm1;

    // kt = 0 loads
    {
        const int kk = 0;
        ar[0] = *(const float4*)&g_h[(size_t)(mtile + sm0) * HH + kk + skq];
        ar[1] = *(const float4*)&g_h[(size_t)(mtile + sm1) * HH + kk + skq];
        br[0] = *(const float4*)&fw[(size_t)brow0 * HH + kk + skq];
        br[1] = *(const float4*)&fw[(size_t)brow1 * HH + kk + skq];
    }
    // store to buffer 0
    {
        uint4 v;
        v.x = f2tf(fmaxf(ar[0].x, 0.f)); v.y = f2tf(fmaxf(ar[0].y, 0.f));
        v.z = f2tf(fmaxf(ar[0].z, 0.f)); v.w = f2tf(fmaxf(ar[0].w, 0.f));
        *(uint4*)&As[0][sm0 * SROW + skq] = v;
        v.x = f2tf(fmaxf(ar[1].x, 0.f)); v.y = f2tf(fmaxf(ar[1].y, 0.f));
        v.z = f2tf(fmaxf(ar[1].z, 0.f)); v.w = f2tf(fmaxf(ar[1].w, 0.f));
        *(uint4*)&As[0][sm1 * SROW + skq] = v;
        v.x = f2tf(br[0].x); v.y = f2tf(br[0].y); v.z = f2tf(br[0].z); v.w = f2tf(br[0].w);
        *(uint4*)&Bs[0][sm0 * SROW + skq] = v;
        v.x = f2tf(br[1].x); v.y = f2tf(br[1].y); v.z = f2tf(br[1].z); v.w = f2tf(br[1].w);
        *(uint4*)&Bs[0][sm1 * SROW + skq] = v;
    }
    __syncthreads();

    int buf = 0;
    for (int kt = 0; kt < FNT; ++kt) {
        // prefetch next tile into regs
        if (kt + 1 < FNT) {
            const int kk = (kt + 1) * FBK;
            ar[0] = *(const float4*)&g_h[(size_t)(mtile + sm0) * HH + kk + skq];
            ar[1] = *(const float4*)&g_h[(size_t)(mtile + sm1) * HH + kk + skq];
            br[0] = *(const float4*)&fw[(size_t)brow0 * HH + kk + skq];
            br[1] = *(const float4*)&fw[(size_t)brow1 * HH + kk + skq];
        }

        // compute current buffer: two k-steps of 8
        #pragma unroll
        for (int ks = 0; ks < FBK; ks += 8) {
            unsigned af[4][4];
            #pragma unroll
            for (int mi = 0; mi < 4; ++mi) {
                const int r = wm * 64 + mi * 16 + qg;
                af[mi][0] = As[buf][r * SROW + ks + qt];
                af[mi][1] = As[buf][(r + 8) * SROW + ks + qt];
                af[mi][2] = As[buf][r * SROW + ks + qt + 4];
                af[mi][3] = As[buf][(r + 8) * SROW + ks + qt + 4];
            }
            unsigned bf[4][2];
            #pragma unroll
            for (int ni = 0; ni < 4; ++ni) {
                const int n = wn * 32 + ni * 8 + qg;
                bf[ni][0] = Bs[buf][n * SROW + ks + qt];
                bf[ni][1] = Bs[buf][n * SROW + ks + qt + 4];
            }
            #pragma unroll
            for (int mi = 0; mi < 4; ++mi)
                #pragma unroll
                for (int ni = 0; ni < 4; ++ni) {
                    asm volatile(
                        "mma.sync.aligned.m16n8k8.row.col.f32.tf32.tf32.f32 "
                        "{%0,%1,%2,%3}, {%4,%5,%6,%7}, {%8,%9}, {%0,%1,%2,%3};"
                        : "+f"(acc[mi][ni][0]), "+f"(acc[mi][ni][1]),
                          "+f"(acc[mi][ni][2]), "+f"(acc[mi][ni][3])
                        : "r"(af[mi][0]), "r"(af[mi][1]), "r"(af[mi][2]), "r"(af[mi][3]),
                          "r"(bf[ni][0]), "r"(bf[ni][1]));
                }
        }

        // stage next tile into the other buffer
        if (kt + 1 < FNT) {
            const int nb = buf ^ 1;
            uint4 v;
            v.x = f2tf(fmaxf(ar[0].x, 0.f)); v.y = f2tf(fmaxf(ar[0].y, 0.f));
            v.z = f2tf(fmaxf(ar[0].z, 0.f)); v.w = f2tf(fmaxf(ar[0].w, 0.f));
            *(uint4*)&As[nb][sm0 * SROW + skq] = v;
            v.x = f2tf(fmaxf(ar[1].x, 0.f)); v.y = f2tf(fmaxf(ar[1].y, 0.f));
            v.z = f2tf(fmaxf(ar[1].z, 0.f)); v.w = f2tf(fmaxf(ar[1].w, 0.f));
            *(uint4*)&As[nb][sm1 * SROW + skq] = v;
            v.x = f2tf(br[0].x); v.y = f2tf(br[0].y); v.z = f2tf(br[0].z); v.w = f2tf(br[0].w);
            *(uint4*)&Bs[nb][sm0 * SROW + skq] = v;
            v.x = f2tf(br[1].x); v.y = f2tf(br[1].y); v.z = f2tf(br[1].z); v.w = f2tf(br[1].w);
            *(uint4*)&Bs[nb][sm1 * SROW + skq] = v;
        }
        __syncthreads();
        buf ^= 1;
    }

    // Epilogue: add bias, write (col==VN -> time region)
    #pragma unroll
    for (int mi = 0; mi < 4; ++mi) {
        const int row0 = mtile + wm * 64 + mi * 16 + qg;
        const int row1 = row0 + 8;
        #pragma unroll
        for (int ni = 0; ni < 4; ++ni) {
            const int col0 = ntile + wn * 32 + ni * 8 + qt * 2;
            const int col1 = col0 + 1;
            if (col0 < VN) out[(size_t)row0 * VN + col0] = acc[mi][ni][0] + fb[col0];
            else if (col0 == VN) out[K_LOC_ELEMS + row0] = acc[mi][ni][0] + fb[col0];
            if (col1 < VN) out[(size_t)row0 * VN + col1] = acc[mi][ni][1] + fb[col1];
            else if (col1 == VN) out[K_LOC_ELEMS + row0] = acc[mi][ni][1] + fb[col1];
            if (col0 < VN) out[(size_t)row1 * VN + col0] = acc[mi][ni][2] + fb[col0];
            else if (col0 == VN) out[K_LOC_ELEMS + row1] = acc[mi][ni][2] + fb[col0];
            if (col1 < VN) out[(size_t)row1 * VN + col1] = acc[mi][ni][3] + fb[col1];
            else if (col1 == VN) out[K_LOC_ELEMS + row1] = acc[mi][ni][3] + fb[col1];
        }
    }
}

// ---------------------------------------------------------------------------
// Softmax: per-row log_softmax (row cached in smem) + time sigmoid.
// ---------------------------------------------------------------------------
__global__ void __launch_bounds__(256)
k_softmax(float* __restrict__ out)
{
    extern __shared__ float row[];       // VN floats
    __shared__ float red[256];

    const int n = blockIdx.x;
    const int tid = threadIdx.x;
    float* base = out + (size_t)n * VN;

    float mx = -1e30f;
    for (int i = tid; i < VN; i += 256) { float v = base[i]; row[i] = v; mx = fmaxf(mx, v); }
    red[tid] = mx; __syncthreads();
    for (int s = 128; s > 0; s >>= 1) { if (tid < s) red[tid] = fmaxf(red[tid], red[tid + s]); __syncthreads(); }
    mx = red[0];
    __syncthreads();

    float sum = 0.f;
    for (int i = tid; i < VN; i += 256) sum += expf(row[i] - mx);
    red[tid] = sum; __syncthreads();
    for (int s = 128; s > 0; s >>= 1) { if (tid < s) red[tid] += red[tid + s]; __syncthreads(); }
    float lse = mx + logf(red[0]);

    for (int i = tid; i < VN; i += 256) base[i] = row[i] - lse;

    if (tid == 0) {
        float tl = out[K_LOC_ELEMS + n];
        out[K_LOC_ELEMS + n] = 1.0f / (1.0f + expf(-tl));
    }
}

// ---------------------------------------------------------------------------
// Launch
// ---------------------------------------------------------------------------
extern "C" void kernel_launch(void* const* d_in, const int* in_sizes, int n_in,
                              void* d_out, int out_size)
{
    const int*   loc   = (const int*)  d_in[0];
    const float* times = (const float*)d_in[1];
    const float* emb   = (const float*)d_in[2];
    const float* w_ih0 = (const float*)d_in[3];
    const float* w_hh0 = (const float*)d_in[4];
    const float* b_ih0 = (const float*)d_in[5];
    const float* b_hh0 = (const float*)d_in[6];
    const float* w_ih1 = (const float*)d_in[7];
    const float* w_hh1 = (const float*)d_in[8];
    const float* b_ih1 = (const float*)d_in[9];
    const float* b_hh1 = (const float*)d_in[10];
    const float* fc_w  = (const float*)d_in[11];
    const float* fc_b  = (const float*)d_in[12];
    float* out = (float*)d_out;

    const int gru_smem = (HH * BB + NG * HH + 4 * NG * BB) * sizeof(float);  // 164 KB
    static int attr_done = 0;
    if (!attr_done) {
        cudaFuncSetAttribute(k_gru, cudaFuncAttributeMaxDynamicSharedMemorySize, gru_smem);
        attr_done = 1;
    }

    // Layer 0
    k_proj0<<<dim3(G3 / 64, NR / 64), 256>>>(loc, times, emb, w_ih0, b_ih0);
    k_zero_state<<<(HH * BB + 255) / 256, 256>>>();
    k_gru<<<NCTA, 256, gru_smem>>>(w_hh0, b_hh0);

    // Layer 1
    k_proj1<<<dim3(G3 / 64, NR / 64), 256>>>(w_ih1, b_ih1);
    k_zero_state<<<(HH * BB + 255) / 256, 256>>>();
    k_gru<<<NCTA, 256, gru_smem>>>(w_hh1, b_hh1);

    // FC -> logits straight into d_out (tensor cores, tf32)
    k_fc_tc<<<dim3((VOUT + FBN - 1) / FBN, NR / FBM), 256>>>(fc_w, fc_b, out);

    // log_softmax + time sigmoid
    k_softmax<<<NR, 256, VN * sizeof(float)>>>(out);
}

// round 9
// speedup vs baseline: 2.1164x; 1.0613x over previous
#include <cuda_runtime.h>
#include <math.h>

// Problem constants
#define VN   10000
#define VOUT 10001
#define EE   256
#define HH   512
#define G3   1536
#define BB   64
#define TT   128
#define NR   8192            // BB*TT
#define K_LOC_ELEMS ((size_t)NR * VN)   // 81,920,000 floats of location logits

// Persistent recurrence config: 128 CTAs = 64 j-groups x 2 batch halves
#define NCTA 128
#define JH   8               // hidden dims per CTA
#define NGR  24              // gate rows per CTA (3 per dim)
#define BH   32              // batches per CTA
#define SP   516             // padded k-row (512+4): conflict-free frag loads

// FC / proj1 tensor-core tiling
#define FBM 128
#define FBN 128
#define FBK 16
#define SROW 20

// Scratch (device globals; no allocations allowed)
// g_xp layout: [t][gate][j][b]  -> ((t*3+gate)*512 + j)*64 + b
__device__ float g_xp[(size_t)NR * G3];
// g_h layout: [m'=t*64+b][j]
__device__ float g_h [(size_t)NR * HH];
__device__ float g_state[BB * HH];          // [b][k]
__device__ __align__(128) unsigned g_epoch[32];

__device__ __forceinline__ unsigned f2tf(float x) {
    unsigned u;
    asm("cvt.rna.tf32.f32 %0, %1;" : "=r"(u) : "f"(x));
    return u;
}

#define MMA_TF32(c0,c1,c2,c3, a0,a1,a2,a3, b0,b1)                         \
    asm volatile(                                                          \
        "mma.sync.aligned.m16n8k8.row.col.f32.tf32.tf32.f32 "             \
        "{%0,%1,%2,%3}, {%4,%5,%6,%7}, {%8,%9}, {%0,%1,%2,%3};"           \
        : "+f"(c0), "+f"(c1), "+f"(c2), "+f"(c3)                           \
        : "r"(a0), "r"(a1), "r"(a2), "r"(a3), "r"(b0), "r"(b1))

// ---------------------------------------------------------------------------
__global__ void k_zero_state() {
    int i = blockIdx.x * blockDim.x + threadIdx.x;
    if (i < BB * HH) g_state[i] = 0.0f;
    if (i == 0) g_epoch[0] = 0;
}

__device__ __forceinline__ void grid_epoch_bar(unsigned target) {
    __syncthreads();
    if (threadIdx.x == 0) {
        __threadfence();
        atomicAdd(&g_epoch[0], 1u);
        while (*((volatile unsigned*)&g_epoch[0]) < target) { }
        __threadfence();
    }
    __syncthreads();
}

// ---------------------------------------------------------------------------
// Persistent GRU via tf32 tensor cores with hi/lo split (3-mma, ~fp32 acc).
// CTA: jg = cta>>1 owns dims [jg*8, +8) (24 gate rows); bh = cta&1 owns
// batches [bh*32, +32). Smem: Whi/Wlo [24][516], Ss [32][516], Cs [24][33].
// ---------------------------------------------------------------------------
__global__ void __launch_bounds__(256)
k_gru_tc(const float* __restrict__ whh, const float* __restrict__ bhh)
{
    extern __shared__ float smem[];
    float* Whi = smem;                     // [24][516]
    float* Wlo = Whi + NGR * SP;           // [24][516]
    float* Ss  = Wlo + NGR * SP;           // [32][516]
    float* Cs  = Ss + BH * SP;             // [24][33]

    const int tid = threadIdx.x;
    const int cta = blockIdx.x;
    const int jg = cta >> 1, bh = cta & 1;
    const int j0 = jg * JH;
    const int gb0 = bh * BH;

    // Load + split weight tile once (rows g = jj*3+gate over full K)
    for (int i = tid; i < NGR * 512; i += 256) {
        const int g = i >> 9, k = i & 511;
        const int jj = g / 3, gate = g - 3 * (g / 3);
        float w = whh[(size_t)(gate * 512 + j0 + jj) * HH + k];
        unsigned hu = f2tf(w);
        float hf = __uint_as_float(hu);
        Whi[g * SP + k] = hf;
        Wlo[g * SP + k] = __uint_as_float(f2tf(w - hf));
    }

    const int lane = tid & 31, warp = tid >> 5;
    const int qg = lane >> 2, qt = lane & 3;
    const int mi = warp >> 2, ni = warp & 3;
    const int m0 = mi * 8;                 // row tiles 0..15 and 8..23 (overlap)
    const int n0 = ni * 8;

    // gate-phase coords: 1 (j,b) per thread
    const int jj = tid >> 5;               // 0..7
    const int bl = tid & 31;
    const int gjg = j0 + jj;
    const int gb = gb0 + bl;

    const float* ahp = &Whi[(m0 + qg) * SP + qt];
    const float* alp = &Wlo[(m0 + qg) * SP + qt];
    const float* bp  = &Ss[(n0 + qg) * SP + qt];

    unsigned target = NCTA;

    for (int t = 0; t < TT; ++t) {
        // Coalesced state gather: 32 rows x 2KB
        for (int i = tid; i < BH * 128; i += 256) {
            const int b = i >> 7, kq = (i & 127) << 2;
            float4 v = __ldcg((const float4*)&g_state[(size_t)(gb0 + b) * HH + kq]);
            *(float4*)&Ss[b * SP + kq] = v;
        }
        __syncthreads();

        float c0 = 0.f, c1 = 0.f, c2 = 0.f, c3 = 0.f;
        #pragma unroll 4
        for (int kt = 0; kt < 64; ++kt) {
            const int k0 = kt * 8;
            unsigned ah0 = __float_as_uint(ahp[k0]);
            unsigned ah1 = __float_as_uint(ahp[8 * SP + k0]);
            unsigned ah2 = __float_as_uint(ahp[k0 + 4]);
            unsigned ah3 = __float_as_uint(ahp[8 * SP + k0 + 4]);
            unsigned al0 = __float_as_uint(alp[k0]);
            unsigned al1 = __float_as_uint(alp[8 * SP + k0]);
            unsigned al2 = __float_as_uint(alp[k0 + 4]);
            unsigned al3 = __float_as_uint(alp[8 * SP + k0 + 4]);
            float s0 = bp[k0], s1 = bp[k0 + 4];
            unsigned bh0 = f2tf(s0);
            unsigned bl0 = f2tf(s0 - __uint_as_float(bh0));
            unsigned bh1 = f2tf(s1);
            unsigned bl1 = f2tf(s1 - __uint_as_float(bh1));

            MMA_TF32(c0, c1, c2, c3, ah0, ah1, ah2, ah3, bh0, bh1);
            MMA_TF32(c0, c1, c2, c3, ah0, ah1, ah2, ah3, bl0, bl1);
            MMA_TF32(c0, c1, c2, c3, al0, al1, al2, al3, bh0, bh1);
        }

        // Write C frags to Cs[gate_row][b]; mi=1 keeps only rows 16..23
        if (mi == 0) {
            Cs[qg * 33 + n0 + 2 * qt]         = c0;
            Cs[qg * 33 + n0 + 2 * qt + 1]     = c1;
            Cs[(qg + 8) * 33 + n0 + 2 * qt]   = c2;
            Cs[(qg + 8) * 33 + n0 + 2 * qt+1] = c3;
        } else {
            Cs[(16 + qg) * 33 + n0 + 2 * qt]     = c2;
            Cs[(16 + qg) * 33 + n0 + 2 * qt + 1] = c3;
        }
        __syncthreads();

        // Gate math
        {
            float sr = Cs[(jj * 3 + 0) * 33 + bl] + __ldg(&bhh[gjg]);
            float sz = Cs[(jj * 3 + 1) * 33 + bl] + __ldg(&bhh[512 + gjg]);
            float sn = Cs[(jj * 3 + 2) * 33 + bl] + __ldg(&bhh[1024 + gjg]);

            float xr = __ldg(&g_xp[((size_t)(t * 3 + 0) * 512 + gjg) * 64 + gb]);
            float xz = __ldg(&g_xp[((size_t)(t * 3 + 1) * 512 + gjg) * 64 + gb]);
            float xn = __ldg(&g_xp[((size_t)(t * 3 + 2) * 512 + gjg) * 64 + gb]);

            float r  = 1.0f / (1.0f + expf(-(xr + sr)));
            float z  = 1.0f / (1.0f + expf(-(xz + sz)));
            float nn = tanhf(xn + r * sn);

            float hold = Ss[bl * SP + gjg];
            float hnew = (1.0f - z) * nn + z * hold;
            g_state[(size_t)gb * HH + gjg] = hnew;
            g_h[((size_t)t * 64 + gb) * HH + gjg] = hnew;
        }

        grid_epoch_bar(target);
        target += NCTA;
    }
}

// ---------------------------------------------------------------------------
// proj0 (fp32): xpT[t][gate][j][b] = emb[loc]·w0 + time·w0[:,256] + b0
// m index n = b*128+t (loc ordering). 64x64 tile, 4x4/thread.
// ---------------------------------------------------------------------------
__global__ void __launch_bounds__(256)
k_proj0(const int* __restrict__ loc, const float* __restrict__ times,
        const float* __restrict__ emb, const float* __restrict__ w0,
        const float* __restrict__ b0)
{
    __shared__ float As[16][64];
    __shared__ float Ws[16][64];
    __shared__ int   locs[64];
    __shared__ float ts[64];

    const int tid   = threadIdx.x;
    const int mtile = blockIdx.y * 64;
    const int ntile = blockIdx.x * 64;
    if (tid < 64) { locs[tid] = loc[mtile + tid]; ts[tid] = times[mtile + tid]; }
    __syncthreads();

    const int tx = tid & 15, ty = tid >> 4;
    const int lm = tid >> 2;
    const int lk = (tid & 3) << 2;
    const int arow = locs[lm];
    const float* wrowp = w0 + (size_t)(ntile + lm) * 257;

    float acc[4][4] = {};

    for (int kk = 0; kk < 256; kk += 16) {
        float4 av = *reinterpret_cast<const float4*>(emb + (size_t)arow * EE + kk + lk);
        float wv0 = wrowp[kk + lk + 0];
        float wv1 = wrowp[kk + lk + 1];
        float wv2 = wrowp[kk + lk + 2];
        float wv3 = wrowp[kk + lk + 3];
        __syncthreads();
        As[lk + 0][lm] = av.x; As[lk + 1][lm] = av.y; As[lk + 2][lm] = av.z; As[lk + 3][lm] = av.w;
        Ws[lk + 0][lm] = wv0;  Ws[lk + 1][lm] = wv1;  Ws[lk + 2][lm] = wv2;  Ws[lk + 3][lm] = wv3;
        __syncthreads();
        #pragma unroll
        for (int k = 0; k < 16; ++k) {
            float a[4], w[4];
            #pragma unroll
            for (int i = 0; i < 4; ++i) { a[i] = As[k][(ty << 2) + i]; w[i] = Ws[k][(tx << 2) + i]; }
            #pragma unroll
            for (int i = 0; i < 4; ++i)
                #pragma unroll
                for (int j = 0; j < 4; ++j) acc[i][j] += a[i] * w[j];
        }
    }

    #pragma unroll
    for (int i = 0; i < 4; ++i) {
        const int m = mtile + (ty << 2) + i;
        const int tt = m & 127, b = m >> 7;
        const float tm = ts[(ty << 2) + i];
        #pragma unroll
        for (int j = 0; j < 4; ++j) {
            const int g = ntile + (tx << 2) + j;
            const int gate = g >> 9, jdim = g & 511;
            g_xp[((size_t)(tt * 3 + gate) * 512 + jdim) * 64 + b] =
                acc[i][j] + tm * w0[(size_t)g * 257 + 256] + b0[g];
        }
    }
}

// ---------------------------------------------------------------------------
// proj1 via tf32 TC: xpT = g_h @ w1^T + b1.  M=8192, N=1536, K=512.
// ---------------------------------------------------------------------------
__global__ void __launch_bounds__(256)
k_proj1_tc(const float* __restrict__ w1, const float* __restrict__ b1)
{
    __shared__ unsigned As[2][FBM * SROW];
    __shared__ unsigned Bs[2][FBN * SROW];

    const int tid  = threadIdx.x;
    const int lane = tid & 31;
    const int warp = tid >> 5;
    const int wm = warp >> 2, wn = warp & 3;
    const int qg = lane >> 2, qt = lane & 3;

    const int mtile = blockIdx.y * FBM;
    const int ntile = blockIdx.x * FBN;

    float acc[4][4][4];
    #pragma unroll
    for (int mi = 0; mi < 4; ++mi)
        #pragma unroll
        for (int ni = 0; ni < 4; ++ni)
            #pragma unroll
            for (int q = 0; q < 4; ++q) acc[mi][ni][q] = 0.0f;

    float4 ar[2], br[2];
    const int sm0 = tid >> 2, skq = (tid & 3) * 4;
    const int sm1 = (tid + 256) >> 2;

    {
        ar[0] = *(const float4*)&g_h[(size_t)(mtile + sm0) * HH + skq];
        ar[1] = *(const float4*)&g_h[(size_t)(mtile + sm1) * HH + skq];
        br[0] = *(const float4*)&w1[(size_t)(ntile + sm0) * HH + skq];
        br[1] = *(const float4*)&w1[(size_t)(ntile + sm1) * HH + skq];
    }
    {
        uint4 v;
        v.x = f2tf(ar[0].x); v.y = f2tf(ar[0].y); v.z = f2tf(ar[0].z); v.w = f2tf(ar[0].w);
        *(uint4*)&As[0][sm0 * SROW + skq] = v;
        v.x = f2tf(ar[1].x); v.y = f2tf(ar[1].y); v.z = f2tf(ar[1].z); v.w = f2tf(ar[1].w);
        *(uint4*)&As[0][sm1 * SROW + skq] = v;
        v.x = f2tf(br[0].x); v.y = f2tf(br[0].y); v.z = f2tf(br[0].z); v.w = f2tf(br[0].w);
        *(uint4*)&Bs[0][sm0 * SROW + skq] = v;
        v.x = f2tf(br[1].x); v.y = f2tf(br[1].y); v.z = f2tf(br[1].z); v.w = f2tf(br[1].w);
        *(uint4*)&Bs[0][sm1 * SROW + skq] = v;
    }
    __syncthreads();

    int buf = 0;
    for (int kt = 0; kt < HH / FBK; ++kt) {
        if (kt + 1 < HH / FBK) {
            const int kk = (kt + 1) * FBK;
            ar[0] = *(const float4*)&g_h[(size_t)(mtile + sm0) * HH + kk + skq];
            ar[1] = *(const float4*)&g_h[(size_t)(mtile + sm1) * HH + kk + skq];
            br[0] = *(const float4*)&w1[(size_t)(ntile + sm0) * HH + kk + skq];
            br[1] = *(const float4*)&w1[(size_t)(ntile + sm1) * HH + kk + skq];
        }
        #pragma unroll
        for (int ks = 0; ks < FBK; ks += 8) {
            unsigned af[4][4];
            #pragma unroll
            for (int mi = 0; mi < 4; ++mi) {
                const int r = wm * 64 + mi * 16 + qg;
                af[mi][0] = As[buf][r * SROW + ks + qt];
                af[mi][1] = As[buf][(r + 8) * SROW + ks + qt];
                af[mi][2] = As[buf][r * SROW + ks + qt + 4];
                af[mi][3] = As[buf][(r + 8) * SROW + ks + qt + 4];
            }
            unsigned bf[4][2];
            #pragma unroll
            for (int ni = 0; ni < 4; ++ni) {
                const int n = wn * 32 + ni * 8 + qg;
                bf[ni][0] = Bs[buf][n * SROW + ks + qt];
                bf[ni][1] = Bs[buf][n * SROW + ks + qt + 4];
            }
            #pragma unroll
            for (int mi = 0; mi < 4; ++mi)
                #pragma unroll
                for (int ni = 0; ni < 4; ++ni)
                    MMA_TF32(acc[mi][ni][0], acc[mi][ni][1], acc[mi][ni][2], acc[mi][ni][3],
                             af[mi][0], af[mi][1], af[mi][2], af[mi][3],
                             bf[ni][0], bf[ni][1]);
        }
        if (kt + 1 < HH / FBK) {
            const int nb = buf ^ 1;
            uint4 v;
            v.x = f2tf(ar[0].x); v.y = f2tf(ar[0].y); v.z = f2tf(ar[0].z); v.w = f2tf(ar[0].w);
            *(uint4*)&As[nb][sm0 * SROW + skq] = v;
            v.x = f2tf(ar[1].x); v.y = f2tf(ar[1].y); v.z = f2tf(ar[1].z); v.w = f2tf(ar[1].w);
            *(uint4*)&As[nb][sm1 * SROW + skq] = v;
            v.x = f2tf(br[0].x); v.y = f2tf(br[0].y); v.z = f2tf(br[0].z); v.w = f2tf(br[0].w);
            *(uint4*)&Bs[nb][sm0 * SROW + skq] = v;
            v.x = f2tf(br[1].x); v.y = f2tf(br[1].y); v.z = f2tf(br[1].z); v.w = f2tf(br[1].w);
            *(uint4*)&Bs[nb][sm1 * SROW + skq] = v;
        }
        __syncthreads();
        buf ^= 1;
    }

    // Epilogue -> transposed xp
    #pragma unroll
    for (int mi = 0; mi < 4; ++mi) {
        #pragma unroll
        for (int rr = 0; rr < 2; ++rr) {
            const int row = mtile + wm * 64 + mi * 16 + qg + rr * 8;   // m' = t*64+b
            const int tt = row >> 6, b = row & 63;
            #pragma unroll
            for (int ni = 0; ni < 4; ++ni) {
                #pragma unroll
                for (int cc = 0; cc < 2; ++cc) {
                    const int col = ntile + wn * 32 + ni * 8 + qt * 2 + cc;
                    const int gate = col >> 9, jdim = col & 511;
                    g_xp[((size_t)(tt * 3 + gate) * 512 + jdim) * 64 + b] =
                        acc[mi][ni][rr * 2 + cc] + b1[col];
                }
            }
        }
    }
}

// ---------------------------------------------------------------------------
// FC via tf32 TC. A rows are m'=t*64+b; output rows remapped to n=b*128+t.
// ---------------------------------------------------------------------------
__global__ void __launch_bounds__(256)
k_fc_tc(const float* __restrict__ fw, const float* __restrict__ fb,
        float* __restrict__ out)
{
    __shared__ unsigned As[2][FBM * SROW];
    __shared__ unsigned Bs[2][FBN * SROW];

    const int tid  = threadIdx.x;
    const int lane = tid & 31;
    const int warp = tid >> 5;
    const int wm = warp >> 2, wn = warp & 3;
    const int qg = lane >> 2, qt = lane & 3;

    const int mtile = blockIdx.y * FBM;
    const int ntile = blockIdx.x * FBN;

    float acc[4][4][4];
    #pragma unroll
    for (int mi = 0; mi < 4; ++mi)
        #pragma unroll
        for (int ni = 0; ni < 4; ++ni)
            #pragma unroll
            for (int q = 0; q < 4; ++q) acc[mi][ni][q] = 0.0f;

    float4 ar[2], br[2];
    const int sm0 = tid >> 2, skq = (tid & 3) * 4;
    const int sm1 = (tid + 256) >> 2;
    const int brow0 = (ntile + sm0 > VN) ? VN : ntile + sm0;
    const int brow1 = (ntile + sm1 > VN) ? VN : ntile + sm1;

    {
        ar[0] = *(const float4*)&g_h[(size_t)(mtile + sm0) * HH + skq];
        ar[1] = *(const float4*)&g_h[(size_t)(mtile + sm1) * HH + skq];
        br[0] = *(const float4*)&fw[(size_t)brow0 * HH + skq];
        br[1] = *(const float4*)&fw[(size_t)brow1 * HH + skq];
    }
    {
        uint4 v;
        v.x = f2tf(fmaxf(ar[0].x, 0.f)); v.y = f2tf(fmaxf(ar[0].y, 0.f));
        v.z = f2tf(fmaxf(ar[0].z, 0.f)); v.w = f2tf(fmaxf(ar[0].w, 0.f));
        *(uint4*)&As[0][sm0 * SROW + skq] = v;
        v.x = f2tf(fmaxf(ar[1].x, 0.f)); v.y = f2tf(fmaxf(ar[1].y, 0.f));
        v.z = f2tf(fmaxf(ar[1].z, 0.f)); v.w = f2tf(fmaxf(ar[1].w, 0.f));
        *(uint4*)&As[0][sm1 * SROW + skq] = v;
        v.x = f2tf(br[0].x); v.y = f2tf(br[0].y); v.z = f2tf(br[0].z); v.w = f2tf(br[0].w);
        *(uint4*)&Bs[0][sm0 * SROW + skq] = v;
        v.x = f2tf(br[1].x); v.y = f2tf(br[1].y); v.z = f2tf(br[1].z); v.w = f2tf(br[1].w);
        *(uint4*)&Bs[0][sm1 * SROW + skq] = v;
    }
    __syncthreads();

    int buf = 0;
    for (int kt = 0; kt < HH / FBK; ++kt) {
        if (kt + 1 < HH / FBK) {
            const int kk = (kt + 1) * FBK;
            ar[0] = *(const float4*)&g_h[(size_t)(mtile + sm0) * HH + kk + skq];
            ar[1] = *(const float4*)&g_h[(size_t)(mtile + sm1) * HH + kk + skq];
            br[0] = *(const float4*)&fw[(size_t)brow0 * HH + kk + skq];
            br[1] = *(const float4*)&fw[(size_t)brow1 * HH + kk + skq];
        }
        #pragma unroll
        for (int ks = 0; ks < FBK; ks += 8) {
            unsigned af[4][4];
            #pragma unroll
            for (int mi = 0; mi < 4; ++mi) {
                const int r = wm * 64 + mi * 16 + qg;
                af[mi][0] = As[buf][r * SROW + ks + qt];
                af[mi][1] = As[buf][(r + 8) * SROW + ks + qt];
                af[mi][2] = As[buf][r * SROW + ks + qt + 4];
                af[mi][3] = As[buf][(r + 8) * SROW + ks + qt + 4];
            }
            unsigned bf[4][2];
            #pragma unroll
            for (int ni = 0; ni < 4; ++ni) {
                const int n = wn * 32 + ni * 8 + qg;
                bf[ni][0] = Bs[buf][n * SROW + ks + qt];
                bf[ni][1] = Bs[buf][n * SROW + ks + qt + 4];
            }
            #pragma unroll
            for (int mi = 0; mi < 4; ++mi)
                #pragma unroll
                for (int ni = 0; ni < 4; ++ni)
                    MMA_TF32(acc[mi][ni][0], acc[mi][ni][1], acc[mi][ni][2], acc[mi][ni][3],
                             af[mi][0], af[mi][1], af[mi][2], af[mi][3],
                             bf[ni][0], bf[ni][1]);
        }
        if (kt + 1 < HH / FBK) {
            const int nb = buf ^ 1;
            uint4 v;
            v.x = f2tf(fmaxf(ar[0].x, 0.f)); v.y = f2tf(fmaxf(ar[0].y, 0.f));
            v.z = f2tf(fmaxf(ar[0].z, 0.f)); v.w = f2tf(fmaxf(ar[0].w, 0.f));
            *(uint4*)&As[nb][sm0 * SROW + skq] = v;
            v.x = f2tf(fmaxf(ar[1].x, 0.f)); v.y = f2tf(fmaxf(ar[1].y, 0.f));
            v.z = f2tf(fmaxf(ar[1].z, 0.f)); v.w = f2tf(fmaxf(ar[1].w, 0.f));
            *(uint4*)&As[nb][sm1 * SROW + skq] = v;
            v.x = f2tf(br[0].x); v.y = f2tf(br[0].y); v.z = f2tf(br[0].z); v.w = f2tf(br[0].w);
            *(uint4*)&Bs[nb][sm0 * SROW + skq] = v;
            v.x = f2tf(br[1].x); v.y = f2tf(br[1].y); v.z = f2tf(br[1].z); v.w = f2tf(br[1].w);
            *(uint4*)&Bs[nb][sm1 * SROW + skq] = v;
        }
        __syncthreads();
        buf ^= 1;
    }

    #pragma unroll
    for (int mi = 0; mi < 4; ++mi) {
        #pragma unroll
        for (int rr = 0; rr < 2; ++rr) {
            const int row = mtile + wm * 64 + mi * 16 + qg + rr * 8;   // m'
            const int n = (row & 63) * 128 + (row >> 6);               // out row
            #pragma unroll
            for (int ni = 0; ni < 4; ++ni) {
                #pragma unroll
                for (int cc = 0; cc < 2; ++cc) {
                    const int col = ntile + wn * 32 + ni * 8 + qt * 2 + cc;
                    if (col < VN)
                        out[(size_t)n * VN + col] = acc[mi][ni][rr * 2 + cc] + fb[col];
                    else if (col == VN)
                        out[K_LOC_ELEMS + n] = acc[mi][ni][rr * 2 + cc] + fb[col];
                }
            }
        }
    }
}

// ---------------------------------------------------------------------------
// Softmax: per-row log_softmax (row cached in smem) + time sigmoid.
// ---------------------------------------------------------------------------
__global__ void __launch_bounds__(256)
k_softmax(float* __restrict__ out)
{
    extern __shared__ float row[];       // VN floats
    __shared__ float red[256];

    const int n = blockIdx.x;
    const int tid = threadIdx.x;
    float* base = out + (size_t)n * VN;

    float mx = -1e30f;
    for (int i = tid; i < VN; i += 256) { float v = base[i]; row[i] = v; mx = fmaxf(mx, v); }
    red[tid] = mx; __syncthreads();
    for (int s = 128; s > 0; s >>= 1) { if (tid < s) red[tid] = fmaxf(red[tid], red[tid + s]); __syncthreads(); }
    mx = red[0];
    __syncthreads();

    float sum = 0.f;
    for (int i = tid; i < VN; i += 256) sum += expf(row[i] - mx);
    red[tid] = sum; __syncthreads();
    for (int s = 128; s > 0; s >>= 1) { if (tid < s) red[tid] += red[tid + s]; __syncthreads(); }
    float lse = mx + logf(red[0]);

    for (int i = tid; i < VN; i += 256) base[i] = row[i] - lse;

    if (tid == 0) {
        float tl = out[K_LOC_ELEMS + n];
        out[K_LOC_ELEMS + n] = 1.0f / (1.0f + expf(-tl));
    }
}

// ---------------------------------------------------------------------------
// Launch
// ---------------------------------------------------------------------------
extern "C" void kernel_launch(void* const* d_in, const int* in_sizes, int n_in,
                              void* d_out, int out_size)
{
    const int*   loc   = (const int*)  d_in[0];
    const float* times = (const float*)d_in[1];
    const float* emb   = (const float*)d_in[2];
    const float* w_ih0 = (const float*)d_in[3];
    const float* w_hh0 = (const float*)d_in[4];
    const float* b_ih0 = (const float*)d_in[5];
    const float* b_hh0 = (const float*)d_in[6];
    const float* w_ih1 = (const float*)d_in[7];
    const float* w_hh1 = (const float*)d_in[8];
    const float* b_ih1 = (const float*)d_in[9];
    const float* b_hh1 = (const float*)d_in[10];
    const float* fc_w  = (const float*)d_in[11];
    const float* fc_b  = (const float*)d_in[12];
    float* out = (float*)d_out;

    const int gru_smem = (2 * NGR * SP + BH * SP + NGR * 33) * sizeof(float); // ~168 KB
    static int attr_done = 0;
    if (!attr_done) {
        cudaFuncSetAttribute(k_gru_tc, cudaFuncAttributeMaxDynamicSharedMemorySize, gru_smem);
        attr_done = 1;
    }

    // Layer 0
    k_proj0<<<dim3(G3 / 64, NR / 64), 256>>>(loc, times, emb, w_ih0, b_ih0);
    k_zero_state<<<(BB * HH + 255) / 256, 256>>>();
    k_gru_tc<<<NCTA, 256, gru_smem>>>(w_hh0, b_hh0);

    // Layer 1
    k_proj1_tc<<<dim3(G3 / FBN, NR / FBM), 256>>>(w_ih1, b_ih1);
    k_zero_state<<<(BB * HH + 255) / 256, 256>>>();
    k_gru_tc<<<NCTA, 256, gru_smem>>>(w_hh1, b_hh1);

    // FC -> logits straight into d_out (tensor cores, tf32)
    k_fc_tc<<<dim3((VOUT + FBN - 1) / FBN, NR / FBM), 256>>>(fc_w, fc_b, out);

    // log_softmax + time sigmoid
    k_softmax<<<NR, 256, VN * sizeof(float)>>>(out);
}

// round 10
// speedup vs baseline: 2.3554x; 1.1129x over previous
#include <cuda_runtime.h>
#include <math.h>

// Problem constants
#define VN   10000
#define VOUT 10001
#define EE   256
#define HH   512
#define G3   1536
#define BB   64
#define TT   128
#define NR   8192            // BB*TT
#define K_LOC_ELEMS ((size_t)NR * VN)   // 81,920,000 floats of location logits

// Persistent recurrence config: 128 CTAs = 64 j-groups x 2 batch halves
#define NCTA 128
#define JH   8               // hidden dims per CTA
#define NGR  24              // gate rows per CTA (3 per dim)
#define BH   32              // batches per CTA
#define SP   516             // padded k-row (512+4): conflict-free frag loads

// Tensor-core GEMM tiling (proj0/proj1/fc)
#define FBM 128
#define FBN 128
#define FBK 16
#define SROW 20

// Scratch (device globals; no allocations allowed)
// g_xp layout: [t][gate][j][b]  -> ((t*3+gate)*512 + j)*64 + b
__device__ float g_xp[(size_t)NR * G3];
// g_h layout: [m'=t*64+b][j]
__device__ float g_h [(size_t)NR * HH];
__device__ float g_state[BB * HH];          // [b][k]
__device__ __align__(128) unsigned g_epoch[32];

__device__ __forceinline__ unsigned f2tf(float x) {
    unsigned u;
    asm("cvt.rna.tf32.f32 %0, %1;" : "=r"(u) : "f"(x));
    return u;
}

#define MMA_TF32(c0,c1,c2,c3, a0,a1,a2,a3, b0,b1)                         \
    asm volatile(                                                          \
        "mma.sync.aligned.m16n8k8.row.col.f32.tf32.tf32.f32 "             \
        "{%0,%1,%2,%3}, {%4,%5,%6,%7}, {%8,%9}, {%0,%1,%2,%3};"           \
        : "+f"(c0), "+f"(c1), "+f"(c2), "+f"(c3)                           \
        : "r"(a0), "r"(a1), "r"(a2), "r"(a3), "r"(b0), "r"(b1))

// ---------------------------------------------------------------------------
__global__ void k_zero_state() {
    int i = blockIdx.x * blockDim.x + threadIdx.x;
    if (i < BB * HH) g_state[i] = 0.0f;
    if (i == 0) g_epoch[0] = 0;
}

__device__ __forceinline__ void grid_epoch_bar(unsigned target) {
    __syncthreads();
    if (threadIdx.x == 0) {
        __threadfence();
        atomicAdd(&g_epoch[0], 1u);
        while (*((volatile unsigned*)&g_epoch[0]) < target) { }
        __threadfence();
    }
    __syncthreads();
}

// ---------------------------------------------------------------------------
// Persistent GRU via tf32 tensor cores with hi/lo split.
// 3 independent accumulator chains (hi*hi, hi*lo, lo*hi) for mma ILP.
// xp gate inputs + biases prefetched before the mma phase.
// ---------------------------------------------------------------------------
__global__ void __launch_bounds__(256)
k_gru_tc(const float* __restrict__ whh, const float* __restrict__ bhh)
{
    extern __shared__ float smem[];
    float* Whi = smem;                     // [24][516]
    float* Wlo = Whi + NGR * SP;           // [24][516]
    float* Ss  = Wlo + NGR * SP;           // [32][516]
    float* Cs  = Ss + BH * SP;             // [24][33]

    const int tid = threadIdx.x;
    const int cta = blockIdx.x;
    const int jg = cta >> 1, bh = cta & 1;
    const int j0 = jg * JH;
    const int gb0 = bh * BH;

    // Load + split weight tile once
    for (int i = tid; i < NGR * 512; i += 256) {
        const int g = i >> 9, k = i & 511;
        const int jj = g / 3, gate = g - 3 * (g / 3);
        float w = whh[(size_t)(gate * 512 + j0 + jj) * HH + k];
        unsigned hu = f2tf(w);
        float hf = __uint_as_float(hu);
        Whi[g * SP + k] = hf;
        Wlo[g * SP + k] = __uint_as_float(f2tf(w - hf));
    }

    const int lane = tid & 31, warp = tid >> 5;
    const int qg = lane >> 2, qt = lane & 3;
    const int mi = warp >> 2, ni = warp & 3;
    const int m0 = mi * 8;
    const int n0 = ni * 8;

    // gate-phase coords: 1 (j,b) per thread
    const int jj = tid >> 5;               // 0..7
    const int bl = tid & 31;
    const int gjg = j0 + jj;
    const int gb = gb0 + bl;

    // biases: constant across steps
    const float bias_r = __ldg(&bhh[gjg]);
    const float bias_z = __ldg(&bhh[512 + gjg]);
    const float bias_n = __ldg(&bhh[1024 + gjg]);

    const float* ahp = &Whi[(m0 + qg) * SP + qt];
    const float* alp = &Wlo[(m0 + qg) * SP + qt];
    const float* bp  = &Ss[(n0 + qg) * SP + qt];

    unsigned target = NCTA;

    for (int t = 0; t < TT; ++t) {
        // Coalesced state gather: 32 rows x 2KB
        for (int i = tid; i < BH * 128; i += 256) {
            const int b = i >> 7, kq = (i & 127) << 2;
            float4 v = __ldcg((const float4*)&g_state[(size_t)(gb0 + b) * HH + kq]);
            *(float4*)&Ss[b * SP + kq] = v;
        }

        // Prefetch xp gate inputs (DRAM) so latency overlaps the mma phase
        const float xr = __ldg(&g_xp[((size_t)(t * 3 + 0) * 512 + gjg) * 64 + gb]);
        const float xz = __ldg(&g_xp[((size_t)(t * 3 + 1) * 512 + gjg) * 64 + gb]);
        const float xn = __ldg(&g_xp[((size_t)(t * 3 + 2) * 512 + gjg) * 64 + gb]);
        __syncthreads();

        // 3 independent accumulator chains
        float h0=0.f,h1=0.f,h2=0.f,h3=0.f;     // hi*hi
        float m0a=0.f,m1a=0.f,m2a=0.f,m3a=0.f; // hi*lo
        float l0=0.f,l1=0.f,l2=0.f,l3=0.f;     // lo*hi
        #pragma unroll 4
        for (int kt = 0; kt < 64; ++kt) {
            const int k0 = kt * 8;
            unsigned ah0 = __float_as_uint(ahp[k0]);
            unsigned ah1 = __float_as_uint(ahp[8 * SP + k0]);
            unsigned ah2 = __float_as_uint(ahp[k0 + 4]);
            unsigned ah3 = __float_as_uint(ahp[8 * SP + k0 + 4]);
            unsigned al0 = __float_as_uint(alp[k0]);
            unsigned al1 = __float_as_uint(alp[8 * SP + k0]);
            unsigned al2 = __float_as_uint(alp[k0 + 4]);
            unsigned al3 = __float_as_uint(alp[8 * SP + k0 + 4]);
            float s0 = bp[k0], s1 = bp[k0 + 4];
            unsigned bh0 = f2tf(s0);
            unsigned bl0 = f2tf(s0 - __uint_as_float(bh0));
            unsigned bh1 = f2tf(s1);
            unsigned bl1 = f2tf(s1 - __uint_as_float(bh1));

            MMA_TF32(h0, h1, h2, h3, ah0, ah1, ah2, ah3, bh0, bh1);
            MMA_TF32(m0a, m1a, m2a, m3a, ah0, ah1, ah2, ah3, bl0, bl1);
            MMA_TF32(l0, l1, l2, l3, al0, al1, al2, al3, bh0, bh1);
        }
        float c0 = h0 + m0a + l0;
        float c1 = h1 + m1a + l1;
        float c2 = h2 + m2a + l2;
        float c3 = h3 + m3a + l3;

        // Write C frags to Cs[gate_row][b]; mi=1 keeps only rows 16..23
        if (mi == 0) {
            Cs[qg * 33 + n0 + 2 * qt]         = c0;
            Cs[qg * 33 + n0 + 2 * qt + 1]     = c1;
            Cs[(qg + 8) * 33 + n0 + 2 * qt]   = c2;
            Cs[(qg + 8) * 33 + n0 + 2 * qt+1] = c3;
        } else {
            Cs[(16 + qg) * 33 + n0 + 2 * qt]     = c2;
            Cs[(16 + qg) * 33 + n0 + 2 * qt + 1] = c3;
        }
        __syncthreads();

        // Gate math
        {
            float sr = Cs[(jj * 3 + 0) * 33 + bl] + bias_r;
            float sz = Cs[(jj * 3 + 1) * 33 + bl] + bias_z;
            float sn = Cs[(jj * 3 + 2) * 33 + bl] + bias_n;

            float r  = 1.0f / (1.0f + expf(-(xr + sr)));
            float z  = 1.0f / (1.0f + expf(-(xz + sz)));
            float nn = tanhf(xn + r * sn);

            float hold = Ss[bl * SP + gjg];
            float hnew = (1.0f - z) * nn + z * hold;
            g_state[(size_t)gb * HH + gjg] = hnew;
            g_h[((size_t)t * 64 + gb) * HH + gjg] = hnew;
        }

        grid_epoch_bar(target);
        target += NCTA;
    }
}

// ---------------------------------------------------------------------------
// proj0 via tf32 TC: xpT = emb[loc] @ w0[:, :256]^T (+ time*w0[:,256] + b0).
// M = 8192 (loc order n = b*128+t), N = 1536, K = 256.
// ---------------------------------------------------------------------------
__global__ void __launch_bounds__(256)
k_proj0_tc(const int* __restrict__ loc, const float* __restrict__ times,
           const float* __restrict__ emb, const float* __restrict__ w0,
           const float* __restrict__ b0)
{
    __shared__ unsigned As[2][FBM * SROW];
    __shared__ unsigned Bs[2][FBN * SROW];
    __shared__ int locs[FBM];

    const int tid  = threadIdx.x;
    const int lane = tid & 31;
    const int warp = tid >> 5;
    const int wm = warp >> 2, wn = warp & 3;
    const int qg = lane >> 2, qt = lane & 3;

    const int mtile = blockIdx.y * FBM;
    const int ntile = blockIdx.x * FBN;

    if (tid < FBM) locs[tid] = loc[mtile + tid];
    __syncthreads();

    float acc[4][4][4];
    #pragma unroll
    for (int mi = 0; mi < 4; ++mi)
        #pragma unroll
        for (int ni = 0; ni < 4; ++ni)
            #pragma unroll
            for (int q = 0; q < 4; ++q) acc[mi][ni][q] = 0.0f;

    float4 ar[2], br[2];
    const int sm0 = tid >> 2, skq = (tid & 3) * 4;
    const int sm1 = (tid + 256) >> 2;
    const int rowA0 = locs[sm0], rowA1 = locs[sm1];
    const float* bptr0 = w0 + (size_t)(ntile + sm0) * 257;
    const float* bptr1 = w0 + (size_t)(ntile + sm1) * 257;

    {
        ar[0] = *(const float4*)&emb[(size_t)rowA0 * EE + skq];
        ar[1] = *(const float4*)&emb[(size_t)rowA1 * EE + skq];
        br[0].x = bptr0[skq]; br[0].y = bptr0[skq + 1]; br[0].z = bptr0[skq + 2]; br[0].w = bptr0[skq + 3];
        br[1].x = bptr1[skq]; br[1].y = bptr1[skq + 1]; br[1].z = bptr1[skq + 2]; br[1].w = bptr1[skq + 3];
    }
    {
        uint4 v;
        v.x = f2tf(ar[0].x); v.y = f2tf(ar[0].y); v.z = f2tf(ar[0].z); v.w = f2tf(ar[0].w);
        *(uint4*)&As[0][sm0 * SROW + skq] = v;
        v.x = f2tf(ar[1].x); v.y = f2tf(ar[1].y); v.z = f2tf(ar[1].z); v.w = f2tf(ar[1].w);
        *(uint4*)&As[0][sm1 * SROW + skq] = v;
        v.x = f2tf(br[0].x); v.y = f2tf(br[0].y); v.z = f2tf(br[0].z); v.w = f2tf(br[0].w);
        *(uint4*)&Bs[0][sm0 * SROW + skq] = v;
        v.x = f2tf(br[1].x); v.y = f2tf(br[1].y); v.z = f2tf(br[1].z); v.w = f2tf(br[1].w);
        *(uint4*)&Bs[0][sm1 * SROW + skq] = v;
    }
    __syncthreads();

    int buf = 0;
    const int NKT = EE / FBK;   // 16
    for (int kt = 0; kt < NKT; ++kt) {
        if (kt + 1 < NKT) {
            const int kk = (kt + 1) * FBK;
            ar[0] = *(const float4*)&emb[(size_t)rowA0 * EE + kk + skq];
            ar[1] = *(const float4*)&emb[(size_t)rowA1 * EE + kk + skq];
            br[0].x = bptr0[kk + skq]; br[0].y = bptr0[kk + skq + 1];
            br[0].z = bptr0[kk + skq + 2]; br[0].w = bptr0[kk + skq + 3];
            br[1].x = bptr1[kk + skq]; br[1].y = bptr1[kk + skq + 1];
            br[1].z = bptr1[kk + skq + 2]; br[1].w = bptr1[kk + skq + 3];
        }
        #pragma unroll
        for (int ks = 0; ks < FBK; ks += 8) {
            unsigned af[4][4];
            #pragma unroll
            for (int mi = 0; mi < 4; ++mi) {
                const int r = wm * 64 + mi * 16 + qg;
                af[mi][0] = As[buf][r * SROW + ks + qt];
                af[mi][1] = As[buf][(r + 8) * SROW + ks + qt];
                af[mi][2] = As[buf][r * SROW + ks + qt + 4];
                af[mi][3] = As[buf][(r + 8) * SROW + ks + qt + 4];
            }
            unsigned bf[4][2];
            #pragma unroll
            for (int ni = 0; ni < 4; ++ni) {
                const int n = wn * 32 + ni * 8 + qg;
                bf[ni][0] = Bs[buf][n * SROW + ks + qt];
                bf[ni][1] = Bs[buf][n * SROW + ks + qt + 4];
            }
            #pragma unroll
            for (int mi = 0; mi < 4; ++mi)
                #pragma unroll
                for (int ni = 0; ni < 4; ++ni)
                    MMA_TF32(acc[mi][ni][0], acc[mi][ni][1], acc[mi][ni][2], acc[mi][ni][3],
                             af[mi][0], af[mi][1], af[mi][2], af[mi][3],
                             bf[ni][0], bf[ni][1]);
        }
        if (kt + 1 < NKT) {
            const int nb = buf ^ 1;
            uint4 v;
            v.x = f2tf(ar[0].x); v.y = f2tf(ar[0].y); v.z = f2tf(ar[0].z); v.w = f2tf(ar[0].w);
            *(uint4*)&As[nb][sm0 * SROW + skq] = v;
            v.x = f2tf(ar[1].x); v.y = f2tf(ar[1].y); v.z = f2tf(ar[1].z); v.w = f2tf(ar[1].w);
            *(uint4*)&As[nb][sm1 * SROW + skq] = v;
            v.x = f2tf(br[0].x); v.y = f2tf(br[0].y); v.z = f2tf(br[0].z); v.w = f2tf(br[0].w);
            *(uint4*)&Bs[nb][sm0 * SROW + skq] = v;
            v.x = f2tf(br[1].x); v.y = f2tf(br[1].y); v.z = f2tf(br[1].z); v.w = f2tf(br[1].w);
            *(uint4*)&Bs[nb][sm1 * SROW + skq] = v;
        }
        __syncthreads();
        buf ^= 1;
    }

    // Epilogue -> transposed xp, + time * w0[:,256] + b0
    #pragma unroll
    for (int mi = 0; mi < 4; ++mi) {
        #pragma unroll
        for (int rr = 0; rr < 2; ++rr) {
            const int row = mtile + wm * 64 + mi * 16 + qg + rr * 8;   // n = b*128+t
            const int tt = row & 127, b = row >> 7;
            const float tm = __ldg(&times[row]);
            #pragma unroll
            for (int ni = 0; ni < 4; ++ni) {
                #pragma unroll
                for (int cc = 0; cc < 2; ++cc) {
                    const int col = ntile + wn * 32 + ni * 8 + qt * 2 + cc;
                    const int gate = col >> 9, jdim = col & 511;
                    g_xp[((size_t)(tt * 3 + gate) * 512 + jdim) * 64 + b] =
                        acc[mi][ni][rr * 2 + cc]
                        + tm * __ldg(&w0[(size_t)col * 257 + 256]) + __ldg(&b0[col]);
                }
            }
        }
    }
}

// ---------------------------------------------------------------------------
// proj1 via tf32 TC: xpT = g_h @ w1^T + b1.  M=8192, N=1536, K=512.
// ---------------------------------------------------------------------------
__global__ void __launch_bounds__(256)
k_proj1_tc(const float* __restrict__ w1, const float* __restrict__ b1)
{
    __shared__ unsigned As[2][FBM * SROW];
    __shared__ unsigned Bs[2][FBN * SROW];

    const int tid  = threadIdx.x;
    const int lane = tid & 31;
    const int warp = tid >> 5;
    const int wm = warp >> 2, wn = warp & 3;
    const int qg = lane >> 2, qt = lane & 3;

    const int mtile = blockIdx.y * FBM;
    const int ntile = blockIdx.x * FBN;

    float acc[4][4][4];
    #pragma unroll
    for (int mi = 0; mi < 4; ++mi)
        #pragma unroll
        for (int ni = 0; ni < 4; ++ni)
            #pragma unroll
            for (int q = 0; q < 4; ++q) acc[mi][ni][q] = 0.0f;

    float4 ar[2], br[2];
    const int sm0 = tid >> 2, skq = (tid & 3) * 4;
    const int sm1 = (tid + 256) >> 2;

    {
        ar[0] = *(const float4*)&g_h[(size_t)(mtile + sm0) * HH + skq];
        ar[1] = *(const float4*)&g_h[(size_t)(mtile + sm1) * HH + skq];
        br[0] = *(const float4*)&w1[(size_t)(ntile + sm0) * HH + skq];
        br[1] = *(const float4*)&w1[(size_t)(ntile + sm1) * HH + skq];
    }
    {
        uint4 v;
        v.x = f2tf(ar[0].x); v.y = f2tf(ar[0].y); v.z = f2tf(ar[0].z); v.w = f2tf(ar[0].w);
        *(uint4*)&As[0][sm0 * SROW + skq] = v;
        v.x = f2tf(ar[1].x); v.y = f2tf(ar[1].y); v.z = f2tf(ar[1].z); v.w = f2tf(ar[1].w);
        *(uint4*)&As[0][sm1 * SROW + skq] = v;
        v.x = f2tf(br[0].x); v.y = f2tf(br[0].y); v.z = f2tf(br[0].z); v.w = f2tf(br[0].w);
        *(uint4*)&Bs[0][sm0 * SROW + skq] = v;
        v.x = f2tf(br[1].x); v.y = f2tf(br[1].y); v.z = f2tf(br[1].z); v.w = f2tf(br[1].w);
        *(uint4*)&Bs[0][sm1 * SROW + skq] = v;
    }
    __syncthreads();

    int buf = 0;
    for (int kt = 0; kt < HH / FBK; ++kt) {
        if (kt + 1 < HH / FBK) {
            const int kk = (kt + 1) * FBK;
            ar[0] = *(const float4*)&g_h[(size_t)(mtile + sm0) * HH + kk + skq];
            ar[1] = *(const float4*)&g_h[(size_t)(mtile + sm1) * HH + kk + skq];
            br[0] = *(const float4*)&w1[(size_t)(ntile + sm0) * HH + kk + skq];
            br[1] = *(const float4*)&w1[(size_t)(ntile + sm1) * HH + kk + skq];
        }
        #pragma unroll
        for (int ks = 0; ks < FBK; ks += 8) {
            unsigned af[4][4];
            #pragma unroll
            for (int mi = 0; mi < 4; ++mi) {
                const int r = wm * 64 + mi * 16 + qg;
                af[mi][0] = As[buf][r * SROW + ks + qt];
                af[mi][1] = As[buf][(r + 8) * SROW + ks + qt];
                af[mi][2] = As[buf][r * SROW + ks + qt + 4];
                af[mi][3] = As[buf][(r + 8) * SROW + ks + qt + 4];
            }
            unsigned bf[4][2];
            #pragma unroll
            for (int ni = 0; ni < 4; ++ni) {
                const int n = wn * 32 + ni * 8 + qg;
                bf[ni][0] = Bs[buf][n * SROW + ks + qt];
                bf[ni][1] = Bs[buf][n * SROW + ks + qt + 4];
            }
            #pragma unroll
            for (int mi = 0; mi < 4; ++mi)
                #pragma unroll
                for (int ni = 0; ni < 4; ++ni)
                    MMA_TF32(acc[mi][ni][0], acc[mi][ni][1], acc[mi][ni][2], acc[mi][ni][3],
                             af[mi][0], af[mi][1], af[mi][2], af[mi][3],
                             bf[ni][0], bf[ni][1]);
        }
        if (kt + 1 < HH / FBK) {
            const int nb = buf ^ 1;
            uint4 v;
            v.x = f2tf(ar[0].x); v.y = f2tf(ar[0].y); v.z = f2tf(ar[0].z); v.w = f2tf(ar[0].w);
            *(uint4*)&As[nb][sm0 * SROW + skq] = v;
            v.x = f2tf(ar[1].x); v.y = f2tf(ar[1].y); v.z = f2tf(ar[1].z); v.w = f2tf(ar[1].w);
            *(uint4*)&As[nb][sm1 * SROW + skq] = v;
            v.x = f2tf(br[0].x); v.y = f2tf(br[0].y); v.z = f2tf(br[0].z); v.w = f2tf(br[0].w);
            *(uint4*)&Bs[nb][sm0 * SROW + skq] = v;
            v.x = f2tf(br[1].x); v.y = f2tf(br[1].y); v.z = f2tf(br[1].z); v.w = f2tf(br[1].w);
            *(uint4*)&Bs[nb][sm1 * SROW + skq] = v;
        }
        __syncthreads();
        buf ^= 1;
    }

    // Epilogue -> transposed xp
    #pragma unroll
    for (int mi = 0; mi < 4; ++mi) {
        #pragma unroll
        for (int rr = 0; rr < 2; ++rr) {
            const int row = mtile + wm * 64 + mi * 16 + qg + rr * 8;   // m' = t*64+b
            const int tt = row >> 6, b = row & 63;
            #pragma unroll
            for (int ni = 0; ni < 4; ++ni) {
                #pragma unroll
                for (int cc = 0; cc < 2; ++cc) {
                    const int col = ntile + wn * 32 + ni * 8 + qt * 2 + cc;
                    const int gate = col >> 9, jdim = col & 511;
                    g_xp[((size_t)(tt * 3 + gate) * 512 + jdim) * 64 + b] =
                        acc[mi][ni][rr * 2 + cc] + b1[col];
                }
            }
        }
    }
}

// ---------------------------------------------------------------------------
// FC via tf32 TC. A rows are m'=t*64+b; output rows remapped to n=b*128+t.
// ---------------------------------------------------------------------------
__global__ void __launch_bounds__(256)
k_fc_tc(const float* __restrict__ fw, const float* __restrict__ fb,
        float* __restrict__ out)
{
    __shared__ unsigned As[2][FBM * SROW];
    __shared__ unsigned Bs[2][FBN * SROW];

    const int tid  = threadIdx.x;
    const int lane = tid & 31;
    const int warp = tid >> 5;
    const int wm = warp >> 2, wn = warp & 3;
    const int qg = lane >> 2, qt = lane & 3;

    const int mtile = blockIdx.y * FBM;
    const int ntile = blockIdx.x * FBN;

    float acc[4][4][4];
    #pragma unroll
    for (int mi = 0; mi < 4; ++mi)
        #pragma unroll
        for (int ni = 0; ni < 4; ++ni)
            #pragma unroll
            for (int q = 0; q < 4; ++q) acc[mi][ni][q] = 0.0f;

    float4 ar[2], br[2];
    const int sm0 = tid >> 2, skq = (tid & 3) * 4;
    const int sm1 = (tid + 256) >> 2;
    const int brow0 = (ntile + sm0 > VN) ? VN : ntile + sm0;
    const int brow1 = (ntile + sm1 > VN) ? VN : ntile + sm1;

    {
        ar[0] = *(const float4*)&g_h[(size_t)(mtile + sm0) * HH + skq];
        ar[1] = *(const float4*)&g_h[(size_t)(mtile + sm1) * HH + skq];
        br[0] = *(const float4*)&fw[(size_t)brow0 * HH + skq];
        br[1] = *(const float4*)&fw[(size_t)brow1 * HH + skq];
    }
    {
        uint4 v;
        v.x = f2tf(fmaxf(ar[0].x, 0.f)); v.y = f2tf(fmaxf(ar[0].y, 0.f));
        v.z = f2tf(fmaxf(ar[0].z, 0.f)); v.w = f2tf(fmaxf(ar[0].w, 0.f));
        *(uint4*)&As[0][sm0 * SROW + skq] = v;
        v.x = f2tf(fmaxf(ar[1].x, 0.f)); v.y = f2tf(fmaxf(ar[1].y, 0.f));
        v.z = f2tf(fmaxf(ar[1].z, 0.f)); v.w = f2tf(fmaxf(ar[1].w, 0.f));
        *(uint4*)&As[0][sm1 * SROW + skq] = v;
        v.x = f2tf(br[0].x); v.y = f2tf(br[0].y); v.z = f2tf(br[0].z); v.w = f2tf(br[0].w);
        *(uint4*)&Bs[0][sm0 * SROW + skq] = v;
        v.x = f2tf(br[1].x); v.y = f2tf(br[1].y); v.z = f2tf(br[1].z); v.w = f2tf(br[1].w);
        *(uint4*)&Bs[0][sm1 * SROW + skq] = v;
    }
    __syncthreads();

    int buf = 0;
    for (int kt = 0; kt < HH / FBK; ++kt) {
        if (kt + 1 < HH / FBK) {
            const int kk = (kt + 1) * FBK;
            ar[0] = *(const float4*)&g_h[(size_t)(mtile + sm0) * HH + kk + skq];
            ar[1] = *(const float4*)&g_h[(size_t)(mtile + sm1) * HH + kk + skq];
            br[0] = *(const float4*)&fw[(size_t)brow0 * HH + kk + skq];
            br[1] = *(const float4*)&fw[(size_t)brow1 * HH + kk + skq];
        }
        #pragma unroll
        for (int ks = 0; ks < FBK; ks += 8) {
            unsigned af[4][4];
            #pragma unroll
            for (int mi = 0; mi < 4; ++mi) {
                const int r = wm * 64 + mi * 16 + qg;
                af[mi][0] = As[buf][r * SROW + ks + qt];
                af[mi][1] = As[buf][(r + 8) * SROW + ks + qt];
                af[mi][2] = As[buf][r * SROW + ks + qt + 4];
                af[mi][3] = As[buf][(r + 8) * SROW + ks + qt + 4];
            }
            unsigned bf[4][2];
            #pragma unroll
            for (int ni = 0; ni < 4; ++ni) {
                const int n = wn * 32 + ni * 8 + qg;
                bf[ni][0] = Bs[buf][n * SROW + ks + qt];
                bf[ni][1] = Bs[buf][n * SROW + ks + qt + 4];
            }
            #pragma unroll
            for (int mi = 0; mi < 4; ++mi)
                #pragma unroll
                for (int ni = 0; ni < 4; ++ni)
                    MMA_TF32(acc[mi][ni][0], acc[mi][ni][1], acc[mi][ni][2], acc[mi][ni][3],
                             af[mi][0], af[mi][1], af[mi][2], af[mi][3],
                             bf[ni][0], bf[ni][1]);
        }
        if (kt + 1 < HH / FBK) {
            const int nb = buf ^ 1;
            uint4 v;
            v.x = f2tf(fmaxf(ar[0].x, 0.f)); v.y = f2tf(fmaxf(ar[0].y, 0.f));
            v.z = f2tf(fmaxf(ar[0].z, 0.f)); v.w = f2tf(fmaxf(ar[0].w, 0.f));
            *(uint4*)&As[nb][sm0 * SROW + skq] = v;
            v.x = f2tf(fmaxf(ar[1].x, 0.f)); v.y = f2tf(fmaxf(ar[1].y, 0.f));
            v.z = f2tf(fmaxf(ar[1].z, 0.f)); v.w = f2tf(fmaxf(ar[1].w, 0.f));
            *(uint4*)&As[nb][sm1 * SROW + skq] = v;
            v.x = f2tf(br[0].x); v.y = f2tf(br[0].y); v.z = f2tf(br[0].z); v.w = f2tf(br[0].w);
            *(uint4*)&Bs[nb][sm0 * SROW + skq] = v;
            v.x = f2tf(br[1].x); v.y = f2tf(br[1].y); v.z = f2tf(br[1].z); v.w = f2tf(br[1].w);
            *(uint4*)&Bs[nb][sm1 * SROW + skq] = v;
        }
        __syncthreads();
        buf ^= 1;
    }

    #pragma unroll
    for (int mi = 0; mi < 4; ++mi) {
        #pragma unroll
        for (int rr = 0; rr < 2; ++rr) {
            const int row = mtile + wm * 64 + mi * 16 + qg + rr * 8;   // m'
            const int n = (row & 63) * 128 + (row >> 6);               // out row
            #pragma unroll
            for (int ni = 0; ni < 4; ++ni) {
                #pragma unroll
                for (int cc = 0; cc < 2; ++cc) {
                    const int col = ntile + wn * 32 + ni * 8 + qt * 2 + cc;
                    if (col < VN)
                        out[(size_t)n * VN + col] = acc[mi][ni][rr * 2 + cc] + fb[col];
                    else if (col == VN)
                        out[K_LOC_ELEMS + n] = acc[mi][ni][rr * 2 + cc] + fb[col];
                }
            }
        }
    }
}

// ---------------------------------------------------------------------------
// Softmax: per-row log_softmax (row cached in smem, float4 I/O) + time sigmoid.
// ---------------------------------------------------------------------------
__global__ void __launch_bounds__(256)
k_softmax(float* __restrict__ out)
{
    extern __shared__ float row[];       // VN floats
    __shared__ float red[256];

    const int n = blockIdx.x;
    const int tid = threadIdx.x;
    float* base = out + (size_t)n * VN;
    const float4* b4 = (const float4*)base;
    float4* r4 = (float4*)row;
    const int NQ = VN / 4;               // 2500

    float mx = -1e30f;
    for (int i = tid; i < NQ; i += 256) {
        float4 v = b4[i];
        r4[i] = v;
        mx = fmaxf(mx, fmaxf(fmaxf(v.x, v.y), fmaxf(v.z, v.w)));
    }
    red[tid] = mx; __syncthreads();
    for (int s = 128; s > 0; s >>= 1) { if (tid < s) red[tid] = fmaxf(red[tid], red[tid + s]); __syncthreads(); }
    mx = red[0];
    __syncthreads();

    float sum = 0.f;
    for (int i = tid; i < NQ; i += 256) {
        float4 v = r4[i];
        sum += expf(v.x - mx) + expf(v.y - mx) + expf(v.z - mx) + expf(v.w - mx);
    }
    red[tid] = sum; __syncthreads();
    for (int s = 128; s > 0; s >>= 1) { if (tid < s) red[tid] += red[tid + s]; __syncthreads(); }
    float lse = mx + logf(red[0]);

    for (int i = tid; i < NQ; i += 256) {
        float4 v = r4[i];
        v.x -= lse; v.y -= lse; v.z -= lse; v.w -= lse;
        ((float4*)base)[i] = v;
    }

    if (tid == 0) {
        float tl = out[K_LOC_ELEMS + n];
        out[K_LOC_ELEMS + n] = 1.0f / (1.0f + expf(-tl));
    }
}

// ---------------------------------------------------------------------------
// Launch
// ---------------------------------------------------------------------------
extern "C" void kernel_launch(void* const* d_in, const int* in_sizes, int n_in,
                              void* d_out, int out_size)
{
    const int*   loc   = (const int*)  d_in[0];
    const float* times = (const float*)d_in[1];
    const float* emb   = (const float*)d_in[2];
    const float* w_ih0 = (const float*)d_in[3];
    const float* w_hh0 = (const float*)d_in[4];
    const float* b_ih0 = (const float*)d_in[5];
    const float* b_hh0 = (const float*)d_in[6];
    const float* w_ih1 = (const float*)d_in[7];
    const float* w_hh1 = (const float*)d_in[8];
    const float* b_ih1 = (const float*)d_in[9];
    const float* b_hh1 = (const float*)d_in[10];
    const float* fc_w  = (const float*)d_in[11];
    const float* fc_b  = (const float*)d_in[12];
    float* out = (float*)d_out;

    const int gru_smem = (2 * NGR * SP + BH * SP + NGR * 33) * sizeof(float); // ~168 KB
    static int attr_done = 0;
    if (!attr_done) {
        cudaFuncSetAttribute(k_gru_tc, cudaFuncAttributeMaxDynamicSharedMemorySize, gru_smem);
        attr_done = 1;
    }

    // Layer 0
    k_proj0_tc<<<dim3(G3 / FBN, NR / FBM), 256>>>(loc, times, emb, w_ih0, b_ih0);
    k_zero_state<<<(BB * HH + 255) / 256, 256>>>();
    k_gru_tc<<<NCTA, 256, gru_smem>>>(w_hh0, b_hh0);

    // Layer 1
    k_proj1_tc<<<dim3(G3 / FBN, NR / FBM), 256>>>(w_ih1, b_ih1);
    k_zero_state<<<(BB * HH + 255) / 256, 256>>>();
    k_gru_tc<<<NCTA, 256, gru_smem>>>(w_hh1, b_hh1);

    // FC -> logits straight into d_out (tensor cores, tf32)
    k_fc_tc<<<dim3((VOUT + FBN - 1) / FBN, NR / FBM), 256>>>(fc_w, fc_b, out);

    // log_softmax + time sigmoid
    k_softmax<<<NR, 256, VN * sizeof(float)>>>(out);
}

// round 12
// speedup vs baseline: 2.3798x; 1.0104x over previous
#include <cuda_runtime.h>
#include <math.h>

// Problem constants
#define VN   10000
#define VOUT 10001
#define EE   256
#define HH   512
#define G3   1536
#define BB   64
#define TT   128
#define NR   8192            // BB*TT
#define K_LOC_ELEMS ((size_t)NR * VN)   // 81,920,000 floats of location logits

// Persistent recurrence config: 128 CTAs = 64 j-groups x 2 batch halves
#define NCTA 128
#define JH   8               // hidden dims per CTA
#define NGR  24              // gate rows per CTA (3 per dim)
#define BH   32              // batches per CTA
#define SP3  520             // frag-packed row stride (==8 mod 32: conflict-free)

// Tensor-core GEMM tiling (proj0/proj1/fc)
#define FBM 128
#define FBN 128
#define FBK 16
#define SROW 20

// Scratch (device globals; no allocations allowed)
// g_xp layout: [t][gate][j][b]  -> ((t*3+gate)*512 + j)*64 + b
__device__ float g_xp[(size_t)NR * G3];
// g_h layout: [m'=t*64+b][j]
__device__ float g_h [(size_t)NR * HH];
__device__ float g_state[BB * HH];          // [b][k]
__device__ __align__(128) unsigned g_epoch[32];

__device__ __forceinline__ unsigned f2tf(float x) {
    unsigned u;
    asm("cvt.rna.tf32.f32 %0, %1;" : "=r"(u) : "f"(x));
    return u;
}

#define MMA_TF32(c0,c1,c2,c3, a0,a1,a2,a3, b0,b1)                         \
    asm volatile(                                                          \
        "mma.sync.aligned.m16n8k8.row.col.f32.tf32.tf32.f32 "             \
        "{%0,%1,%2,%3}, {%4,%5,%6,%7}, {%8,%9}, {%0,%1,%2,%3};"           \
        : "+f"(c0), "+f"(c1), "+f"(c2), "+f"(c3)                           \
        : "r"(a0), "r"(a1), "r"(a2), "r"(a3), "r"(b0), "r"(b1))

// ---------------------------------------------------------------------------
__global__ void k_zero_state() {
    int i = blockIdx.x * blockDim.x + threadIdx.x;
    if (i < BB * HH) g_state[i] = 0.0f;
    if (i == 0) g_epoch[0] = 0;
}

__device__ __forceinline__ void grid_epoch_bar(unsigned target) {
    __syncthreads();
    if (threadIdx.x == 0) {
        __threadfence();
        atomicAdd(&g_epoch[0], 1u);
        while (*((volatile unsigned*)&g_epoch[0]) < target) { }
        __threadfence();
    }
    __syncthreads();
}

// ---------------------------------------------------------------------------
// Persistent GRU via tf32 tensor cores.
// Weights rounded once to tf32 (fixed perturbation); state kept hi/lo (22-bit)
// -> 2 mma chains. Fragment-pair-packed smem: slot(k) = (k>>3)*8+(k&3)*2+((k>>2)&1)
// so every fragment load is an LDS.64 (conflict-free at row stride 520).
// ---------------------------------------------------------------------------
__global__ void __launch_bounds__(256)
k_gru_tc(const float* __restrict__ whh, const float* __restrict__ bhh)
{
    extern __shared__ float smem[];
    float* Wh = smem;                      // [24][520] tf32-rounded, frag-packed
    float* Sp = Wh + NGR * SP3;            // [32][520] fp32 state, frag-packed
    float* Cs = Sp + BH * SP3;             // [24][33]

    const int tid = threadIdx.x;
    const int cta = blockIdx.x;
    const int jg = cta >> 1, bhf = cta & 1;
    const int j0 = jg * JH;
    const int gb0 = bhf * BH;

    // Load + round + pack weight tile once
    for (int i = tid; i < NGR * 512; i += 256) {
        const int g = i >> 9, k = i & 511;
        const int jj = g / 3, gate = g - 3 * (g / 3);
        float w = whh[(size_t)(gate * 512 + j0 + jj) * HH + k];
        const int slot = (k >> 3) * 8 + (k & 3) * 2 + ((k >> 2) & 1);
        Wh[g * SP3 + slot] = __uint_as_float(f2tf(w));
    }

    const int lane = tid & 31, warp = tid >> 5;
    const int qg = lane >> 2, qt = lane & 3;
    const int mi = warp >> 2, ni = warp & 3;
    const int m0 = mi * 8;
    const int n0 = ni * 8;

    // gate-phase coords: 1 (j,b) per thread
    const int jj = tid >> 5;               // 0..7
    const int bl = tid & 31;
    const int gjg = j0 + jj;
    const int gb = gb0 + bl;
    const int hslot = (gjg >> 3) * 8 + (gjg & 3) * 2 + ((gjg >> 2) & 1);

    // biases: constant across steps
    const float bias_r = __ldg(&bhh[gjg]);
    const float bias_z = __ldg(&bhh[512 + gjg]);
    const float bias_n = __ldg(&bhh[1024 + gjg]);

    const float* aP0 = &Wh[(m0 + qg) * SP3 + qt * 2];
    const float* aP1 = &Wh[(m0 + 8 + qg) * SP3 + qt * 2];
    const float* bP  = &Sp[(n0 + qg) * SP3 + qt * 2];

    unsigned target = NCTA;

    for (int t = 0; t < TT; ++t) {
        // Coalesced state gather -> frag-packed smem (4-word scatter per float4)
        for (int i = tid; i < BH * 128; i += 256) {
            const int b = i >> 7, kq = (i & 127) << 2;
            float4 v = __ldcg((const float4*)&g_state[(size_t)(gb0 + b) * HH + kq]);
            float* dst = &Sp[b * SP3 + (kq >> 3) * 8 + ((kq >> 2) & 1)];
            dst[0] = v.x; dst[2] = v.y; dst[4] = v.z; dst[6] = v.w;
        }

        // Prefetch xp gate inputs (DRAM) so latency overlaps the mma phase
        const float xr = __ldg(&g_xp[((size_t)(t * 3 + 0) * 512 + gjg) * 64 + gb]);
        const float xz = __ldg(&g_xp[((size_t)(t * 3 + 1) * 512 + gjg) * 64 + gb]);
        const float xn = __ldg(&g_xp[((size_t)(t * 3 + 2) * 512 + gjg) * 64 + gb]);
        __syncthreads();

        // 2 independent accumulator chains: W_tf32 * (state_hi + state_lo)
        float h0=0.f,h1=0.f,h2=0.f,h3=0.f;     // W * hi
        float g0=0.f,g1=0.f,g2=0.f,g3=0.f;     // W * lo
        #pragma unroll 8
        for (int kt = 0; kt < 64; ++kt) {
            float2 aA = *(const float2*)(aP0 + kt * 8);   // a0 (k=qt), a2 (k=qt+4)
            float2 aB = *(const float2*)(aP1 + kt * 8);   // a1, a3
            float2 bv = *(const float2*)(bP  + kt * 8);   // s(k=qt), s(k=qt+4)
            unsigned bh0 = f2tf(bv.x);
            unsigned bl0 = f2tf(bv.x - __uint_as_float(bh0));
            unsigned bh1 = f2tf(bv.y);
            unsigned bl1 = f2tf(bv.y - __uint_as_float(bh1));
            MMA_TF32(h0, h1, h2, h3,
                     __float_as_uint(aA.x), __float_as_uint(aB.x),
                     __float_as_uint(aA.y), __float_as_uint(aB.y), bh0, bh1);
            MMA_TF32(g0, g1, g2, g3,
                     __float_as_uint(aA.x), __float_as_uint(aB.x),
                     __float_as_uint(aA.y), __float_as_uint(aB.y), bl0, bl1);
        }
        float c0 = h0 + g0;
        float c1 = h1 + g1;
        float c2 = h2 + g2;
        float c3 = h3 + g3;

        // Write C frags to Cs[gate_row][b]; mi=1 keeps only rows 16..23
        if (mi == 0) {
            Cs[qg * 33 + n0 + 2 * qt]         = c0;
            Cs[qg * 33 + n0 + 2 * qt + 1]     = c1;
            Cs[(qg + 8) * 33 + n0 + 2 * qt]   = c2;
            Cs[(qg + 8) * 33 + n0 + 2 * qt+1] = c3;
        } else {
            Cs[(16 + qg) * 33 + n0 + 2 * qt]     = c2;
            Cs[(16 + qg) * 33 + n0 + 2 * qt + 1] = c3;
        }
        __syncthreads();

        // Gate math
        {
            float sr = Cs[(jj * 3 + 0) * 33 + bl] + bias_r;
            float sz = Cs[(jj * 3 + 1) * 33 + bl] + bias_z;
            float sn = Cs[(jj * 3 + 2) * 33 + bl] + bias_n;

            float r  = 1.0f / (1.0f + expf(-(xr + sr)));
            float z  = 1.0f / (1.0f + expf(-(xz + sz)));
            float nn = tanhf(xn + r * sn);

            float hold = Sp[bl * SP3 + hslot];
            float hnew = (1.0f - z) * nn + z * hold;
            g_state[(size_t)gb * HH + gjg] = hnew;
            g_h[((size_t)t * 64 + gb) * HH + gjg] = hnew;
        }

        grid_epoch_bar(target);
        target += NCTA;
    }
}

// ---------------------------------------------------------------------------
// proj0 via tf32 TC: xpT = emb[loc] @ w0[:, :256]^T (+ time*w0[:,256] + b0).
// M = 8192 (loc order n = b*128+t), N = 1536, K = 256.
// ---------------------------------------------------------------------------
__global__ void __launch_bounds__(256)
k_proj0_tc(const int* __restrict__ loc, const float* __restrict__ times,
           const float* __restrict__ emb, const float* __restrict__ w0,
           const float* __restrict__ b0)
{
    __shared__ unsigned As[2][FBM * SROW];
    __shared__ unsigned Bs[2][FBN * SROW];
    __shared__ int locs[FBM];

    const int tid  = threadIdx.x;
    const int lane = tid & 31;
    const int warp = tid >> 5;
    const int wm = warp >> 2, wn = warp & 3;
    const int qg = lane >> 2, qt = lane & 3;

    const int mtile = blockIdx.y * FBM;
    const int ntile = blockIdx.x * FBN;

    if (tid < FBM) locs[tid] = loc[mtile + tid];
    __syncthreads();

    float acc[4][4][4];
    #pragma unroll
    for (int mi = 0; mi < 4; ++mi)
        #pragma unroll
        for (int ni = 0; ni < 4; ++ni)
            #pragma unroll
            for (int q = 0; q < 4; ++q) acc[mi][ni][q] = 0.0f;

    float4 ar[2], br[2];
    const int sm0 = tid >> 2, skq = (tid & 3) * 4;
    const int sm1 = (tid + 256) >> 2;
    const int rowA0 = locs[sm0], rowA1 = locs[sm1];
    const float* bptr0 = w0 + (size_t)(ntile + sm0) * 257;
    const float* bptr1 = w0 + (size_t)(ntile + sm1) * 257;

    {
        ar[0] = *(const float4*)&emb[(size_t)rowA0 * EE + skq];
        ar[1] = *(const float4*)&emb[(size_t)rowA1 * EE + skq];
        br[0].x = bptr0[skq]; br[0].y = bptr0[skq + 1]; br[0].z = bptr0[skq + 2]; br[0].w = bptr0[skq + 3];
        br[1].x = bptr1[skq]; br[1].y = bptr1[skq + 1]; br[1].z = bptr1[skq + 2]; br[1].w = bptr1[skq + 3];
    }
    {
        uint4 v;
        v.x = f2tf(ar[0].x); v.y = f2tf(ar[0].y); v.z = f2tf(ar[0].z); v.w = f2tf(ar[0].w);
        *(uint4*)&As[0][sm0 * SROW + skq] = v;
        v.x = f2tf(ar[1].x); v.y = f2tf(ar[1].y); v.z = f2tf(ar[1].z); v.w = f2tf(ar[1].w);
        *(uint4*)&As[0][sm1 * SROW + skq] = v;
        v.x = f2tf(br[0].x); v.y = f2tf(br[0].y); v.z = f2tf(br[0].z); v.w = f2tf(br[0].w);
        *(uint4*)&Bs[0][sm0 * SROW + skq] = v;
        v.x = f2tf(br[1].x); v.y = f2tf(br[1].y); v.z = f2tf(br[1].z); v.w = f2tf(br[1].w);
        *(uint4*)&Bs[0][sm1 * SROW + skq] = v;
    }
    __syncthreads();

    int buf = 0;
    const int NKT = EE / FBK;   // 16
    for (int kt = 0; kt < NKT; ++kt) {
        if (kt + 1 < NKT) {
            const int kk = (kt + 1) * FBK;
            ar[0] = *(const float4*)&emb[(size_t)rowA0 * EE + kk + skq];
            ar[1] = *(const float4*)&emb[(size_t)rowA1 * EE + kk + skq];
            br[0].x = bptr0[kk + skq]; br[0].y = bptr0[kk + skq + 1];
            br[0].z = bptr0[kk + skq + 2]; br[0].w = bptr0[kk + skq + 3];
            br[1].x = bptr1[kk + skq]; br[1].y = bptr1[kk + skq + 1];
            br[1].z = bptr1[kk + skq + 2]; br[1].w = bptr1[kk + skq + 3];
        }
        #pragma unroll
        for (int ks = 0; ks < FBK; ks += 8) {
            unsigned af[4][4];
            #pragma unroll
            for (int mi = 0; mi < 4; ++mi) {
                const int r = wm * 64 + mi * 16 + qg;
                af[mi][0] = As[buf][r * SROW + ks + qt];
                af[mi][1] = As[buf][(r + 8) * SROW + ks + qt];
                af[mi][2] = As[buf][r * SROW + ks + qt + 4];
                af[mi][3] = As[buf][(r + 8) * SROW + ks + qt + 4];
            }
            unsigned bf[4][2];
            #pragma unroll
            for (int ni = 0; ni < 4; ++ni) {
                const int n = wn * 32 + ni * 8 + qg;
                bf[ni][0] = Bs[buf][n * SROW + ks + qt];
                bf[ni][1] = Bs[buf][n * SROW + ks + qt + 4];
            }
            #pragma unroll
            for (int mi = 0; mi < 4; ++mi)
                #pragma unroll
                for (int ni = 0; ni < 4; ++ni)
                    MMA_TF32(acc[mi][ni][0], acc[mi][ni][1], acc[mi][ni][2], acc[mi][ni][3],
                             af[mi][0], af[mi][1], af[mi][2], af[mi][3],
                             bf[ni][0], bf[ni][1]);
        }
        if (kt + 1 < NKT) {
            const int nb = buf ^ 1;
            uint4 v;
            v.x = f2tf(ar[0].x); v.y = f2tf(ar[0].y); v.z = f2tf(ar[0].z); v.w = f2tf(ar[0].w);
            *(uint4*)&As[nb][sm0 * SROW + skq] = v;
            v.x = f2tf(ar[1].x); v.y = f2tf(ar[1].y); v.z = f2tf(ar[1].z); v.w = f2tf(ar[1].w);
            *(uint4*)&As[nb][sm1 * SROW + skq] = v;
            v.x = f2tf(br[0].x); v.y = f2tf(br[0].y); v.z = f2tf(br[0].z); v.w = f2tf(br[0].w);
            *(uint4*)&Bs[nb][sm0 * SROW + skq] = v;
            v.x = f2tf(br[1].x); v.y = f2tf(br[1].y); v.z = f2tf(br[1].z); v.w = f2tf(br[1].w);
            *(uint4*)&Bs[nb][sm1 * SROW + skq] = v;
        }
        __syncthreads();
        buf ^= 1;
    }

    // Epilogue -> transposed xp, + time * w0[:,256] + b0
    #pragma unroll
    for (int mi = 0; mi < 4; ++mi) {
        #pragma unroll
        for (int rr = 0; rr < 2; ++rr) {
            const int row = mtile + wm * 64 + mi * 16 + qg + rr * 8;   // n = b*128+t
            const int tt = row & 127, b = row >> 7;
            const float tm = __ldg(&times[row]);
            #pragma unroll
            for (int ni = 0; ni < 4; ++ni) {
                #pragma unroll
                for (int cc = 0; cc < 2; ++cc) {
                    const int col = ntile + wn * 32 + ni * 8 + qt * 2 + cc;
                    const int gate = col >> 9, jdim = col & 511;
                    g_xp[((size_t)(tt * 3 + gate) * 512 + jdim) * 64 + b] =
                        acc[mi][ni][rr * 2 + cc]
                        + tm * __ldg(&w0[(size_t)col * 257 + 256]) + __ldg(&b0[col]);
                }
            }
        }
    }
}

// ---------------------------------------------------------------------------
// proj1 via tf32 TC: xpT = g_h @ w1^T + b1.  M=8192, N=1536, K=512.
// ---------------------------------------------------------------------------
__global__ void __launch_bounds__(256)
k_proj1_tc(const float* __restrict__ w1, const float* __restrict__ b1)
{
    __shared__ unsigned As[2][FBM * SROW];
    __shared__ unsigned Bs[2][FBN * SROW];

    const int tid  = threadIdx.x;
    const int lane = tid & 31;
    const int warp = tid >> 5;
    const int wm = warp >> 2, wn = warp & 3;
    const int qg = lane >> 2, qt = lane & 3;

    const int mtile = blockIdx.y * FBM;
    const int ntile = blockIdx.x * FBN;

    float acc[4][4][4];
    #pragma unroll
    for (int mi = 0; mi < 4; ++mi)
        #pragma unroll
        for (int ni = 0; ni < 4; ++ni)
            #pragma unroll
            for (int q = 0; q < 4; ++q) acc[mi][ni][q] = 0.0f;

    float4 ar[2], br[2];
    const int sm0 = tid >> 2, skq = (tid & 3) * 4;
    const int sm1 = (tid + 256) >> 2;

    {
        ar[0] = *(const float4*)&g_h[(size_t)(mtile + sm0) * HH + skq];
        ar[1] = *(const float4*)&g_h[(size_t)(mtile + sm1) * HH + skq];
        br[0] = *(const float4*)&w1[(size_t)(ntile + sm0) * HH + skq];
        br[1] = *(const float4*)&w1[(size_t)(ntile + sm1) * HH + skq];
    }
    {
        uint4 v;
        v.x = f2tf(ar[0].x); v.y = f2tf(ar[0].y); v.z = f2tf(ar[0].z); v.w = f2tf(ar[0].w);
        *(uint4*)&As[0][sm0 * SROW + skq] = v;
        v.x = f2tf(ar[1].x); v.y = f2tf(ar[1].y); v.z = f2tf(ar[1].z); v.w = f2tf(ar[1].w);
        *(uint4*)&As[0][sm1 * SROW + skq] = v;
        v.x = f2tf(br[0].x); v.y = f2tf(br[0].y); v.z = f2tf(br[0].z); v.w = f2tf(br[0].w);
        *(uint4*)&Bs[0][sm0 * SROW + skq] = v;
        v.x = f2tf(br[1].x); v.y = f2tf(br[1].y); v.z = f2tf(br[1].z); v.w = f2tf(br[1].w);
        *(uint4*)&Bs[0][sm1 * SROW + skq] = v;
    }
    __syncthreads();

    int buf = 0;
    for (int kt = 0; kt < HH / FBK; ++kt) {
        if (kt + 1 < HH / FBK) {
            const int kk = (kt + 1) * FBK;
            ar[0] = *(const float4*)&g_h[(size_t)(mtile + sm0) * HH + kk + skq];
            ar[1] = *(const float4*)&g_h[(size_t)(mtile + sm1) * HH + kk + skq];
            br[0] = *(const float4*)&w1[(size_t)(ntile + sm0) * HH + kk + skq];
            br[1] = *(const float4*)&w1[(size_t)(ntile + sm1) * HH + kk + skq];
        }
        #pragma unroll
        for (int ks = 0; ks < FBK; ks += 8) {
            unsigned af[4][4];
            #pragma unroll
            for (int mi = 0; mi < 4; ++mi) {
                const int r = wm * 64 + mi * 16 + qg;
                af[mi][0] = As[buf][r * SROW + ks + qt];
                af[mi][1] = As[buf][(r + 8) * SROW + ks + qt];
                af[mi][2] = As[buf][r * SROW + ks + qt + 4];
                af[mi][3] = As[buf][(r + 8) * SROW + ks + qt + 4];
            }
            unsigned bf[4][2];
            #pragma unroll
            for (int ni = 0; ni < 4; ++ni) {
                const int n = wn * 32 + ni * 8 + qg;
                bf[ni][0] = Bs[buf][n * SROW + ks + qt];
                bf[ni][1] = Bs[buf][n * SROW + ks + qt + 4];
            }
            #pragma unroll
            for (int mi = 0; mi < 4; ++mi)
                #pragma unroll
                for (int ni = 0; ni < 4; ++ni)
                    MMA_TF32(acc[mi][ni][0], acc[mi][ni][1], acc[mi][ni][2], acc[mi][ni][3],
                             af[mi][0], af[mi][1], af[mi][2], af[mi][3],
                             bf[ni][0], bf[ni][1]);
        }
        if (kt + 1 < HH / FBK) {
            const int nb = buf ^ 1;
            uint4 v;
            v.x = f2tf(ar[0].x); v.y = f2tf(ar[0].y); v.z = f2tf(ar[0].z); v.w = f2tf(ar[0].w);
            *(uint4*)&As[nb][sm0 * SROW + skq] = v;
            v.x = f2tf(ar[1].x); v.y = f2tf(ar[1].y); v.z = f2tf(ar[1].z); v.w = f2tf(ar[1].w);
            *(uint4*)&As[nb][sm1 * SROW + skq] = v;
            v.x = f2tf(br[0].x); v.y = f2tf(br[0].y); v.z = f2tf(br[0].z); v.w = f2tf(br[0].w);
            *(uint4*)&Bs[nb][sm0 * SROW + skq] = v;
            v.x = f2tf(br[1].x); v.y = f2tf(br[1].y); v.z = f2tf(br[1].z); v.w = f2tf(br[1].w);
            *(uint4*)&Bs[nb][sm1 * SROW + skq] = v;
        }
        __syncthreads();
        buf ^= 1;
    }

    // Epilogue -> transposed xp
    #pragma unroll
    for (int mi = 0; mi < 4; ++mi) {
        #pragma unroll
        for (int rr = 0; rr < 2; ++rr) {
            const int row = mtile + wm * 64 + mi * 16 + qg + rr * 8;   // m' = t*64+b
            const int tt = row >> 6, b = row & 63;
            #pragma unroll
            for (int ni = 0; ni < 4; ++ni) {
                #pragma unroll
                for (int cc = 0; cc < 2; ++cc) {
                    const int col = ntile + wn * 32 + ni * 8 + qt * 2 + cc;
                    const int gate = col >> 9, jdim = col & 511;
                    g_xp[((size_t)(tt * 3 + gate) * 512 + jdim) * 64 + b] =
                        acc[mi][ni][rr * 2 + cc] + b1[col];
                }
            }
        }
    }
}

// ---------------------------------------------------------------------------
// FC via tf32 TC. A rows are m'=t*64+b; output rows remapped to n=b*128+t.
// ---------------------------------------------------------------------------
__global__ void __launch_bounds__(256)
k_fc_tc(const float* __restrict__ fw, const float* __restrict__ fb,
        float* __restrict__ out)
{
    __shared__ unsigned As[2][FBM * SROW];
    __shared__ unsigned Bs[2][FBN * SROW];

    const int tid  = threadIdx.x;
    const int lane = tid & 31;
    const int warp = tid >> 5;
    const int wm = warp >> 2, wn = warp & 3;
    const int qg = lane >> 2, qt = lane & 3;

    const int mtile = blockIdx.y * FBM;
    const int ntile = blockIdx.x * FBN;

    float acc[4][4][4];
    #pragma unroll
    for (int mi = 0; mi < 4; ++mi)
        #pragma unroll
        for (int ni = 0; ni < 4; ++ni)
            #pragma unroll
            for (int q = 0; q < 4; ++q) acc[mi][ni][q] = 0.0f;

    float4 ar[2], br[2];
    const int sm0 = tid >> 2, skq = (tid & 3) * 4;
    const int sm1 = (tid + 256) >> 2;
    const int brow0 = (ntile + sm0 > VN) ? VN : ntile + sm0;
    const int brow1 = (ntile + sm1 > VN) ? VN : ntile + sm1;

    {
        ar[0] = *(const float4*)&g_h[(size_t)(mtile + sm0) * HH + skq];
        ar[1] = *(const float4*)&g_h[(size_t)(mtile + sm1) * HH + skq];
        br[0] = *(const float4*)&fw[(size_t)brow0 * HH + skq];
        br[1] = *(const float4*)&fw[(size_t)brow1 * HH + skq];
    }
    {
        uint4 v;
        v.x = f2tf(fmaxf(ar[0].x, 0.f)); v.y = f2tf(fmaxf(ar[0].y, 0.f));
        v.z = f2tf(fmaxf(ar[0].z, 0.f)); v.w = f2tf(fmaxf(ar[0].w, 0.f));
        *(uint4*)&As[0][sm0 * SROW + skq] = v;
        v.x = f2tf(fmaxf(ar[1].x, 0.f)); v.y = f2tf(fmaxf(ar[1].y, 0.f));
        v.z = f2tf(fmaxf(ar[1].z, 0.f)); v.w = f2tf(fmaxf(ar[1].w, 0.f));
        *(uint4*)&As[0][sm1 * SROW + skq] = v;
        v.x = f2tf(br[0].x); v.y = f2tf(br[0].y); v.z = f2tf(br[0].z); v.w = f2tf(br[0].w);
        *(uint4*)&Bs[0][sm0 * SROW + skq] = v;
        v.x = f2tf(br[1].x); v.y = f2tf(br[1].y); v.z = f2tf(br[1].z); v.w = f2tf(br[1].w);
        *(uint4*)&Bs[0][sm1 * SROW + skq] = v;
    }
    __syncthreads();

    int buf = 0;
    for (int kt = 0; kt < HH / FBK; ++kt) {
        if (kt + 1 < HH / FBK) {
            const int kk = (kt + 1) * FBK;
            ar[0] = *(const float4*)&g_h[(size_t)(mtile + sm0) * HH + kk + skq];
            ar[1] = *(const float4*)&g_h[(size_t)(mtile + sm1) * HH + kk + skq];
            br[0] = *(const float4*)&fw[(size_t)brow0 * HH + kk + skq];
            br[1] = *(const float4*)&fw[(size_t)brow1 * HH + kk + skq];
        }
        #pragma unroll
        for (int ks = 0; ks < FBK; ks += 8) {
            unsigned af[4][4];
            #pragma unroll
            for (int mi = 0; mi < 4; ++mi) {
                const int r = wm * 64 + mi * 16 + qg;
                af[mi][0] = As[buf][r * SROW + ks + qt];
                af[mi][1] = As[buf][(r + 8) * SROW + ks + qt];
                af[mi][2] = As[buf][r * SROW + ks + qt + 4];
                af[mi][3] = As[buf][(r + 8) * SROW + ks + qt + 4];
            }
            unsigned bf[4][2];
            #pragma unroll
            for (int ni = 0; ni < 4; ++ni) {
                const int n = wn * 32 + ni * 8 + qg;
                bf[ni][0] = Bs[buf][n * SROW + ks + qt];
                bf[ni][1] = Bs[buf][n * SROW + ks + qt + 4];
            }
            #pragma unroll
            for (int mi = 0; mi < 4; ++mi)
                #pragma unroll
                for (int ni = 0; ni < 4; ++ni)
                    MMA_TF32(acc[mi][ni][0], acc[mi][ni][1], acc[mi][ni][2], acc[mi][ni][3],
                             af[mi][0], af[mi][1], af[mi][2], af[mi][3],
                             bf[ni][0], bf[ni][1]);
        }
        if (kt + 1 < HH / FBK) {
            const int nb = buf ^ 1;
            uint4 v;
            v.x = f2tf(fmaxf(ar[0].x, 0.f)); v.y = f2tf(fmaxf(ar[0].y, 0.f));
            v.z = f2tf(fmaxf(ar[0].z, 0.f)); v.w = f2tf(fmaxf(ar[0].w, 0.f));
            *(uint4*)&As[nb][sm0 * SROW + skq] = v;
            v.x = f2tf(fmaxf(ar[1].x, 0.f)); v.y = f2tf(fmaxf(ar[1].y, 0.f));
            v.z = f2tf(fmaxf(ar[1].z, 0.f)); v.w = f2tf(fmaxf(ar[1].w, 0.f));
            *(uint4*)&As[nb][sm1 * SROW + skq] = v;
            v.x = f2tf(br[0].x); v.y = f2tf(br[0].y); v.z = f2tf(br[0].z); v.w = f2tf(br[0].w);
            *(uint4*)&Bs[nb][sm0 * SROW + skq] = v;
            v.x = f2tf(br[1].x); v.y = f2tf(br[1].y); v.z = f2tf(br[1].z); v.w = f2tf(br[1].w);
            *(uint4*)&Bs[nb][sm1 * SROW + skq] = v;
        }
        __syncthreads();
        buf ^= 1;
    }

    #pragma unroll
    for (int mi = 0; mi < 4; ++mi) {
        #pragma unroll
        for (int rr = 0; rr < 2; ++rr) {
            const int row = mtile + wm * 64 + mi * 16 + qg + rr * 8;   // m'
            const int n = (row & 63) * 128 + (row >> 6);               // out row
            #pragma unroll
            for (int ni = 0; ni < 4; ++ni) {
                #pragma unroll
                for (int cc = 0; cc < 2; ++cc) {
                    const int col = ntile + wn * 32 + ni * 8 + qt * 2 + cc;
                    if (col < VN)
                        out[(size_t)n * VN + col] = acc[mi][ni][rr * 2 + cc] + fb[col];
                    else if (col == VN)
                        out[K_LOC_ELEMS + n] = acc[mi][ni][rr * 2 + cc] + fb[col];
                }
            }
        }
    }
}

// ---------------------------------------------------------------------------
// Softmax: per-row log_softmax (row cached in smem, float4 I/O) + time sigmoid.
// ---------------------------------------------------------------------------
__global__ void __launch_bounds__(256)
k_softmax(float* __restrict__ out)
{
    extern __shared__ float row[];       // VN floats
    __shared__ float red[256];

    const int n = blockIdx.x;
    const int tid = threadIdx.x;
    float* base = out + (size_t)n * VN;
    const float4* b4 = (const float4*)base;
    float4* r4 = (float4*)row;
    const int NQ = VN / 4;               // 2500

    float mx = -1e30f;
    for (int i = tid; i < NQ; i += 256) {
        float4 v = b4[i];
        r4[i] = v;
        mx = fmaxf(mx, fmaxf(fmaxf(v.x, v.y), fmaxf(v.z, v.w)));
    }
    red[tid] = mx; __syncthreads();
    for (int s = 128; s > 0; s >>= 1) { if (tid < s) red[tid] = fmaxf(red[tid], red[tid + s]); __syncthreads(); }
    mx = red[0];
    __syncthreads();

    float sum = 0.f;
    for (int i = tid; i < NQ; i += 256) {
        float4 v = r4[i];
        sum += expf(v.x - mx) + expf(v.y - mx) + expf(v.z - mx) + expf(v.w - mx);
    }
    red[tid] = sum; __syncthreads();
    for (int s = 128; s > 0; s >>= 1) { if (tid < s) red[tid] += red[tid + s]; __syncthreads(); }
    float lse = mx + logf(red[0]);

    for (int i = tid; i < NQ; i += 256) {
        float4 v = r4[i];
        v.x -= lse; v.y -= lse; v.z -= lse; v.w -= lse;
        ((float4*)base)[i] = v;
    }

    if (tid == 0) {
        float tl = out[K_LOC_ELEMS + n];
        out[K_LOC_ELEMS + n] = 1.0f / (1.0f + expf(-tl));
    }
}

// ---------------------------------------------------------------------------
// Launch
// ---------------------------------------------------------------------------
extern "C" void kernel_launch(void* const* d_in, const int* in_sizes, int n_in,
                              void* d_out, int out_size)
{
    const int*   loc   = (const int*)  d_in[0];
    const float* times = (const float*)d_in[1];
    const float* emb   = (const float*)d_in[2];
    const float* w_ih0 = (const float*)d_in[3];
    const float* w_hh0 = (const float*)d_in[4];
    const float* b_ih0 = (const float*)d_in[5];
    const float* b_hh0 = (const float*)d_in[6];
    const float* w_ih1 = (const float*)d_in[7];
    const float* w_hh1 = (const float*)d_in[8];
    const float* b_ih1 = (const float*)d_in[9];
    const float* b_hh1 = (const float*)d_in[10];
    const float* fc_w  = (const float*)d_in[11];
    const float* fc_b  = (const float*)d_in[12];
    float* out = (float*)d_out;

    const int gru_smem = (NGR * SP3 + BH * SP3 + NGR * 33) * sizeof(float); // ~120 KB
    static int attr_done = 0;
    if (!attr_done) {
        cudaFuncSetAttribute(k_gru_tc, cudaFuncAttributeMaxDynamicSharedMemorySize, gru_smem);
        attr_done = 1;
    }

    // Layer 0
    k_proj0_tc<<<dim3(G3 / FBN, NR / FBM), 256>>>(loc, times, emb, w_ih0, b_ih0);
    k_zero_state<<<(BB * HH + 255) / 256, 256>>>();
    k_gru_tc<<<NCTA, 256, gru_smem>>>(w_hh0, b_hh0);

    // Layer 1
    k_proj1_tc<<<dim3(G3 / FBN, NR / FBM), 256>>>(w_ih1, b_ih1);
    k_zero_state<<<(BB * HH + 255) / 256, 256>>>();
    k_gru_tc<<<NCTA, 256, gru_smem>>>(w_hh1, b_hh1);

    // FC -> logits straight into d_out (tensor cores, tf32)
    k_fc_tc<<<dim3((VOUT + FBN - 1) / FBN, NR / FBM), 256>>>(fc_w, fc_b, out);

    // log_softmax + time sigmoid
    k_softmax<<<NR, 256, VN * sizeof(float)>>>(out);
}

// round 13
// speedup vs baseline: 2.6146x; 1.0987x over previous
#include <cuda_runtime.h>
#include <math.h>

// Problem constants
#define VN   10000
#define VOUT 10001
#define EE   256
#define HH   512
#define G3   1536
#define BB   64
#define TT   128
#define NR   8192            // BB*TT
#define K_LOC_ELEMS ((size_t)NR * VN)   // 81,920,000 floats of location logits

// Persistent recurrence config: 128 CTAs = 64 j-groups x 2 batch halves
#define NCTA 128
#define NHALF 64             // CTAs per independent batch-half chain
#define JH   8               // hidden dims per CTA
#define NGR  24              // gate rows per CTA (3 per dim)
#define BH   32              // batches per CTA
#define SP3  520             // frag-packed row stride (==8 mod 32: conflict-free)

// Tensor-core GEMM tiling (proj0/proj1 tf32)
#define FBM 128
#define FBN 128
#define FBK 16
#define SROW 20
// FC bf16 tiling
#define SROWB 12             // bf16x2 words per 16-k row (8 data + 4 pad); 12 mod 32 -> conflict-free frags

// Scratch (device globals; no allocations allowed)
// g_xp layout: [t][gate][j][b]  -> ((t*3+gate)*512 + j)*64 + b
__device__ float g_xp[(size_t)NR * G3];
// g_h layout: [m'=t*64+b][j]
__device__ float g_h [(size_t)NR * HH];
__device__ float g_state[BB * HH];          // [b][k]
__device__ __align__(128) unsigned g_epochs[64];   // [0]=half0, [32]=half1 (separate lines)

__device__ __forceinline__ unsigned f2tf(float x) {
    unsigned u;
    asm("cvt.rna.tf32.f32 %0, %1;" : "=r"(u) : "f"(x));
    return u;
}

// pack two f32 -> bf16x2 (lo = first elem, hi = second)
__device__ __forceinline__ unsigned pbf2(float lo, float hi) {
    unsigned r;
    asm("cvt.rn.bf16x2.f32 %0, %1, %2;" : "=r"(r) : "f"(hi), "f"(lo));
    return r;
}

#define MMA_TF32(c0,c1,c2,c3, a0,a1,a2,a3, b0,b1)                         \
    asm volatile(                                                          \
        "mma.sync.aligned.m16n8k8.row.col.f32.tf32.tf32.f32 "             \
        "{%0,%1,%2,%3}, {%4,%5,%6,%7}, {%8,%9}, {%0,%1,%2,%3};"           \
        : "+f"(c0), "+f"(c1), "+f"(c2), "+f"(c3)                           \
        : "r"(a0), "r"(a1), "r"(a2), "r"(a3), "r"(b0), "r"(b1))

#define MMA_BF16(c0,c1,c2,c3, a0,a1,a2,a3, b0,b1)                         \
    asm volatile(                                                          \
        "mma.sync.aligned.m16n8k16.row.col.f32.bf16.bf16.f32 "            \
        "{%0,%1,%2,%3}, {%4,%5,%6,%7}, {%8,%9}, {%0,%1,%2,%3};"           \
        : "+f"(c0), "+f"(c1), "+f"(c2), "+f"(c3)                           \
        : "r"(a0), "r"(a1), "r"(a2), "r"(a3), "r"(b0), "r"(b1))

// ---------------------------------------------------------------------------
__global__ void k_zero_state() {
    int i = blockIdx.x * blockDim.x + threadIdx.x;
    if (i < BB * HH) g_state[i] = 0.0f;
    if (i == 0) { g_epochs[0] = 0; g_epochs[32] = 0; }
}

// Half-grid barrier: release-arrive + acquire-poll (no MEMBAR.ALL.GPU).
// bar.sync before arrival makes all CTA threads' writes ordered-before the
// release; acquire on the poll pairs with it (standard grid.sync pattern).
__device__ __forceinline__ void half_bar(unsigned* ctr, unsigned target) {
    __syncthreads();
    if (threadIdx.x == 0) {
        asm volatile("red.release.gpu.add.u32 [%0], 1;" :: "l"(ctr) : "memory");
        unsigned v;
        do {
            asm volatile("ld.acquire.gpu.u32 %0, [%1];" : "=r"(v) : "l"(ctr) : "memory");
        } while (v < target);
    }
    __syncthreads();
}

// ---------------------------------------------------------------------------
// Persistent GRU via tf32 tensor cores.
// Weights rounded once to tf32 (fixed perturbation); state kept hi/lo (22-bit)
// -> 2 mma chains. Fragment-pair-packed smem: slot(k) = (k>>3)*8+(k&3)*2+((k>>2)&1)
// so every fragment load is an LDS.64 (conflict-free at row stride 520).
// Two independent batch-half chains, each with its own 64-CTA barrier.
// ---------------------------------------------------------------------------
__global__ void __launch_bounds__(256)
k_gru_tc(const float* __restrict__ whh, const float* __restrict__ bhh)
{
    extern __shared__ float smem[];
    float* Wh = smem;                      // [24][520] tf32-rounded, frag-packed
    float* Sp = Wh + NGR * SP3;            // [32][520] fp32 state, frag-packed
    float* Cs = Sp + BH * SP3;             // [24][33]

    const int tid = threadIdx.x;
    const int cta = blockIdx.x;
    const int jg = cta >> 1, bhf = cta & 1;
    const int j0 = jg * JH;
    const int gb0 = bhf * BH;
    unsigned* ctr = &g_epochs[bhf * 32];

    // Load + round + pack weight tile once
    for (int i = tid; i < NGR * 512; i += 256) {
        const int g = i >> 9, k = i & 511;
        const int jj = g / 3, gate = g - 3 * (g / 3);
        float w = whh[(size_t)(gate * 512 + j0 + jj) * HH + k];
        const int slot = (k >> 3) * 8 + (k & 3) * 2 + ((k >> 2) & 1);
        Wh[g * SP3 + slot] = __uint_as_float(f2tf(w));
    }

    const int lane = tid & 31, warp = tid >> 5;
    const int qg = lane >> 2, qt = lane & 3;
    const int mi = warp >> 2, ni = warp & 3;
    const int m0 = mi * 8;
    const int n0 = ni * 8;

    // gate-phase coords: 1 (j,b) per thread
    const int jj = tid >> 5;               // 0..7
    const int bl = tid & 31;
    const int gjg = j0 + jj;
    const int gb = gb0 + bl;
    const int hslot = (gjg >> 3) * 8 + (gjg & 3) * 2 + ((gjg >> 2) & 1);

    // biases: constant across steps
    const float bias_r = __ldg(&bhh[gjg]);
    const float bias_z = __ldg(&bhh[512 + gjg]);
    const float bias_n = __ldg(&bhh[1024 + gjg]);

    const float* aP0 = &Wh[(m0 + qg) * SP3 + qt * 2];
    const float* aP1 = &Wh[(m0 + 8 + qg) * SP3 + qt * 2];
    const float* bP  = &Sp[(n0 + qg) * SP3 + qt * 2];

    unsigned target = NHALF;

    for (int t = 0; t < TT; ++t) {
        // Coalesced state gather -> frag-packed smem (4-word scatter per float4)
        for (int i = tid; i < BH * 128; i += 256) {
            const int b = i >> 7, kq = (i & 127) << 2;
            float4 v = __ldcg((const float4*)&g_state[(size_t)(gb0 + b) * HH + kq]);
            float* dst = &Sp[b * SP3 + (kq >> 3) * 8 + ((kq >> 2) & 1)];
            dst[0] = v.x; dst[2] = v.y; dst[4] = v.z; dst[6] = v.w;
        }

        // Prefetch xp gate inputs (DRAM) so latency overlaps the mma phase
        const float xr = __ldg(&g_xp[((size_t)(t * 3 + 0) * 512 + gjg) * 64 + gb]);
        const float xz = __ldg(&g_xp[((size_t)(t * 3 + 1) * 512 + gjg) * 64 + gb]);
        const float xn = __ldg(&g_xp[((size_t)(t * 3 + 2) * 512 + gjg) * 64 + gb]);
        __syncthreads();

        // 2 independent accumulator chains: W_tf32 * (state_hi + state_lo)
        float h0=0.f,h1=0.f,h2=0.f,h3=0.f;     // W * hi
        float g0=0.f,g1=0.f,g2=0.f,g3=0.f;     // W * lo
        #pragma unroll 8
        for (int kt = 0; kt < 64; ++kt) {
            float2 aA = *(const float2*)(aP0 + kt * 8);   // a0 (k=qt), a2 (k=qt+4)
            float2 aB = *(const float2*)(aP1 + kt * 8);   // a1, a3
            float2 bv = *(const float2*)(bP  + kt * 8);   // s(k=qt), s(k=qt+4)
            unsigned bh0 = f2tf(bv.x);
            unsigned bl0 = f2tf(bv.x - __uint_as_float(bh0));
            unsigned bh1 = f2tf(bv.y);
            unsigned bl1 = f2tf(bv.y - __uint_as_float(bh1));
            MMA_TF32(h0, h1, h2, h3,
                     __float_as_uint(aA.x), __float_as_uint(aB.x),
                     __float_as_uint(aA.y), __float_as_uint(aB.y), bh0, bh1);
            MMA_TF32(g0, g1, g2, g3,
                     __float_as_uint(aA.x), __float_as_uint(aB.x),
                     __float_as_uint(aA.y), __float_as_uint(aB.y), bl0, bl1);
        }
        float c0 = h0 + g0;
        float c1 = h1 + g1;
        float c2 = h2 + g2;
        float c3 = h3 + g3;

        // Write C frags to Cs[gate_row][b]; mi=1 keeps only rows 16..23
        if (mi == 0) {
            Cs[qg * 33 + n0 + 2 * qt]         = c0;
            Cs[qg * 33 + n0 + 2 * qt + 1]     = c1;
            Cs[(qg + 8) * 33 + n0 + 2 * qt]   = c2;
            Cs[(qg + 8) * 33 + n0 + 2 * qt+1] = c3;
        } else {
            Cs[(16 + qg) * 33 + n0 + 2 * qt]     = c2;
            Cs[(16 + qg) * 33 + n0 + 2 * qt + 1] = c3;
        }
        __syncthreads();

        // Gate math
        {
            float sr = Cs[(jj * 3 + 0) * 33 + bl] + bias_r;
            float sz = Cs[(jj * 3 + 1) * 33 + bl] + bias_z;
            float sn = Cs[(jj * 3 + 2) * 33 + bl] + bias_n;

            float r  = 1.0f / (1.0f + expf(-(xr + sr)));
            float z  = 1.0f / (1.0f + expf(-(xz + sz)));
            float nn = tanhf(xn + r * sn);

            float hold = Sp[bl * SP3 + hslot];
            float hnew = (1.0f - z) * nn + z * hold;
            g_state[(size_t)gb * HH + gjg] = hnew;
            g_h[((size_t)t * 64 + gb) * HH + gjg] = hnew;
        }

        half_bar(ctr, target);
        target += NHALF;
    }
}

// ---------------------------------------------------------------------------
// proj0 via tf32 TC: xpT = emb[loc] @ w0[:, :256]^T (+ time*w0[:,256] + b0).
// M = 8192 (loc order n = b*128+t), N = 1536, K = 256.
// ---------------------------------------------------------------------------
__global__ void __launch_bounds__(256)
k_proj0_tc(const int* __restrict__ loc, const float* __restrict__ times,
           const float* __restrict__ emb, const float* __restrict__ w0,
           const float* __restrict__ b0)
{
    __shared__ unsigned As[2][FBM * SROW];
    __shared__ unsigned Bs[2][FBN * SROW];
    __shared__ int locs[FBM];

    const int tid  = threadIdx.x;
    const int lane = tid & 31;
    const int warp = tid >> 5;
    const int wm = warp >> 2, wn = warp & 3;
    const int qg = lane >> 2, qt = lane & 3;

    const int mtile = blockIdx.y * FBM;
    const int ntile = blockIdx.x * FBN;

    if (tid < FBM) locs[tid] = loc[mtile + tid];
    __syncthreads();

    float acc[4][4][4];
    #pragma unroll
    for (int mi = 0; mi < 4; ++mi)
        #pragma unroll
        for (int ni = 0; ni < 4; ++ni)
            #pragma unroll
            for (int q = 0; q < 4; ++q) acc[mi][ni][q] = 0.0f;

    float4 ar[2], br[2];
    const int sm0 = tid >> 2, skq = (tid & 3) * 4;
    const int sm1 = (tid + 256) >> 2;
    const int rowA0 = locs[sm0], rowA1 = locs[sm1];
    const float* bptr0 = w0 + (size_t)(ntile + sm0) * 257;
    const float* bptr1 = w0 + (size_t)(ntile + sm1) * 257;

    {
        ar[0] = *(const float4*)&emb[(size_t)rowA0 * EE + skq];
        ar[1] = *(const float4*)&emb[(size_t)rowA1 * EE + skq];
        br[0].x = bptr0[skq]; br[0].y = bptr0[skq + 1]; br[0].z = bptr0[skq + 2]; br[0].w = bptr0[skq + 3];
        br[1].x = bptr1[skq]; br[1].y = bptr1[skq + 1]; br[1].z = bptr1[skq + 2]; br[1].w = bptr1[skq + 3];
    }
    {
        uint4 v;
        v.x = f2tf(ar[0].x); v.y = f2tf(ar[0].y); v.z = f2tf(ar[0].z); v.w = f2tf(ar[0].w);
        *(uint4*)&As[0][sm0 * SROW + skq] = v;
        v.x = f2tf(ar[1].x); v.y = f2tf(ar[1].y); v.z = f2tf(ar[1].z); v.w = f2tf(ar[1].w);
        *(uint4*)&As[0][sm1 * SROW + skq] = v;
        v.x = f2tf(br[0].x); v.y = f2tf(br[0].y); v.z = f2tf(br[0].z); v.w = f2tf(br[0].w);
        *(uint4*)&Bs[0][sm0 * SROW + skq] = v;
        v.x = f2tf(br[1].x); v.y = f2tf(br[1].y); v.z = f2tf(br[1].z); v.w = f2tf(br[1].w);
        *(uint4*)&Bs[0][sm1 * SROW + skq] = v;
    }
    __syncthreads();

    int buf = 0;
    const int NKT = EE / FBK;   // 16
    for (int kt = 0; kt < NKT; ++kt) {
        if (kt + 1 < NKT) {
            const int kk = (kt + 1) * FBK;
            ar[0] = *(const float4*)&emb[(size_t)rowA0 * EE + kk + skq];
            ar[1] = *(const float4*)&emb[(size_t)rowA1 * EE + kk + skq];
            br[0].x = bptr0[kk + skq]; br[0].y = bptr0[kk + skq + 1];
            br[0].z = bptr0[kk + skq + 2]; br[0].w = bptr0[kk + skq + 3];
            br[1].x = bptr1[kk + skq]; br[1].y = bptr1[kk + skq + 1];
            br[1].z = bptr1[kk + skq + 2]; br[1].w = bptr1[kk + skq + 3];
        }
        #pragma unroll
        for (int ks = 0; ks < FBK; ks += 8) {
            unsigned af[4][4];
            #pragma unroll
            for (int mi = 0; mi < 4; ++mi) {
                const int r = wm * 64 + mi * 16 + qg;
                af[mi][0] = As[buf][r * SROW + ks + qt];
                af[mi][1] = As[buf][(r + 8) * SROW + ks + qt];
                af[mi][2] = As[buf][r * SROW + ks + qt + 4];
                af[mi][3] = As[buf][(r + 8) * SROW + ks + qt + 4];
            }
            unsigned bf[4][2];
            #pragma unroll
            for (int ni = 0; ni < 4; ++ni) {
                const int n = wn * 32 + ni * 8 + qg;
                bf[ni][0] = Bs[buf][n * SROW + ks + qt];
                bf[ni][1] = Bs[buf][n * SROW + ks + qt + 4];
            }
            #pragma unroll
            for (int mi = 0; mi < 4; ++mi)
                #pragma unroll
                for (int ni = 0; ni < 4; ++ni)
                    MMA_TF32(acc[mi][ni][0], acc[mi][ni][1], acc[mi][ni][2], acc[mi][ni][3],
                             af[mi][0], af[mi][1], af[mi][2], af[mi][3],
                             bf[ni][0], bf[ni][1]);
        }
        if (kt + 1 < NKT) {
            const int nb = buf ^ 1;
            uint4 v;
            v.x = f2tf(ar[0].x); v.y = f2tf(ar[0].y); v.z = f2tf(ar[0].z); v.w = f2tf(ar[0].w);
            *(uint4*)&As[nb][sm0 * SROW + skq] = v;
            v.x = f2tf(ar[1].x); v.y = f2tf(ar[1].y); v.z = f2tf(ar[1].z); v.w = f2tf(ar[1].w);
            *(uint4*)&As[nb][sm1 * SROW + skq] = v;
            v.x = f2tf(br[0].x); v.y = f2tf(br[0].y); v.z = f2tf(br[0].z); v.w = f2tf(br[0].w);
            *(uint4*)&Bs[nb][sm0 * SROW + skq] = v;
            v.x = f2tf(br[1].x); v.y = f2tf(br[1].y); v.z = f2tf(br[1].z); v.w = f2tf(br[1].w);
            *(uint4*)&Bs[nb][sm1 * SROW + skq] = v;
        }
        __syncthreads();
        buf ^= 1;
    }

    // Epilogue -> transposed xp, + time * w0[:,256] + b0
    #pragma unroll
    for (int mi = 0; mi < 4; ++mi) {
        #pragma unroll
        for (int rr = 0; rr < 2; ++rr) {
            const int row = mtile + wm * 64 + mi * 16 + qg + rr * 8;   // n = b*128+t
            const int tt = row & 127, b = row >> 7;
            const float tm = __ldg(&times[row]);
            #pragma unroll
            for (int ni = 0; ni < 4; ++ni) {
                #pragma unroll
                for (int cc = 0; cc < 2; ++cc) {
                    const int col = ntile + wn * 32 + ni * 8 + qt * 2 + cc;
                    const int gate = col >> 9, jdim = col & 511;
                    g_xp[((size_t)(tt * 3 + gate) * 512 + jdim) * 64 + b] =
                        acc[mi][ni][rr * 2 + cc]
                        + tm * __ldg(&w0[(size_t)col * 257 + 256]) + __ldg(&b0[col]);
                }
            }
        }
    }
}

// ---------------------------------------------------------------------------
// proj1 via tf32 TC: xpT = g_h @ w1^T + b1.  M=8192, N=1536, K=512.
// ---------------------------------------------------------------------------
__global__ void __launch_bounds__(256)
k_proj1_tc(const float* __restrict__ w1, const float* __restrict__ b1)
{
    __shared__ unsigned As[2][FBM * SROW];
    __shared__ unsigned Bs[2][FBN * SROW];

    const int tid  = threadIdx.x;
    const int lane = tid & 31;
    const int warp = tid >> 5;
    const int wm = warp >> 2, wn = warp & 3;
    const int qg = lane >> 2, qt = lane & 3;

    const int mtile = blockIdx.y * FBM;
    const int ntile = blockIdx.x * FBN;

    float acc[4][4][4];
    #pragma unroll
    for (int mi = 0; mi < 4; ++mi)
        #pragma unroll
        for (int ni = 0; ni < 4; ++ni)
            #pragma unroll
            for (int q = 0; q < 4; ++q) acc[mi][ni][q] = 0.0f;

    float4 ar[2], br[2];
    const int sm0 = tid >> 2, skq = (tid & 3) * 4;
    const int sm1 = (tid + 256) >> 2;

    {
        ar[0] = *(const float4*)&g_h[(size_t)(mtile + sm0) * HH + skq];
        ar[1] = *(const float4*)&g_h[(size_t)(mtile + sm1) * HH + skq];
        br[0] = *(const float4*)&w1[(size_t)(ntile + sm0) * HH + skq];
        br[1] = *(const float4*)&w1[(size_t)(ntile + sm1) * HH + skq];
    }
    {
        uint4 v;
        v.x = f2tf(ar[0].x); v.y = f2tf(ar[0].y); v.z = f2tf(ar[0].z); v.w = f2tf(ar[0].w);
        *(uint4*)&As[0][sm0 * SROW + skq] = v;
        v.x = f2tf(ar[1].x); v.y = f2tf(ar[1].y); v.z = f2tf(ar[1].z); v.w = f2tf(ar[1].w);
        *(uint4*)&As[0][sm1 * SROW + skq] = v;
        v.x = f2tf(br[0].x); v.y = f2tf(br[0].y); v.z = f2tf(br[0].z); v.w = f2tf(br[0].w);
        *(uint4*)&Bs[0][sm0 * SROW + skq] = v;
        v.x = f2tf(br[1].x); v.y = f2tf(br[1].y); v.z = f2tf(br[1].z); v.w = f2tf(br[1].w);
        *(uint4*)&Bs[0][sm1 * SROW + skq] = v;
    }
    __syncthreads();

    int buf = 0;
    for (int kt = 0; kt < HH / FBK; ++kt) {
        if (kt + 1 < HH / FBK) {
            const int kk = (kt + 1) * FBK;
            ar[0] = *(const float4*)&g_h[(size_t)(mtile + sm0) * HH + kk + skq];
            ar[1] = *(const float4*)&g_h[(size_t)(mtile + sm1) * HH + kk + skq];
            br[0] = *(const float4*)&w1[(size_t)(ntile + sm0) * HH + kk + skq];
            br[1] = *(const float4*)&w1[(size_t)(ntile + sm1) * HH + kk + skq];
        }
        #pragma unroll
        for (int ks = 0; ks < FBK; ks += 8) {
            unsigned af[4][4];
            #pragma unroll
            for (int mi = 0; mi < 4; ++mi) {
                const int r = wm * 64 + mi * 16 + qg;
                af[mi][0] = As[buf][r * SROW + ks + qt];
                af[mi][1] = As[buf][(r + 8) * SROW + ks + qt];
                af[mi][2] = As[buf][r * SROW + ks + qt + 4];
                af[mi][3] = As[buf][(r + 8) * SROW + ks + qt + 4];
            }
            unsigned bf[4][2];
            #pragma unroll
            for (int ni = 0; ni < 4; ++ni) {
                const int n = wn * 32 + ni * 8 + qg;
                bf[ni][0] = Bs[buf][n * SROW + ks + qt];
                bf[ni][1] = Bs[buf][n * SROW + ks + qt + 4];
            }
            #pragma unroll
            for (int mi = 0; mi < 4; ++mi)
                #pragma unroll
                for (int ni = 0; ni < 4; ++ni)
                    MMA_TF32(acc[mi][ni][0], acc[mi][ni][1], acc[mi][ni][2], acc[mi][ni][3],
                             af[mi][0], af[mi][1], af[mi][2], af[mi][3],
                             bf[ni][0], bf[ni][1]);
        }
        if (kt + 1 < HH / FBK) {
            const int nb = buf ^ 1;
            uint4 v;
            v.x = f2tf(ar[0].x); v.y = f2tf(ar[0].y); v.z = f2tf(ar[0].z); v.w = f2tf(ar[0].w);
            *(uint4*)&As[nb][sm0 * SROW + skq] = v;
            v.x = f2tf(ar[1].x); v.y = f2tf(ar[1].y); v.z = f2tf(ar[1].z); v.w = f2tf(ar[1].w);
            *(uint4*)&As[nb][sm1 * SROW + skq] = v;
            v.x = f2tf(br[0].x); v.y = f2tf(br[0].y); v.z = f2tf(br[0].z); v.w = f2tf(br[0].w);
            *(uint4*)&Bs[nb][sm0 * SROW + skq] = v;
            v.x = f2tf(br[1].x); v.y = f2tf(br[1].y); v.z = f2tf(br[1].z); v.w = f2tf(br[1].w);
            *(uint4*)&Bs[nb][sm1 * SROW + skq] = v;
        }
        __syncthreads();
        buf ^= 1;
    }

    // Epilogue -> transposed xp
    #pragma unroll
    for (int mi = 0; mi < 4; ++mi) {
        #pragma unroll
        for (int rr = 0; rr < 2; ++rr) {
            const int row = mtile + wm * 64 + mi * 16 + qg + rr * 8;   // m' = t*64+b
            const int tt = row >> 6, b = row & 63;
            #pragma unroll
            for (int ni = 0; ni < 4; ++ni) {
                #pragma unroll
                for (int cc = 0; cc < 2; ++cc) {
                    const int col = ntile + wn * 32 + ni * 8 + qt * 2 + cc;
                    const int gate = col >> 9, jdim = col & 511;
                    g_xp[((size_t)(tt * 3 + gate) * 512 + jdim) * 64 + b] =
                        acc[mi][ni][rr * 2 + cc] + b1[col];
                }
            }
        }
    }
}

// ---------------------------------------------------------------------------
// FC via bf16 TC (m16n8k16). A rows are m'=t*64+b; output rows n=b*128+t.
// smem rows: 16 k-values = 8 bf16x2 words, stride SROWB=12 (conflict-free).
// ---------------------------------------------------------------------------
__global__ void __launch_bounds__(256)
k_fc_tc(const float* __restrict__ fw, const float* __restrict__ fb,
        float* __restrict__ out)
{
    __shared__ unsigned As[2][FBM * SROWB];
    __shared__ unsigned Bs[2][FBN * SROWB];

    const int tid  = threadIdx.x;
    const int lane = tid & 31;
    const int warp = tid >> 5;
    const int wm = warp >> 2, wn = warp & 3;
    const int qg = lane >> 2, qt = lane & 3;

    const int mtile = blockIdx.y * FBM;
    const int ntile = blockIdx.x * FBN;

    float acc[4][4][4];
    #pragma unroll
    for (int mi = 0; mi < 4; ++mi)
        #pragma unroll
        for (int ni = 0; ni < 4; ++ni)
            #pragma unroll
            for (int q = 0; q < 4; ++q) acc[mi][ni][q] = 0.0f;

    float4 ar[2], br[2];
    const int sm0 = tid >> 2, skq = (tid & 3) * 4;   // f32 column within 16
    const int sw  = (tid & 3) * 2;                   // bf16x2 word offset
    const int sm1 = (tid + 256) >> 2;
    const int brow0 = (ntile + sm0 > VN) ? VN : ntile + sm0;
    const int brow1 = (ntile + sm1 > VN) ? VN : ntile + sm1;

    {
        ar[0] = *(const float4*)&g_h[(size_t)(mtile + sm0) * HH + skq];
        ar[1] = *(const float4*)&g_h[(size_t)(mtile + sm1) * HH + skq];
        br[0] = *(const float4*)&fw[(size_t)brow0 * HH + skq];
        br[1] = *(const float4*)&fw[(size_t)brow1 * HH + skq];
    }
    {
        uint2 u;
        u.x = pbf2(fmaxf(ar[0].x, 0.f), fmaxf(ar[0].y, 0.f));
        u.y = pbf2(fmaxf(ar[0].z, 0.f), fmaxf(ar[0].w, 0.f));
        *(uint2*)&As[0][sm0 * SROWB + sw] = u;
        u.x = pbf2(fmaxf(ar[1].x, 0.f), fmaxf(ar[1].y, 0.f));
        u.y = pbf2(fmaxf(ar[1].z, 0.f), fmaxf(ar[1].w, 0.f));
        *(uint2*)&As[0][sm1 * SROWB + sw] = u;
        u.x = pbf2(br[0].x, br[0].y); u.y = pbf2(br[0].z, br[0].w);
        *(uint2*)&Bs[0][sm0 * SROWB + sw] = u;
        u.x = pbf2(br[1].x, br[1].y); u.y = pbf2(br[1].z, br[1].w);
        *(uint2*)&Bs[0][sm1 * SROWB + sw] = u;
    }
    __syncthreads();

    int buf = 0;
    for (int kt = 0; kt < HH / 16; ++kt) {
        if (kt + 1 < HH / 16) {
            const int kk = (kt + 1) * 16;
            ar[0] = *(const float4*)&g_h[(size_t)(mtile + sm0) * HH + kk + skq];
            ar[1] = *(const float4*)&g_h[(size_t)(mtile + sm1) * HH + kk + skq];
            br[0] = *(const float4*)&fw[(size_t)brow0 * HH + kk + skq];
            br[1] = *(const float4*)&fw[(size_t)brow1 * HH + kk + skq];
        }

        // one m16n8k16 per (mi, ni) per kt
        {
            unsigned af[4][4];
            #pragma unroll
            for (int mi = 0; mi < 4; ++mi) {
                const int r = wm * 64 + mi * 16 + qg;
                af[mi][0] = As[buf][r * SROWB + qt];
                af[mi][1] = As[buf][(r + 8) * SROWB + qt];
                af[mi][2] = As[buf][r * SROWB + qt + 4];
                af[mi][3] = As[buf][(r + 8) * SROWB + qt + 4];
            }
            unsigned bfr[4][2];
            #pragma unroll
            for (int ni = 0; ni < 4; ++ni) {
                const int n = wn * 32 + ni * 8 + qg;
                bfr[ni][0] = Bs[buf][n * SROWB + qt];
                bfr[ni][1] = Bs[buf][n * SROWB + qt + 4];
            }
            #pragma unroll
            for (int mi = 0; mi < 4; ++mi)
                #pragma unroll
                for (int ni = 0; ni < 4; ++ni)
                    MMA_BF16(acc[mi][ni][0], acc[mi][ni][1], acc[mi][ni][2], acc[mi][ni][3],
                             af[mi][0], af[mi][1], af[mi][2], af[mi][3],
                             bfr[ni][0], bfr[ni][1]);
        }

        if (kt + 1 < HH / 16) {
            const int nb = buf ^ 1;
            uint2 u;
            u.x = pbf2(fmaxf(ar[0].x, 0.f), fmaxf(ar[0].y, 0.f));
            u.y = pbf2(fmaxf(ar[0].z, 0.f), fmaxf(ar[0].w, 0.f));
            *(uint2*)&As[nb][sm0 * SROWB + sw] = u;
            u.x = pbf2(fmaxf(ar[1].x, 0.f), fmaxf(ar[1].y, 0.f));
            u.y = pbf2(fmaxf(ar[1].z, 0.f), fmaxf(ar[1].w, 0.f));
            *(uint2*)&As[nb][sm1 * SROWB + sw] = u;
            u.x = pbf2(br[0].x, br[0].y); u.y = pbf2(br[0].z, br[0].w);
            *(uint2*)&Bs[nb][sm0 * SROWB + sw] = u;
            u.x = pbf2(br[1].x, br[1].y); u.y = pbf2(br[1].z, br[1].w);
            *(uint2*)&Bs[nb][sm1 * SROWB + sw] = u;
        }
        __syncthreads();
        buf ^= 1;
    }

    #pragma unroll
    for (int mi = 0; mi < 4; ++mi) {
        #pragma unroll
        for (int rr = 0; rr < 2; ++rr) {
            const int row = mtile + wm * 64 + mi * 16 + qg + rr * 8;   // m'
            const int n = (row & 63) * 128 + (row >> 6);               // out row
            #pragma unroll
            for (int ni = 0; ni < 4; ++ni) {
                #pragma unroll
                for (int cc = 0; cc < 2; ++cc) {
                    const int col = ntile + wn * 32 + ni * 8 + qt * 2 + cc;
                    if (col < VN)
                        out[(size_t)n * VN + col] = acc[mi][ni][rr * 2 + cc] + fb[col];
                    else if (col == VN)
                        out[K_LOC_ELEMS + n] = acc[mi][ni][rr * 2 + cc] + fb[col];
                }
            }
        }
    }
}

// ---------------------------------------------------------------------------
// Softmax: per-row log_softmax (row cached in smem, float4 I/O) + time sigmoid.
// ---------------------------------------------------------------------------
__global__ void __launch_bounds__(256)
k_softmax(float* __restrict__ out)
{
    extern __shared__ float row[];       // VN floats
    __shared__ float red[256];

    const int n = blockIdx.x;
    const int tid = threadIdx.x;
    float* base = out + (size_t)n * VN;
    const float4* b4 = (const float4*)base;
    float4* r4 = (float4*)row;
    const int NQ = VN / 4;               // 2500

    float mx = -1e30f;
    for (int i = tid; i < NQ; i += 256) {
        float4 v = b4[i];
        r4[i] = v;
        mx = fmaxf(mx, fmaxf(fmaxf(v.x, v.y), fmaxf(v.z, v.w)));
    }
    red[tid] = mx; __syncthreads();
    for (int s = 128; s > 0; s >>= 1) { if (tid < s) red[tid] = fmaxf(red[tid], red[tid + s]); __syncthreads(); }
    mx = red[0];
    __syncthreads();

    float sum = 0.f;
    for (int i = tid; i < NQ; i += 256) {
        float4 v = r4[i];
        sum += expf(v.x - mx) + expf(v.y - mx) + expf(v.z - mx) + expf(v.w - mx);
    }
    red[tid] = sum; __syncthreads();
    for (int s = 128; s > 0; s >>= 1) { if (tid < s) red[tid] += red[tid + s]; __syncthreads(); }
    float lse = mx + logf(red[0]);

    for (int i = tid; i < NQ; i += 256) {
        float4 v = r4[i];
        v.x -= lse; v.y -= lse; v.z -= lse; v.w -= lse;
        ((float4*)base)[i] = v;
    }

    if (tid == 0) {
        float tl = out[K_LOC_ELEMS + n];
        out[K_LOC_ELEMS + n] = 1.0f / (1.0f + expf(-tl));
    }
}

// ---------------------------------------------------------------------------
// Launch
// ---------------------------------------------------------------------------
extern "C" void kernel_launch(void* const* d_in, const int* in_sizes, int n_in,
                              void* d_out, int out_size)
{
    const int*   loc   = (const int*)  d_in[0];
    const float* times = (const float*)d_in[1];
    const float* emb   = (const float*)d_in[2];
    const float* w_ih0 = (const float*)d_in[3];
    const float* w_hh0 = (const float*)d_in[4];
    const float* b_ih0 = (const float*)d_in[5];
    const float* b_hh0 = (const float*)d_in[6];
    const float* w_ih1 = (const float*)d_in[7];
    const float* w_hh1 = (const float*)d_in[8];
    const float* b_ih1 = (const float*)d_in[9];
    const float* b_hh1 = (const float*)d_in[10];
    const float* fc_w  = (const float*)d_in[11];
    const float* fc_b  = (const float*)d_in[12];
    float* out = (float*)d_out;

    const int gru_smem = (NGR * SP3 + BH * SP3 + NGR * 33) * sizeof(float); // ~120 KB
    static int attr_done = 0;
    if (!attr_done) {
        cudaFuncSetAttribute(k_gru_tc, cudaFuncAttributeMaxDynamicSharedMemorySize, gru_smem);
        attr_done = 1;
    }

    // Layer 0
    k_proj0_tc<<<dim3(G3 / FBN, NR / FBM), 256>>>(loc, times, emb, w_ih0, b_ih0);
    k_zero_state<<<(BB * HH + 255) / 256, 256>>>();
    k_gru_tc<<<NCTA, 256, gru_smem>>>(w_hh0, b_hh0);

    // Layer 1
    k_proj1_tc<<<dim3(G3 / FBN, NR / FBM), 256>>>(w_ih1, b_ih1);
    k_zero_state<<<(BB * HH + 255) / 256, 256>>>();
    k_gru_tc<<<NCTA, 256, gru_smem>>>(w_hh1, b_hh1);

    // FC -> logits straight into d_out (tensor cores, bf16)
    k_fc_tc<<<dim3((VOUT + FBN - 1) / FBN, NR / FBM), 256>>>(fc_w, fc_b, out);

    // log_softmax + time sigmoid
    k_softmax<<<NR, 256, VN * sizeof(float)>>>(out);
}

// round 14
// speedup vs baseline: 2.8346x; 1.0841x over previous
#include <cuda_runtime.h>
#include <cuda_bf16.h>
#include <math.h>

// Problem constants
#define VN   10000
#define VOUT 10001
#define EE   256
#define HH   512
#define G3   1536
#define BB   64
#define TT   128
#define NR   8192            // BB*TT
#define K_LOC_ELEMS ((size_t)NR * VN)   // 81,920,000 floats of location logits

// Persistent recurrence config: 128 CTAs = 64 j-groups x 2 batch halves
#define NCTA 128
#define NHALF 64             // CTAs per independent batch-half chain
#define JH   8               // hidden dims per CTA
#define NGR  24              // gate rows per CTA (3 per dim)
#define BH   32              // batches per CTA
#define SP3  520             // frag-packed row stride (==8 mod 32: conflict-free)

// Tensor-core GEMM tiling (proj0/proj1 tf32)
#define FBM 128
#define FBN 128
#define FBK 16
#define SROW 20
// FC bf16 tiling
#define SROWB 12             // bf16x2 words per 16-k row (8 data + 4 pad); conflict-free frags

// Scratch (device globals; no allocations allowed)
// g_xp layout: [t][gate][j][b]  -> ((t*3+gate)*512 + j)*64 + b
__device__ float g_xp[(size_t)NR * G3];
// g_h layout: [m'=t*64+b][j]
__device__ float g_h [(size_t)NR * HH];
// packed state: word = bf16(hi) << 16 | bf16(lo), per [b][k]
__device__ unsigned g_state_p[BB * HH];
__device__ __align__(128) unsigned g_epochs[64];   // [0]=half0, [32]=half1 (separate lines)

__device__ __forceinline__ unsigned f2tf(float x) {
    unsigned u;
    asm("cvt.rna.tf32.f32 %0, %1;" : "=r"(u) : "f"(x));
    return u;
}

// pack two f32 -> bf16x2 (lo = first elem, hi = second)
__device__ __forceinline__ unsigned pbf2(float lo, float hi) {
    unsigned r;
    asm("cvt.rn.bf16x2.f32 %0, %1, %2;" : "=r"(r) : "f"(hi), "f"(lo));
    return r;
}

// pack state value: high 16 = bf16(s), low 16 = bf16(s - hi)
__device__ __forceinline__ unsigned pack_state(float s) {
    __nv_bfloat16 h = __float2bfloat16(s);
    float hf = __bfloat162float(h);
    __nv_bfloat16 l = __float2bfloat16(s - hf);
    return ((unsigned)__bfloat16_as_ushort(h) << 16) | (unsigned)__bfloat16_as_ushort(l);
}

#define MMA_TF32(c0,c1,c2,c3, a0,a1,a2,a3, b0,b1)                         \
    asm volatile(                                                          \
        "mma.sync.aligned.m16n8k8.row.col.f32.tf32.tf32.f32 "             \
        "{%0,%1,%2,%3}, {%4,%5,%6,%7}, {%8,%9}, {%0,%1,%2,%3};"           \
        : "+f"(c0), "+f"(c1), "+f"(c2), "+f"(c3)                           \
        : "r"(a0), "r"(a1), "r"(a2), "r"(a3), "r"(b0), "r"(b1))

#define MMA_BF16(c0,c1,c2,c3, a0,a1,a2,a3, b0,b1)                         \
    asm volatile(                                                          \
        "mma.sync.aligned.m16n8k16.row.col.f32.bf16.bf16.f32 "            \
        "{%0,%1,%2,%3}, {%4,%5,%6,%7}, {%8,%9}, {%0,%1,%2,%3};"           \
        : "+f"(c0), "+f"(c1), "+f"(c2), "+f"(c3)                           \
        : "r"(a0), "r"(a1), "r"(a2), "r"(a3), "r"(b0), "r"(b1))

// ---------------------------------------------------------------------------
__global__ void k_zero_state() {
    int i = blockIdx.x * blockDim.x + threadIdx.x;
    if (i < BB * HH) g_state_p[i] = 0u;
    if (i == 0) { g_epochs[0] = 0; g_epochs[32] = 0; }
}

// Half-grid barrier: release-arrive + acquire-poll (no MEMBAR.ALL.GPU).
__device__ __forceinline__ void half_bar(unsigned* ctr, unsigned target) {
    __syncthreads();
    if (threadIdx.x == 0) {
        asm volatile("red.release.gpu.add.u32 [%0], 1;" :: "l"(ctr) : "memory");
        unsigned v;
        do {
            asm volatile("ld.acquire.gpu.u32 %0, [%1];" : "=r"(v) : "l"(ctr) : "memory");
        } while (v < target);
    }
    __syncthreads();
}

// ---------------------------------------------------------------------------
// Persistent GRU via tf32 tensor cores.
// Weights tf32-rounded in smem. State stored globally as packed bf16 hi/lo:
// the mma b-operands are produced by 2 logic ops per word (no cvt chain),
// and the gather traffic is halved. Frag-pair packing (slot(k) =
// (k>>3)*8+(k&3)*2+((k>>2)&1)) makes every fragment load an LDS.64.
// Two independent batch-half chains, each with its own 64-CTA barrier.
// ---------------------------------------------------------------------------
__global__ void __launch_bounds__(256)
k_gru_tc(const float* __restrict__ whh, const float* __restrict__ bhh)
{
    extern __shared__ float smem[];
    float*    Wh  = smem;                      // [24][520] tf32-rounded, frag-packed
    unsigned* SpU = (unsigned*)(Wh + NGR * SP3); // [32][520] packed state words
    float*    Cs  = (float*)(SpU + BH * SP3);  // [24][33]

    const int tid = threadIdx.x;
    const int cta = blockIdx.x;
    const int jg = cta >> 1, bhf = cta & 1;
    const int j0 = jg * JH;
    const int gb0 = bhf * BH;
    unsigned* ctr = &g_epochs[bhf * 32];

    // Load + round + pack weight tile once
    for (int i = tid; i < NGR * 512; i += 256) {
        const int g = i >> 9, k = i & 511;
        const int jj = g / 3, gate = g - 3 * (g / 3);
        float w = whh[(size_t)(gate * 512 + j0 + jj) * HH + k];
        const int slot = (k >> 3) * 8 + (k & 3) * 2 + ((k >> 2) & 1);
        Wh[g * SP3 + slot] = __uint_as_float(f2tf(w));
    }

    const int lane = tid & 31, warp = tid >> 5;
    const int qg = lane >> 2, qt = lane & 3;
    const int mi = warp >> 2, ni = warp & 3;
    const int m0 = mi * 8;
    const int n0 = ni * 8;

    // gate-phase coords: 1 (j,b) per thread
    const int jj = tid >> 5;               // 0..7
    const int bl = tid & 31;
    const int gjg = j0 + jj;
    const int gb = gb0 + bl;
    const int hslot = (gjg >> 3) * 8 + (gjg & 3) * 2 + ((gjg >> 2) & 1);

    // biases: constant across steps
    const float bias_r = __ldg(&bhh[gjg]);
    const float bias_z = __ldg(&bhh[512 + gjg]);
    const float bias_n = __ldg(&bhh[1024 + gjg]);

    const float*    aP0 = &Wh[(m0 + qg) * SP3 + qt * 2];
    const float*    aP1 = &Wh[(m0 + 8 + qg) * SP3 + qt * 2];
    const unsigned* bP  = &SpU[(n0 + qg) * SP3 + qt * 2];

    unsigned target = NHALF;

    for (int t = 0; t < TT; ++t) {
        // Coalesced packed-state gather (half the volume of fp32)
        for (int i = tid; i < BH * 32; i += 256) {
            const int b = i >> 5, kq = (i & 31) << 4;     // 16 k's per uint4? no:
            // each uint4 = 4 words = 4 k's; 128 words per row / 4 = 32 chunks
            uint4 v = __ldcg((const uint4*)&g_state_p[(size_t)(gb0 + b) * HH + (i & 31) * 16]);
            // (i&31)*16 .. +3 wait: uint4 covers 4 words; chunk index c = i&31 covers k = c*16? 
            // -- replaced below by explicit 4-word handling
            (void)v; (void)kq;
        }
        // NOTE: simple correct version: 4 words (4 consecutive k) per iteration
        for (int i = tid; i < BH * 128; i += 256) {
            const int b = i >> 7, kq = (i & 127) << 2;    // 4 consecutive k
            uint4 v = __ldcg((const uint4*)&g_state_p[(size_t)(gb0 + b) * HH + kq]);
            unsigned* dst = &SpU[b * SP3 + (kq >> 3) * 8 + ((kq >> 2) & 1)];
            dst[0] = v.x; dst[2] = v.y; dst[4] = v.z; dst[6] = v.w;
        }

        // Prefetch xp gate inputs (DRAM) so latency overlaps the mma phase
        const float xr = __ldg(&g_xp[((size_t)(t * 3 + 0) * 512 + gjg) * 64 + gb]);
        const float xz = __ldg(&g_xp[((size_t)(t * 3 + 1) * 512 + gjg) * 64 + gb]);
        const float xn = __ldg(&g_xp[((size_t)(t * 3 + 2) * 512 + gjg) * 64 + gb]);
        __syncthreads();

        // 2 independent accumulator chains: W_tf32 * (state_hi + state_lo)
        float h0=0.f,h1=0.f,h2=0.f,h3=0.f;     // W * hi
        float g0=0.f,g1=0.f,g2=0.f,g3=0.f;     // W * lo
        #pragma unroll 8
        for (int kt = 0; kt < 64; ++kt) {
            float2 aA = *(const float2*)(aP0 + kt * 8);   // a0 (k=qt), a2 (k=qt+4)
            float2 aB = *(const float2*)(aP1 + kt * 8);   // a1, a3
            uint2  bw = *(const uint2*)(bP  + kt * 8);    // packed s(qt), s(qt+4)
            unsigned bh0 = bw.x & 0xFFFF0000u;
            unsigned bl0 = bw.x << 16;
            unsigned bh1 = bw.y & 0xFFFF0000u;
            unsigned bl1 = bw.y << 16;
            MMA_TF32(h0, h1, h2, h3,
                     __float_as_uint(aA.x), __float_as_uint(aB.x),
                     __float_as_uint(aA.y), __float_as_uint(aB.y), bh0, bh1);
            MMA_TF32(g0, g1, g2, g3,
                     __float_as_uint(aA.x), __float_as_uint(aB.x),
                     __float_as_uint(aA.y), __float_as_uint(aB.y), bl0, bl1);
        }
        float c0 = h0 + g0;
        float c1 = h1 + g1;
        float c2 = h2 + g2;
        float c3 = h3 + g3;

        // Write C frags to Cs[gate_row][b]; mi=1 keeps only rows 16..23
        if (mi == 0) {
            Cs[qg * 33 + n0 + 2 * qt]         = c0;
            Cs[qg * 33 + n0 + 2 * qt + 1]     = c1;
            Cs[(qg + 8) * 33 + n0 + 2 * qt]   = c2;
            Cs[(qg + 8) * 33 + n0 + 2 * qt+1] = c3;
        } else {
            Cs[(16 + qg) * 33 + n0 + 2 * qt]     = c2;
            Cs[(16 + qg) * 33 + n0 + 2 * qt + 1] = c3;
        }
        __syncthreads();

        // Gate math
        {
            float sr = Cs[(jj * 3 + 0) * 33 + bl] + bias_r;
            float sz = Cs[(jj * 3 + 1) * 33 + bl] + bias_z;
            float sn = Cs[(jj * 3 + 2) * 33 + bl] + bias_n;

            float r  = 1.0f / (1.0f + expf(-(xr + sr)));
            float z  = 1.0f / (1.0f + expf(-(xz + sz)));
            float nn = tanhf(xn + r * sn);

            unsigned hw = SpU[bl * SP3 + hslot];
            float hold = __uint_as_float(hw & 0xFFFF0000u) + __uint_as_float(hw << 16);
            float hnew = (1.0f - z) * nn + z * hold;
            g_state_p[(size_t)gb * HH + gjg] = pack_state(hnew);
            g_h[((size_t)t * 64 + gb) * HH + gjg] = hnew;
        }

        half_bar(ctr, target);
        target += NHALF;
    }
}

// ---------------------------------------------------------------------------
// proj0 via tf32 TC: xpT = emb[loc] @ w0[:, :256]^T (+ time*w0[:,256] + b0).
// ---------------------------------------------------------------------------
__global__ void __launch_bounds__(256)
k_proj0_tc(const int* __restrict__ loc, const float* __restrict__ times,
           const float* __restrict__ emb, const float* __restrict__ w0,
           const float* __restrict__ b0)
{
    __shared__ unsigned As[2][FBM * SROW];
    __shared__ unsigned Bs[2][FBN * SROW];
    __shared__ int locs[FBM];

    const int tid  = threadIdx.x;
    const int lane = tid & 31;
    const int warp = tid >> 5;
    const int wm = warp >> 2, wn = warp & 3;
    const int qg = lane >> 2, qt = lane & 3;

    const int mtile = blockIdx.y * FBM;
    const int ntile = blockIdx.x * FBN;

    if (tid < FBM) locs[tid] = loc[mtile + tid];
    __syncthreads();

    float acc[4][4][4];
    #pragma unroll
    for (int mi = 0; mi < 4; ++mi)
        #pragma unroll
        for (int ni = 0; ni < 4; ++ni)
            #pragma unroll
            for (int q = 0; q < 4; ++q) acc[mi][ni][q] = 0.0f;

    float4 ar[2], br[2];
    const int sm0 = tid >> 2, skq = (tid & 3) * 4;
    const int sm1 = (tid + 256) >> 2;
    const int rowA0 = locs[sm0], rowA1 = locs[sm1];
    const float* bptr0 = w0 + (size_t)(ntile + sm0) * 257;
    const float* bptr1 = w0 + (size_t)(ntile + sm1) * 257;

    {
        ar[0] = *(const float4*)&emb[(size_t)rowA0 * EE + skq];
        ar[1] = *(const float4*)&emb[(size_t)rowA1 * EE + skq];
        br[0].x = bptr0[skq]; br[0].y = bptr0[skq + 1]; br[0].z = bptr0[skq + 2]; br[0].w = bptr0[skq + 3];
        br[1].x = bptr1[skq]; br[1].y = bptr1[skq + 1]; br[1].z = bptr1[skq + 2]; br[1].w = bptr1[skq + 3];
    }
    {
        uint4 v;
        v.x = f2tf(ar[0].x); v.y = f2tf(ar[0].y); v.z = f2tf(ar[0].z); v.w = f2tf(ar[0].w);
        *(uint4*)&As[0][sm0 * SROW + skq] = v;
        v.x = f2tf(ar[1].x); v.y = f2tf(ar[1].y); v.z = f2tf(ar[1].z); v.w = f2tf(ar[1].w);
        *(uint4*)&As[0][sm1 * SROW + skq] = v;
        v.x = f2tf(br[0].x); v.y = f2tf(br[0].y); v.z = f2tf(br[0].z); v.w = f2tf(br[0].w);
        *(uint4*)&Bs[0][sm0 * SROW + skq] = v;
        v.x = f2tf(br[1].x); v.y = f2tf(br[1].y); v.z = f2tf(br[1].z); v.w = f2tf(br[1].w);
        *(uint4*)&Bs[0][sm1 * SROW + skq] = v;
    }
    __syncthreads();

    int buf = 0;
    const int NKT = EE / FBK;   // 16
    for (int kt = 0; kt < NKT; ++kt) {
        if (kt + 1 < NKT) {
            const int kk = (kt + 1) * FBK;
            ar[0] = *(const float4*)&emb[(size_t)rowA0 * EE + kk + skq];
            ar[1] = *(const float4*)&emb[(size_t)rowA1 * EE + kk + skq];
            br[0].x = bptr0[kk + skq]; br[0].y = bptr0[kk + skq + 1];
            br[0].z = bptr0[kk + skq + 2]; br[0].w = bptr0[kk + skq + 3];
            br[1].x = bptr1[kk + skq]; br[1].y = bptr1[kk + skq + 1];
            br[1].z = bptr1[kk + skq + 2]; br[1].w = bptr1[kk + skq + 3];
        }
        #pragma unroll
        for (int ks = 0; ks < FBK; ks += 8) {
            unsigned af[4][4];
            #pragma unroll
            for (int mi = 0; mi < 4; ++mi) {
                const int r = wm * 64 + mi * 16 + qg;
                af[mi][0] = As[buf][r * SROW + ks + qt];
                af[mi][1] = As[buf][(r + 8) * SROW + ks + qt];
                af[mi][2] = As[buf][r * SROW + ks + qt + 4];
                af[mi][3] = As[buf][(r + 8) * SROW + ks + qt + 4];
            }
            unsigned bf[4][2];
            #pragma unroll
            for (int ni = 0; ni < 4; ++ni) {
                const int n = wn * 32 + ni * 8 + qg;
                bf[ni][0] = Bs[buf][n * SROW + ks + qt];
                bf[ni][1] = Bs[buf][n * SROW + ks + qt + 4];
            }
            #pragma unroll
            for (int mi = 0; mi < 4; ++mi)
                #pragma unroll
                for (int ni = 0; ni < 4; ++ni)
                    MMA_TF32(acc[mi][ni][0], acc[mi][ni][1], acc[mi][ni][2], acc[mi][ni][3],
                             af[mi][0], af[mi][1], af[mi][2], af[mi][3],
                             bf[ni][0], bf[ni][1]);
        }
        if (kt + 1 < NKT) {
            const int nb = buf ^ 1;
            uint4 v;
            v.x = f2tf(ar[0].x); v.y = f2tf(ar[0].y); v.z = f2tf(ar[0].z); v.w = f2tf(ar[0].w);
            *(uint4*)&As[nb][sm0 * SROW + skq] = v;
            v.x = f2tf(ar[1].x); v.y = f2tf(ar[1].y); v.z = f2tf(ar[1].z); v.w = f2tf(ar[1].w);
            *(uint4*)&As[nb][sm1 * SROW + skq] = v;
            v.x = f2tf(br[0].x); v.y = f2tf(br[0].y); v.z = f2tf(br[0].z); v.w = f2tf(br[0].w);
            *(uint4*)&Bs[nb][sm0 * SROW + skq] = v;
            v.x = f2tf(br[1].x); v.y = f2tf(br[1].y); v.z = f2tf(br[1].z); v.w = f2tf(br[1].w);
            *(uint4*)&Bs[nb][sm1 * SROW + skq] = v;
        }
        __syncthreads();
        buf ^= 1;
    }

    // Epilogue -> transposed xp, + time * w0[:,256] + b0
    #pragma unroll
    for (int mi = 0; mi < 4; ++mi) {
        #pragma unroll
        for (int rr = 0; rr < 2; ++rr) {
            const int row = mtile + wm * 64 + mi * 16 + qg + rr * 8;   // n = b*128+t
            const int tt = row & 127, b = row >> 7;
            const float tm = __ldg(&times[row]);
            #pragma unroll
            for (int ni = 0; ni < 4; ++ni) {
                #pragma unroll
                for (int cc = 0; cc < 2; ++cc) {
                    const int col = ntile + wn * 32 + ni * 8 + qt * 2 + cc;
                    const int gate = col >> 9, jdim = col & 511;
                    g_xp[((size_t)(tt * 3 + gate) * 512 + jdim) * 64 + b] =
                        acc[mi][ni][rr * 2 + cc]
                        + tm * __ldg(&w0[(size_t)col * 257 + 256]) + __ldg(&b0[col]);
                }
            }
        }
    }
}

// ---------------------------------------------------------------------------
// proj1 via tf32 TC: xpT = g_h @ w1^T + b1.  M=8192, N=1536, K=512.
// ---------------------------------------------------------------------------
__global__ void __launch_bounds__(256)
k_proj1_tc(const float* __restrict__ w1, const float* __restrict__ b1)
{
    __shared__ unsigned As[2][FBM * SROW];
    __shared__ unsigned Bs[2][FBN * SROW];

    const int tid  = threadIdx.x;
    const int lane = tid & 31;
    const int warp = tid >> 5;
    const int wm = warp >> 2, wn = warp & 3;
    const int qg = lane >> 2, qt = lane & 3;

    const int mtile = blockIdx.y * FBM;
    const int ntile = blockIdx.x * FBN;

    float acc[4][4][4];
    #pragma unroll
    for (int mi = 0; mi < 4; ++mi)
        #pragma unroll
        for (int ni = 0; ni < 4; ++ni)
            #pragma unroll
            for (int q = 0; q < 4; ++q) acc[mi][ni][q] = 0.0f;

    float4 ar[2], br[2];
    const int sm0 = tid >> 2, skq = (tid & 3) * 4;
    const int sm1 = (tid + 256) >> 2;

    {
        ar[0] = *(const float4*)&g_h[(size_t)(mtile + sm0) * HH + skq];
        ar[1] = *(const float4*)&g_h[(size_t)(mtile + sm1) * HH + skq];
        br[0] = *(const float4*)&w1[(size_t)(ntile + sm0) * HH + skq];
        br[1] = *(const float4*)&w1[(size_t)(ntile + sm1) * HH + skq];
    }
    {
        uint4 v;
        v.x = f2tf(ar[0].x); v.y = f2tf(ar[0].y); v.z = f2tf(ar[0].z); v.w = f2tf(ar[0].w);
        *(uint4*)&As[0][sm0 * SROW + skq] = v;
        v.x = f2tf(ar[1].x); v.y = f2tf(ar[1].y); v.z = f2tf(ar[1].z); v.w = f2tf(ar[1].w);
        *(uint4*)&As[0][sm1 * SROW + skq] = v;
        v.x = f2tf(br[0].x); v.y = f2tf(br[0].y); v.z = f2tf(br[0].z); v.w = f2tf(br[0].w);
        *(uint4*)&Bs[0][sm0 * SROW + skq] = v;
        v.x = f2tf(br[1].x); v.y = f2tf(br[1].y); v.z = f2tf(br[1].z); v.w = f2tf(br[1].w);
        *(uint4*)&Bs[0][sm1 * SROW + skq] = v;
    }
    __syncthreads();

    int buf = 0;
    for (int kt = 0; kt < HH / FBK; ++kt) {
        if (kt + 1 < HH / FBK) {
            const int kk = (kt + 1) * FBK;
            ar[0] = *(const float4*)&g_h[(size_t)(mtile + sm0) * HH + kk + skq];
            ar[1] = *(const float4*)&g_h[(size_t)(mtile + sm1) * HH + kk + skq];
            br[0] = *(const float4*)&w1[(size_t)(ntile + sm0) * HH + kk + skq];
            br[1] = *(const float4*)&w1[(size_t)(ntile + sm1) * HH + kk + skq];
        }
        #pragma unroll
        for (int ks = 0; ks < FBK; ks += 8) {
            unsigned af[4][4];
            #pragma unroll
            for (int mi = 0; mi < 4; ++mi) {
                const int r = wm * 64 + mi * 16 + qg;
                af[mi][0] = As[buf][r * SROW + ks + qt];
                af[mi][1] = As[buf][(r + 8) * SROW + ks + qt];
                af[mi][2] = As[buf][r * SROW + ks + qt + 4];
                af[mi][3] = As[buf][(r + 8) * SROW + ks + qt + 4];
            }
            unsigned bf[4][2];
            #pragma unroll
            for (int ni = 0; ni < 4; ++ni) {
                const int n = wn * 32 + ni * 8 + qg;
                bf[ni][0] = Bs[buf][n * SROW + ks + qt];
                bf[ni][1] = Bs[buf][n * SROW + ks + qt + 4];
            }
            #pragma unroll
            for (int mi = 0; mi < 4; ++mi)
                #pragma unroll
                for (int ni = 0; ni < 4; ++ni)
                    MMA_TF32(acc[mi][ni][0], acc[mi][ni][1], acc[mi][ni][2], acc[mi][ni][3],
                             af[mi][0], af[mi][1], af[mi][2], af[mi][3],
                             bf[ni][0], bf[ni][1]);
        }
        if (kt + 1 < HH / FBK) {
            const int nb = buf ^ 1;
            uint4 v;
            v.x = f2tf(ar[0].x); v.y = f2tf(ar[0].y); v.z = f2tf(ar[0].z); v.w = f2tf(ar[0].w);
            *(uint4*)&As[nb][sm0 * SROW + skq] = v;
            v.x = f2tf(ar[1].x); v.y = f2tf(ar[1].y); v.z = f2tf(ar[1].z); v.w = f2tf(ar[1].w);
            *(uint4*)&As[nb][sm1 * SROW + skq] = v;
            v.x = f2tf(br[0].x); v.y = f2tf(br[0].y); v.z = f2tf(br[0].z); v.w = f2tf(br[0].w);
            *(uint4*)&Bs[nb][sm0 * SROW + skq] = v;
            v.x = f2tf(br[1].x); v.y = f2tf(br[1].y); v.z = f2tf(br[1].z); v.w = f2tf(br[1].w);
            *(uint4*)&Bs[nb][sm1 * SROW + skq] = v;
        }
        __syncthreads();
        buf ^= 1;
    }

    // Epilogue -> transposed xp
    #pragma unroll
    for (int mi = 0; mi < 4; ++mi) {
        #pragma unroll
        for (int rr = 0; rr < 2; ++rr) {
            const int row = mtile + wm * 64 + mi * 16 + qg + rr * 8;   // m' = t*64+b
            const int tt = row >> 6, b = row & 63;
            #pragma unroll
            for (int ni = 0; ni < 4; ++ni) {
                #pragma unroll
                for (int cc = 0; cc < 2; ++cc) {
                    const int col = ntile + wn * 32 + ni * 8 + qt * 2 + cc;
                    const int gate = col >> 9, jdim = col & 511;
                    g_xp[((size_t)(tt * 3 + gate) * 512 + jdim) * 64 + b] =
                        acc[mi][ni][rr * 2 + cc] + b1[col];
                }
            }
        }
    }
}

// ---------------------------------------------------------------------------
// FC via bf16 TC (m16n8k16). A rows are m'=t*64+b; output rows n=b*128+t.
// ---------------------------------------------------------------------------
__global__ void __launch_bounds__(256)
k_fc_tc(const float* __restrict__ fw, const float* __restrict__ fb,
        float* __restrict__ out)
{
    __shared__ unsigned As[2][FBM * SROWB];
    __shared__ unsigned Bs[2][FBN * SROWB];

    const int tid  = threadIdx.x;
    const int lane = tid & 31;
    const int warp = tid >> 5;
    const int wm = warp >> 2, wn = warp & 3;
    const int qg = lane >> 2, qt = lane & 3;

    const int mtile = blockIdx.y * FBM;
    const int ntile = blockIdx.x * FBN;

    float acc[4][4][4];
    #pragma unroll
    for (int mi = 0; mi < 4; ++mi)
        #pragma unroll
        for (int ni = 0; ni < 4; ++ni)
            #pragma unroll
            for (int q = 0; q < 4; ++q) acc[mi][ni][q] = 0.0f;

    float4 ar[2], br[2];
    const int sm0 = tid >> 2, skq = (tid & 3) * 4;   // f32 column within 16
    const int sw  = (tid & 3) * 2;                   // bf16x2 word offset
    const int sm1 = (tid + 256) >> 2;
    const int brow0 = (ntile + sm0 > VN) ? VN : ntile + sm0;
    const int brow1 = (ntile + sm1 > VN) ? VN : ntile + sm1;

    {
        ar[0] = *(const float4*)&g_h[(size_t)(mtile + sm0) * HH + skq];
        ar[1] = *(const float4*)&g_h[(size_t)(mtile + sm1) * HH + skq];
        br[0] = *(const float4*)&fw[(size_t)brow0 * HH + skq];
        br[1] = *(const float4*)&fw[(size_t)brow1 * HH + skq];
    }
    {
        uint2 u;
        u.x = pbf2(fmaxf(ar[0].x, 0.f), fmaxf(ar[0].y, 0.f));
        u.y = pbf2(fmaxf(ar[0].z, 0.f), fmaxf(ar[0].w, 0.f));
        *(uint2*)&As[0][sm0 * SROWB + sw] = u;
        u.x = pbf2(fmaxf(ar[1].x, 0.f), fmaxf(ar[1].y, 0.f));
        u.y = pbf2(fmaxf(ar[1].z, 0.f), fmaxf(ar[1].w, 0.f));
        *(uint2*)&As[0][sm1 * SROWB + sw] = u;
        u.x = pbf2(br[0].x, br[0].y); u.y = pbf2(br[0].z, br[0].w);
        *(uint2*)&Bs[0][sm0 * SROWB + sw] = u;
        u.x = pbf2(br[1].x, br[1].y); u.y = pbf2(br[1].z, br[1].w);
        *(uint2*)&Bs[0][sm1 * SROWB + sw] = u;
    }
    __syncthreads();

    int buf = 0;
    for (int kt = 0; kt < HH / 16; ++kt) {
        if (kt + 1 < HH / 16) {
            const int kk = (kt + 1) * 16;
            ar[0] = *(const float4*)&g_h[(size_t)(mtile + sm0) * HH + kk + skq];
            ar[1] = *(const float4*)&g_h[(size_t)(mtile + sm1) * HH + kk + skq];
            br[0] = *(const float4*)&fw[(size_t)brow0 * HH + kk + skq];
            br[1] = *(const float4*)&fw[(size_t)brow1 * HH + kk + skq];
        }

        {
            unsigned af[4][4];
            #pragma unroll
            for (int mi = 0; mi < 4; ++mi) {
                const int r = wm * 64 + mi * 16 + qg;
                af[mi][0] = As[buf][r * SROWB + qt];
                af[mi][1] = As[buf][(r + 8) * SROWB + qt];
                af[mi][2] = As[buf][r * SROWB + qt + 4];
                af[mi][3] = As[buf][(r + 8) * SROWB + qt + 4];
            }
            unsigned bfr[4][2];
            #pragma unroll
            for (int ni = 0; ni < 4; ++ni) {
                const int n = wn * 32 + ni * 8 + qg;
                bfr[ni][0] = Bs[buf][n * SROWB + qt];
                bfr[ni][1] = Bs[buf][n * SROWB + qt + 4];
            }
            #pragma unroll
            for (int mi = 0; mi < 4; ++mi)
                #pragma unroll
                for (int ni = 0; ni < 4; ++ni)
                    MMA_BF16(acc[mi][ni][0], acc[mi][ni][1], acc[mi][ni][2], acc[mi][ni][3],
                             af[mi][0], af[mi][1], af[mi][2], af[mi][3],
                             bfr[ni][0], bfr[ni][1]);
        }

        if (kt + 1 < HH / 16) {
            const int nb = buf ^ 1;
            uint2 u;
            u.x = pbf2(fmaxf(ar[0].x, 0.f), fmaxf(ar[0].y, 0.f));
            u.y = pbf2(fmaxf(ar[0].z, 0.f), fmaxf(ar[0].w, 0.f));
            *(uint2*)&As[nb][sm0 * SROWB + sw] = u;
            u.x = pbf2(fmaxf(ar[1].x, 0.f), fmaxf(ar[1].y, 0.f));
            u.y = pbf2(fmaxf(ar[1].z, 0.f), fmaxf(ar[1].w, 0.f));
            *(uint2*)&As[nb][sm1 * SROWB + sw] = u;
            u.x = pbf2(br[0].x, br[0].y); u.y = pbf2(br[0].z, br[0].w);
            *(uint2*)&Bs[nb][sm0 * SROWB + sw] = u;
            u.x = pbf2(br[1].x, br[1].y); u.y = pbf2(br[1].z, br[1].w);
            *(uint2*)&Bs[nb][sm1 * SROWB + sw] = u;
        }
        __syncthreads();
        buf ^= 1;
    }

    #pragma unroll
    for (int mi = 0; mi < 4; ++mi) {
        #pragma unroll
        for (int rr = 0; rr < 2; ++rr) {
            const int row = mtile + wm * 64 + mi * 16 + qg + rr * 8;   // m'
            const int n = (row & 63) * 128 + (row >> 6);               // out row
            #pragma unroll
            for (int ni = 0; ni < 4; ++ni) {
                #pragma unroll
                for (int cc = 0; cc < 2; ++cc) {
                    const int col = ntile + wn * 32 + ni * 8 + qt * 2 + cc;
                    if (col < VN)
                        out[(size_t)n * VN + col] = acc[mi][ni][rr * 2 + cc] + fb[col];
                    else if (col == VN)
                        out[K_LOC_ELEMS + n] = acc[mi][ni][rr * 2 + cc] + fb[col];
                }
            }
        }
    }
}

// ---------------------------------------------------------------------------
// Softmax: per-row log_softmax (row cached in smem, float4 I/O) + time sigmoid.
// ---------------------------------------------------------------------------
__global__ void __launch_bounds__(256)
k_softmax(float* __restrict__ out)
{
    extern __shared__ float row[];       // VN floats
    __shared__ float red[256];

    const int n = blockIdx.x;
    const int tid = threadIdx.x;
    float* base = out + (size_t)n * VN;
    const float4* b4 = (const float4*)base;
    float4* r4 = (float4*)row;
    const int NQ = VN / 4;               // 2500

    float mx = -1e30f;
    for (int i = tid; i < NQ; i += 256) {
        float4 v = b4[i];
        r4[i] = v;
        mx = fmaxf(mx, fmaxf(fmaxf(v.x, v.y), fmaxf(v.z, v.w)));
    }
    red[tid] = mx; __syncthreads();
    for (int s = 128; s > 0; s >>= 1) { if (tid < s) red[tid] = fmaxf(red[tid], red[tid + s]); __syncthreads(); }
    mx = red[0];
    __syncthreads();

    float sum = 0.f;
    for (int i = tid; i < NQ; i += 256) {
        float4 v = r4[i];
        sum += expf(v.x - mx) + expf(v.y - mx) + expf(v.z - mx) + expf(v.w - mx);
    }
    red[tid] = sum; __syncthreads();
    for (int s = 128; s > 0; s >>= 1) { if (tid < s) red[tid] += red[tid + s]; __syncthreads(); }
    float lse = mx + logf(red[0]);

    for (int i = tid; i < NQ; i += 256) {
        float4 v = r4[i];
        v.x -= lse; v.y -= lse; v.z -= lse; v.w -= lse;
        ((float4*)base)[i] = v;
    }

    if (tid == 0) {
        float tl = out[K_LOC_ELEMS + n];
        out[K_LOC_ELEMS + n] = 1.0f / (1.0f + expf(-tl));
    }
}

// ---------------------------------------------------------------------------
// Launch
// ---------------------------------------------------------------------------
extern "C" void kernel_launch(void* const* d_in, const int* in_sizes, int n_in,
                              void* d_out, int out_size)
{
    const int*   loc   = (const int*)  d_in[0];
    const float* times = (const float*)d_in[1];
    const float* emb   = (const float*)d_in[2];
    const float* w_ih0 = (const float*)d_in[3];
    const float* w_hh0 = (const float*)d_in[4];
    const float* b_ih0 = (const float*)d_in[5];
    const float* b_hh0 = (const float*)d_in[6];
    const float* w_ih1 = (const float*)d_in[7];
    const float* w_hh1 = (const float*)d_in[8];
    const float* b_ih1 = (const float*)d_in[9];
    const float* b_hh1 = (const float*)d_in[10];
    const float* fc_w  = (const float*)d_in[11];
    const float* fc_b  = (const float*)d_in[12];
    float* out = (float*)d_out;

    const int gru_smem = (NGR * SP3 + BH * SP3 + NGR * 33) * sizeof(float); // ~120 KB
    static int attr_done = 0;
    if (!attr_done) {
        cudaFuncSetAttribute(k_gru_tc, cudaFuncAttributeMaxDynamicSharedMemorySize, gru_smem);
        attr_done = 1;
    }

    // Layer 0
    k_proj0_tc<<<dim3(G3 / FBN, NR / FBM), 256>>>(loc, times, emb, w_ih0, b_ih0);
    k_zero_state<<<(BB * HH + 255) / 256, 256>>>();
    k_gru_tc<<<NCTA, 256, gru_smem>>>(w_hh0, b_hh0);

    // Layer 1
    k_proj1_tc<<<dim3(G3 / FBN, NR / FBM), 256>>>(w_ih1, b_ih1);
    k_zero_state<<<(BB * HH + 255) / 256, 256>>>();
    k_gru_tc<<<NCTA, 256, gru_smem>>>(w_hh1, b_hh1);

    // FC -> logits straight into d_out (tensor cores, bf16)
    k_fc_tc<<<dim3((VOUT + FBN - 1) / FBN, NR / FBM), 256>>>(fc_w, fc_b, out);

    // log_softmax + time sigmoid
    k_softmax<<<NR, 256, VN * sizeof(float)>>>(out);
}

// round 15
// speedup vs baseline: 3.1202x; 1.1008x over previous
#include <cuda_runtime.h>
#include <cuda_bf16.h>
#include <math.h>

// Problem constants
#define VN   10000
#define VOUT 10001
#define EE   256
#define HH   512
#define G3   1536
#define BB   64
#define TT   128
#define NR   8192            // BB*TT
#define K_LOC_ELEMS ((size_t)NR * VN)   // 81,920,000 floats of location logits

// Persistent recurrence config: 128 CTAs = 64 j-groups x 2 batch halves
#define NCTA 128
#define NHALF 64             // CTAs per independent batch-half chain
#define JH   8               // hidden dims per CTA
#define NGR  24              // gate rows per CTA (3 per dim)
#define BH   32              // batches per CTA
#define SP3  520             // frag-packed row stride (==8 mod 32: conflict-free)

// Tensor-core GEMM tiling (proj0/proj1 tf32)
#define FBM 128
#define FBN 128
#define FBK 16
#define SROW 20
// FC bf16 tiling
#define SROWB 12             // bf16x2 words per 16-k row (8 data + 4 pad); conflict-free frags

// Scratch (device globals; no allocations allowed)
// g_xp layout: [t][gate][j][b]  -> ((t*3+gate)*512 + j)*64 + b
__device__ float g_xp[(size_t)NR * G3];
// g_h layout: [m'=t*64+b][j]
__device__ float g_h [(size_t)NR * HH];
// packed state, PRODUCER-PERMUTED frag-pack layout: word at [b*512 + slot(k)]
// word = bf16(hi) << 16 | bf16(lo)
__device__ unsigned g_state_p[BB * HH];
__device__ __align__(128) unsigned g_epochs[64];   // [0]=half0, [32]=half1 (separate lines)

__device__ __forceinline__ unsigned f2tf(float x) {
    unsigned u;
    asm("cvt.rna.tf32.f32 %0, %1;" : "=r"(u) : "f"(x));
    return u;
}

// pack two f32 -> bf16x2 (lo = first elem, hi = second)
__device__ __forceinline__ unsigned pbf2(float lo, float hi) {
    unsigned r;
    asm("cvt.rn.bf16x2.f32 %0, %1, %2;" : "=r"(r) : "f"(hi), "f"(lo));
    return r;
}

// pack state value: high 16 = bf16(s), low 16 = bf16(s - hi)
__device__ __forceinline__ unsigned pack_state(float s) {
    __nv_bfloat16 h = __float2bfloat16(s);
    float hf = __bfloat162float(h);
    __nv_bfloat16 l = __float2bfloat16(s - hf);
    return ((unsigned)__bfloat16_as_ushort(h) << 16) | (unsigned)__bfloat16_as_ushort(l);
}

#define MMA_TF32(c0,c1,c2,c3, a0,a1,a2,a3, b0,b1)                         \
    asm volatile(                                                          \
        "mma.sync.aligned.m16n8k8.row.col.f32.tf32.tf32.f32 "             \
        "{%0,%1,%2,%3}, {%4,%5,%6,%7}, {%8,%9}, {%0,%1,%2,%3};"           \
        : "+f"(c0), "+f"(c1), "+f"(c2), "+f"(c3)                           \
        : "r"(a0), "r"(a1), "r"(a2), "r"(a3), "r"(b0), "r"(b1))

#define MMA_BF16(c0,c1,c2,c3, a0,a1,a2,a3, b0,b1)                         \
    asm volatile(                                                          \
        "mma.sync.aligned.m16n8k16.row.col.f32.bf16.bf16.f32 "            \
        "{%0,%1,%2,%3}, {%4,%5,%6,%7}, {%8,%9}, {%0,%1,%2,%3};"           \
        : "+f"(c0), "+f"(c1), "+f"(c2), "+f"(c3)                           \
        : "r"(a0), "r"(a1), "r"(a2), "r"(a3), "r"(b0), "r"(b1))

// ---------------------------------------------------------------------------
__global__ void k_zero_state() {
    int i = blockIdx.x * blockDim.x + threadIdx.x;
    if (i < BB * HH) g_state_p[i] = 0u;
    if (i == 0) { g_epochs[0] = 0; g_epochs[32] = 0; }
}

// Half-grid barrier: release-arrive + acquire-poll (no MEMBAR.ALL.GPU).
__device__ __forceinline__ void half_bar(unsigned* ctr, unsigned target) {
    __syncthreads();
    if (threadIdx.x == 0) {
        asm volatile("red.release.gpu.add.u32 [%0], 1;" :: "l"(ctr) : "memory");
        unsigned v;
        do {
            asm volatile("ld.acquire.gpu.u32 %0, [%1];" : "=r"(v) : "l"(ctr) : "memory");
        } while (v < target);
    }
    __syncthreads();
}

// ---------------------------------------------------------------------------
// Persistent GRU via tf32 tensor cores.
// Weights tf32-rounded in smem. State stored globally as packed bf16 hi/lo
// in PRODUCER-PERMUTED frag-pack order, so the per-step gather is a straight
// uint4 copy (no scatter). Gate-phase coords (jj = tid&7, bl = tid>>3) make
// the state/g_h stores coalesce into 4 sectors per warp.
// Two independent batch-half chains, each with its own 64-CTA barrier.
// ---------------------------------------------------------------------------
__global__ void __launch_bounds__(256)
k_gru_tc(const float* __restrict__ whh, const float* __restrict__ bhh)
{
    extern __shared__ float smem[];
    float*    Wh  = smem;                        // [24][520] tf32-rounded, frag-packed
    unsigned* SpU = (unsigned*)(Wh + NGR * SP3); // [32][520] packed state words
    float*    Cs  = (float*)(SpU + BH * SP3);    // [24][33]

    const int tid = threadIdx.x;
    const int cta = blockIdx.x;
    const int jg = cta >> 1, bhf = cta & 1;
    const int j0 = jg * JH;
    const int gb0 = bhf * BH;
    unsigned* ctr = &g_epochs[bhf * 32];

    // Load + round + pack weight tile once
    for (int i = tid; i < NGR * 512; i += 256) {
        const int g = i >> 9, k = i & 511;
        const int jj = g / 3, gate = g - 3 * (g / 3);
        float w = whh[(size_t)(gate * 512 + j0 + jj) * HH + k];
        const int slot = (k >> 3) * 8 + (k & 3) * 2 + ((k >> 2) & 1);
        Wh[g * SP3 + slot] = __uint_as_float(f2tf(w));
    }

    const int lane = tid & 31, warp = tid >> 5;
    const int qg = lane >> 2, qt = lane & 3;
    const int mi = warp >> 2, ni = warp & 3;
    const int m0 = mi * 8;
    const int n0 = ni * 8;

    // gate-phase coords: jj fast (8), bl slow (32) -> coalesced slot stores
    const int jj = tid & 7;
    const int bl = tid >> 3;
    const int gjg = j0 + jj;
    const int gb = gb0 + bl;
    const int hslot = (gjg >> 3) * 8 + (gjg & 3) * 2 + ((gjg >> 2) & 1);

    // biases: constant across steps
    const float bias_r = __ldg(&bhh[gjg]);
    const float bias_z = __ldg(&bhh[512 + gjg]);
    const float bias_n = __ldg(&bhh[1024 + gjg]);

    const float*    aP0 = &Wh[(m0 + qg) * SP3 + qt * 2];
    const float*    aP1 = &Wh[(m0 + 8 + qg) * SP3 + qt * 2];
    const unsigned* bP  = &SpU[(n0 + qg) * SP3 + qt * 2];

    unsigned target = NHALF;

    for (int t = 0; t < TT; ++t) {
        // Straight coalesced copy: global (already frag-packed) -> smem
        for (int i = tid; i < BH * 128; i += 256) {
            const int b = i >> 7, c = (i & 127) << 2;
            uint4 v = __ldcg((const uint4*)&g_state_p[(size_t)(gb0 + b) * HH + c]);
            *(uint4*)&SpU[b * SP3 + c] = v;
        }

        // Prefetch xp gate inputs (DRAM) so latency overlaps the mma phase
        const float xr = __ldg(&g_xp[((size_t)(t * 3 + 0) * 512 + gjg) * 64 + gb]);
        const float xz = __ldg(&g_xp[((size_t)(t * 3 + 1) * 512 + gjg) * 64 + gb]);
        const float xn = __ldg(&g_xp[((size_t)(t * 3 + 2) * 512 + gjg) * 64 + gb]);
        __syncthreads();

        // 2 independent accumulator chains: W_tf32 * (state_hi + state_lo)
        float h0=0.f,h1=0.f,h2=0.f,h3=0.f;     // W * hi
        float g0=0.f,g1=0.f,g2=0.f,g3=0.f;     // W * lo
        #pragma unroll 8
        for (int kt = 0; kt < 64; ++kt) {
            float2 aA = *(const float2*)(aP0 + kt * 8);   // a0 (k=qt), a2 (k=qt+4)
            float2 aB = *(const float2*)(aP1 + kt * 8);   // a1, a3
            uint2  bw = *(const uint2*)(bP  + kt * 8);    // packed s(qt), s(qt+4)
            unsigned bh0 = bw.x & 0xFFFF0000u;
            unsigned bl0 = bw.x << 16;
            unsigned bh1 = bw.y & 0xFFFF0000u;
            unsigned bl1 = bw.y << 16;
            MMA_TF32(h0, h1, h2, h3,
                     __float_as_uint(aA.x), __float_as_uint(aB.x),
                     __float_as_uint(aA.y), __float_as_uint(aB.y), bh0, bh1);
            MMA_TF32(g0, g1, g2, g3,
                     __float_as_uint(aA.x), __float_as_uint(aB.x),
                     __float_as_uint(aA.y), __float_as_uint(aB.y), bl0, bl1);
        }
        float c0 = h0 + g0;
        float c1 = h1 + g1;
        float c2 = h2 + g2;
        float c3 = h3 + g3;

        // Write C frags to Cs[gate_row][b]; mi=1 keeps only rows 16..23
        if (mi == 0) {
            Cs[qg * 33 + n0 + 2 * qt]         = c0;
            Cs[qg * 33 + n0 + 2 * qt + 1]     = c1;
            Cs[(qg + 8) * 33 + n0 + 2 * qt]   = c2;
            Cs[(qg + 8) * 33 + n0 + 2 * qt+1] = c3;
        } else {
            Cs[(16 + qg) * 33 + n0 + 2 * qt]     = c2;
            Cs[(16 + qg) * 33 + n0 + 2 * qt + 1] = c3;
        }
        __syncthreads();

        // Gate math
        {
            float sr = Cs[(jj * 3 + 0) * 33 + bl] + bias_r;
            float sz = Cs[(jj * 3 + 1) * 33 + bl] + bias_z;
            float sn = Cs[(jj * 3 + 2) * 33 + bl] + bias_n;

            float r  = 1.0f / (1.0f + expf(-(xr + sr)));
            float z  = 1.0f / (1.0f + expf(-(xz + sz)));
            float nn = tanhf(xn + r * sn);

            unsigned hw = SpU[bl * SP3 + hslot];
            float hold = __uint_as_float(hw & 0xFFFF0000u) + __uint_as_float(hw << 16);
            float hnew = (1.0f - z) * nn + z * hold;
            g_state_p[(size_t)gb * HH + hslot] = pack_state(hnew);   // producer-permuted
            g_h[((size_t)t * 64 + gb) * HH + gjg] = hnew;
        }

        half_bar(ctr, target);
        target += NHALF;
    }
}

// ---------------------------------------------------------------------------
// proj0 via tf32 TC: xpT = emb[loc] @ w0[:, :256]^T (+ time*w0[:,256] + b0).
// ---------------------------------------------------------------------------
__global__ void __launch_bounds__(256)
k_proj0_tc(const int* __restrict__ loc, const float* __restrict__ times,
           const float* __restrict__ emb, const float* __restrict__ w0,
           const float* __restrict__ b0)
{
    __shared__ unsigned As[2][FBM * SROW];
    __shared__ unsigned Bs[2][FBN * SROW];
    __shared__ int locs[FBM];

    const int tid  = threadIdx.x;
    const int lane = tid & 31;
    const int warp = tid >> 5;
    const int wm = warp >> 2, wn = warp & 3;
    const int qg = lane >> 2, qt = lane & 3;

    const int mtile = blockIdx.y * FBM;
    const int ntile = blockIdx.x * FBN;

    if (tid < FBM) locs[tid] = loc[mtile + tid];
    __syncthreads();

    float acc[4][4][4];
    #pragma unroll
    for (int mi = 0; mi < 4; ++mi)
        #pragma unroll
        for (int ni = 0; ni < 4; ++ni)
            #pragma unroll
            for (int q = 0; q < 4; ++q) acc[mi][ni][q] = 0.0f;

    float4 ar[2], br[2];
    const int sm0 = tid >> 2, skq = (tid & 3) * 4;
    const int sm1 = (tid + 256) >> 2;
    const int rowA0 = locs[sm0], rowA1 = locs[sm1];
    const float* bptr0 = w0 + (size_t)(ntile + sm0) * 257;
    const float* bptr1 = w0 + (size_t)(ntile + sm1) * 257;

    {
        ar[0] = *(const float4*)&emb[(size_t)rowA0 * EE + skq];
        ar[1] = *(const float4*)&emb[(size_t)rowA1 * EE + skq];
        br[0].x = bptr0[skq]; br[0].y = bptr0[skq + 1]; br[0].z = bptr0[skq + 2]; br[0].w = bptr0[skq + 3];
        br[1].x = bptr1[skq]; br[1].y = bptr1[skq + 1]; br[1].z = bptr1[skq + 2]; br[1].w = bptr1[skq + 3];
    }
    {
        uint4 v;
        v.x = f2tf(ar[0].x); v.y = f2tf(ar[0].y); v.z = f2tf(ar[0].z); v.w = f2tf(ar[0].w);
        *(uint4*)&As[0][sm0 * SROW + skq] = v;
        v.x = f2tf(ar[1].x); v.y = f2tf(ar[1].y); v.z = f2tf(ar[1].z); v.w = f2tf(ar[1].w);
        *(uint4*)&As[0][sm1 * SROW + skq] = v;
        v.x = f2tf(br[0].x); v.y = f2tf(br[0].y); v.z = f2tf(br[0].z); v.w = f2tf(br[0].w);
        *(uint4*)&Bs[0][sm0 * SROW + skq] = v;
        v.x = f2tf(br[1].x); v.y = f2tf(br[1].y); v.z = f2tf(br[1].z); v.w = f2tf(br[1].w);
        *(uint4*)&Bs[0][sm1 * SROW + skq] = v;
    }
    __syncthreads();

    int buf = 0;
    const int NKT = EE / FBK;   // 16
    for (int kt = 0; kt < NKT; ++kt) {
        if (kt + 1 < NKT) {
            const int kk = (kt + 1) * FBK;
            ar[0] = *(const float4*)&emb[(size_t)rowA0 * EE + kk + skq];
            ar[1] = *(const float4*)&emb[(size_t)rowA1 * EE + kk + skq];
            br[0].x = bptr0[kk + skq]; br[0].y = bptr0[kk + skq + 1];
            br[0].z = bptr0[kk + skq + 2]; br[0].w = bptr0[kk + skq + 3];
            br[1].x = bptr1[kk + skq]; br[1].y = bptr1[kk + skq + 1];
            br[1].z = bptr1[kk + skq + 2]; br[1].w = bptr1[kk + skq + 3];
        }
        #pragma unroll
        for (int ks = 0; ks < FBK; ks += 8) {
            unsigned af[4][4];
            #pragma unroll
            for (int mi = 0; mi < 4; ++mi) {
                const int r = wm * 64 + mi * 16 + qg;
                af[mi][0] = As[buf][r * SROW + ks + qt];
                af[mi][1] = As[buf][(r + 8) * SROW + ks + qt];
                af[mi][2] = As[buf][r * SROW + ks + qt + 4];
                af[mi][3] = As[buf][(r + 8) * SROW + ks + qt + 4];
            }
            unsigned bf[4][2];
            #pragma unroll
            for (int ni = 0; ni < 4; ++ni) {
                const int n = wn * 32 + ni * 8 + qg;
                bf[ni][0] = Bs[buf][n * SROW + ks + qt];
                bf[ni][1] = Bs[buf][n * SROW + ks + qt + 4];
            }
            #pragma unroll
            for (int mi = 0; mi < 4; ++mi)
                #pragma unroll
                for (int ni = 0; ni < 4; ++ni)
                    MMA_TF32(acc[mi][ni][0], acc[mi][ni][1], acc[mi][ni][2], acc[mi][ni][3],
                             af[mi][0], af[mi][1], af[mi][2], af[mi][3],
                             bf[ni][0], bf[ni][1]);
        }
        if (kt + 1 < NKT) {
            const int nb = buf ^ 1;
            uint4 v;
            v.x = f2tf(ar[0].x); v.y = f2tf(ar[0].y); v.z = f2tf(ar[0].z); v.w = f2tf(ar[0].w);
            *(uint4*)&As[nb][sm0 * SROW + skq] = v;
            v.x = f2tf(ar[1].x); v.y = f2tf(ar[1].y); v.z = f2tf(ar[1].z); v.w = f2tf(ar[1].w);
            *(uint4*)&As[nb][sm1 * SROW + skq] = v;
            v.x = f2tf(br[0].x); v.y = f2tf(br[0].y); v.z = f2tf(br[0].z); v.w = f2tf(br[0].w);
            *(uint4*)&Bs[nb][sm0 * SROW + skq] = v;
            v.x = f2tf(br[1].x); v.y = f2tf(br[1].y); v.z = f2tf(br[1].z); v.w = f2tf(br[1].w);
            *(uint4*)&Bs[nb][sm1 * SROW + skq] = v;
        }
        __syncthreads();
        buf ^= 1;
    }

    // Epilogue -> transposed xp, + time * w0[:,256] + b0
    #pragma unroll
    for (int mi = 0; mi < 4; ++mi) {
        #pragma unroll
        for (int rr = 0; rr < 2; ++rr) {
            const int row = mtile + wm * 64 + mi * 16 + qg + rr * 8;   // n = b*128+t
            const int tt = row & 127, b = row >> 7;
            const float tm = __ldg(&times[row]);
            #pragma unroll
            for (int ni = 0; ni < 4; ++ni) {
                #pragma unroll
                for (int cc = 0; cc < 2; ++cc) {
                    const int col = ntile + wn * 32 + ni * 8 + qt * 2 + cc;
                    const int gate = col >> 9, jdim = col & 511;
                    g_xp[((size_t)(tt * 3 + gate) * 512 + jdim) * 64 + b] =
                        acc[mi][ni][rr * 2 + cc]
                        + tm * __ldg(&w0[(size_t)col * 257 + 256]) + __ldg(&b0[col]);
                }
            }
        }
    }
}

// ---------------------------------------------------------------------------
// proj1 via tf32 TC: xpT = g_h @ w1^T + b1.  M=8192, N=1536, K=512.
// ---------------------------------------------------------------------------
__global__ void __launch_bounds__(256)
k_proj1_tc(const float* __restrict__ w1, const float* __restrict__ b1)
{
    __shared__ unsigned As[2][FBM * SROW];
    __shared__ unsigned Bs[2][FBN * SROW];

    const int tid  = threadIdx.x;
    const int lane = tid & 31;
    const int warp = tid >> 5;
    const int wm = warp >> 2, wn = warp & 3;
    const int qg = lane >> 2, qt = lane & 3;

    const int mtile = blockIdx.y * FBM;
    const int ntile = blockIdx.x * FBN;

    float acc[4][4][4];
    #pragma unroll
    for (int mi = 0; mi < 4; ++mi)
        #pragma unroll
        for (int ni = 0; ni < 4; ++ni)
            #pragma unroll
            for (int q = 0; q < 4; ++q) acc[mi][ni][q] = 0.0f;

    float4 ar[2], br[2];
    const int sm0 = tid >> 2, skq = (tid & 3) * 4;
    const int sm1 = (tid + 256) >> 2;

    {
        ar[0] = *(const float4*)&g_h[(size_t)(mtile + sm0) * HH + skq];
        ar[1] = *(const float4*)&g_h[(size_t)(mtile + sm1) * HH + skq];
        br[0] = *(const float4*)&w1[(size_t)(ntile + sm0) * HH + skq];
        br[1] = *(const float4*)&w1[(size_t)(ntile + sm1) * HH + skq];
    }
    {
        uint4 v;
        v.x = f2tf(ar[0].x); v.y = f2tf(ar[0].y); v.z = f2tf(ar[0].z); v.w = f2tf(ar[0].w);
        *(uint4*)&As[0][sm0 * SROW + skq] = v;
        v.x = f2tf(ar[1].x); v.y = f2tf(ar[1].y); v.z = f2tf(ar[1].z); v.w = f2tf(ar[1].w);
        *(uint4*)&As[0][sm1 * SROW + skq] = v;
        v.x = f2tf(br[0].x); v.y = f2tf(br[0].y); v.z = f2tf(br[0].z); v.w = f2tf(br[0].w);
        *(uint4*)&Bs[0][sm0 * SROW + skq] = v;
        v.x = f2tf(br[1].x); v.y = f2tf(br[1].y); v.z = f2tf(br[1].z); v.w = f2tf(br[1].w);
        *(uint4*)&Bs[0][sm1 * SROW + skq] = v;
    }
    __syncthreads();

    int buf = 0;
    for (int kt = 0; kt < HH / FBK; ++kt) {
        if (kt + 1 < HH / FBK) {
            const int kk = (kt + 1) * FBK;
            ar[0] = *(const float4*)&g_h[(size_t)(mtile + sm0) * HH + kk + skq];
            ar[1] = *(const float4*)&g_h[(size_t)(mtile + sm1) * HH + kk + skq];
            br[0] = *(const float4*)&w1[(size_t)(ntile + sm0) * HH + kk + skq];
            br[1] = *(const float4*)&w1[(size_t)(ntile + sm1) * HH + kk + skq];
        }
        #pragma unroll
        for (int ks = 0; ks < FBK; ks += 8) {
            unsigned af[4][4];
            #pragma unroll
            for (int mi = 0; mi < 4; ++mi) {
                const int r = wm * 64 + mi * 16 + qg;
                af[mi][0] = As[buf][r * SROW + ks + qt];
                af[mi][1] = As[buf][(r + 8) * SROW + ks + qt];
                af[mi][2] = As[buf][r * SROW + ks + qt + 4];
                af[mi][3] = As[buf][(r + 8) * SROW + ks + qt + 4];
            }
            unsigned bf[4][2];
            #pragma unroll
            for (int ni = 0; ni < 4; ++ni) {
                const int n = wn * 32 + ni * 8 + qg;
                bf[ni][0] = Bs[buf][n * SROW + ks + qt];
                bf[ni][1] = Bs[buf][n * SROW + ks + qt + 4];
            }
            #pragma unroll
            for (int mi = 0; mi < 4; ++mi)
                #pragma unroll
                for (int ni = 0; ni < 4; ++ni)
                    MMA_TF32(acc[mi][ni][0], acc[mi][ni][1], acc[mi][ni][2], acc[mi][ni][3],
                             af[mi][0], af[mi][1], af[mi][2], af[mi][3],
                             bf[ni][0], bf[ni][1]);
        }
        if (kt + 1 < HH / FBK) {
            const int nb = buf ^ 1;
            uint4 v;
            v.x = f2tf(ar[0].x); v.y = f2tf(ar[0].y); v.z = f2tf(ar[0].z); v.w = f2tf(ar[0].w);
            *(uint4*)&As[nb][sm0 * SROW + skq] = v;
            v.x = f2tf(ar[1].x); v.y = f2tf(ar[1].y); v.z = f2tf(ar[1].z); v.w = f2tf(ar[1].w);
            *(uint4*)&As[nb][sm1 * SROW + skq] = v;
            v.x = f2tf(br[0].x); v.y = f2tf(br[0].y); v.z = f2tf(br[0].z); v.w = f2tf(br[0].w);
            *(uint4*)&Bs[nb][sm0 * SROW + skq] = v;
            v.x = f2tf(br[1].x); v.y = f2tf(br[1].y); v.z = f2tf(br[1].z); v.w = f2tf(br[1].w);
            *(uint4*)&Bs[nb][sm1 * SROW + skq] = v;
        }
        __syncthreads();
        buf ^= 1;
    }

    // Epilogue -> transposed xp
    #pragma unroll
    for (int mi = 0; mi < 4; ++mi) {
        #pragma unroll
        for (int rr = 0; rr < 2; ++rr) {
            const int row = mtile + wm * 64 + mi * 16 + qg + rr * 8;   // m' = t*64+b
            const int tt = row >> 6, b = row & 63;
            #pragma unroll
            for (int ni = 0; ni < 4; ++ni) {
                #pragma unroll
                for (int cc = 0; cc < 2; ++cc) {
                    const int col = ntile + wn * 32 + ni * 8 + qt * 2 + cc;
                    const int gate = col >> 9, jdim = col & 511;
                    g_xp[((size_t)(tt * 3 + gate) * 512 + jdim) * 64 + b] =
                        acc[mi][ni][rr * 2 + cc] + b1[col];
                }
            }
        }
    }
}

// ---------------------------------------------------------------------------
// FC via bf16 TC (m16n8k16). A rows are m'=t*64+b; output rows n=b*128+t.
// ---------------------------------------------------------------------------
__global__ void __launch_bounds__(256)
k_fc_tc(const float* __restrict__ fw, const float* __restrict__ fb,
        float* __restrict__ out)
{
    __shared__ unsigned As[2][FBM * SROWB];
    __shared__ unsigned Bs[2][FBN * SROWB];

    const int tid  = threadIdx.x;
    const int lane = tid & 31;
    const int warp = tid >> 5;
    const int wm = warp >> 2, wn = warp & 3;
    const int qg = lane >> 2, qt = lane & 3;

    const int mtile = blockIdx.y * FBM;
    const int ntile = blockIdx.x * FBN;

    float acc[4][4][4];
    #pragma unroll
    for (int mi = 0; mi < 4; ++mi)
        #pragma unroll
        for (int ni = 0; ni < 4; ++ni)
            #pragma unroll
            for (int q = 0; q < 4; ++q) acc[mi][ni][q] = 0.0f;

    float4 ar[2], br[2];
    const int sm0 = tid >> 2, skq = (tid & 3) * 4;   // f32 column within 16
    const int sw  = (tid & 3) * 2;                   // bf16x2 word offset
    const int sm1 = (tid + 256) >> 2;
    const int brow0 = (ntile + sm0 > VN) ? VN : ntile + sm0;
    const int brow1 = (ntile + sm1 > VN) ? VN : ntile + sm1;

    {
        ar[0] = *(const float4*)&g_h[(size_t)(mtile + sm0) * HH + skq];
        ar[1] = *(const float4*)&g_h[(size_t)(mtile + sm1) * HH + skq];
        br[0] = *(const float4*)&fw[(size_t)brow0 * HH + skq];
        br[1] = *(const float4*)&fw[(size_t)brow1 * HH + skq];
    }
    {
        uint2 u;
        u.x = pbf2(fmaxf(ar[0].x, 0.f), fmaxf(ar[0].y, 0.f));
        u.y = pbf2(fmaxf(ar[0].z, 0.f), fmaxf(ar[0].w, 0.f));
        *(uint2*)&As[0][sm0 * SROWB + sw] = u;
        u.x = pbf2(fmaxf(ar[1].x, 0.f), fmaxf(ar[1].y, 0.f));
        u.y = pbf2(fmaxf(ar[1].z, 0.f), fmaxf(ar[1].w, 0.f));
        *(uint2*)&As[0][sm1 * SROWB + sw] = u;
        u.x = pbf2(br[0].x, br[0].y); u.y = pbf2(br[0].z, br[0].w);
        *(uint2*)&Bs[0][sm0 * SROWB + sw] = u;
        u.x = pbf2(br[1].x, br[1].y); u.y = pbf2(br[1].z, br[1].w);
        *(uint2*)&Bs[0][sm1 * SROWB + sw] = u;
    }
    __syncthreads();

    int buf = 0;
    for (int kt = 0; kt < HH / 16; ++kt) {
        if (kt + 1 < HH / 16) {
            const int kk = (kt + 1) * 16;
            ar[0] = *(const float4*)&g_h[(size_t)(mtile + sm0) * HH + kk + skq];
            ar[1] = *(const float4*)&g_h[(size_t)(mtile + sm1) * HH + kk + skq];
            br[0] = *(const float4*)&fw[(size_t)brow0 * HH + kk + skq];
            br[1] = *(const float4*)&fw[(size_t)brow1 * HH + kk + skq];
        }

        {
            unsigned af[4][4];
            #pragma unroll
            for (int mi = 0; mi < 4; ++mi) {
                const int r = wm * 64 + mi * 16 + qg;
                af[mi][0] = As[buf][r * SROWB + qt];
                af[mi][1] = As[buf][(r + 8) * SROWB + qt];
                af[mi][2] = As[buf][r * SROWB + qt + 4];
                af[mi][3] = As[buf][(r + 8) * SROWB + qt + 4];
            }
            unsigned bfr[4][2];
            #pragma unroll
            for (int ni = 0; ni < 4; ++ni) {
                const int n = wn * 32 + ni * 8 + qg;
                bfr[ni][0] = Bs[buf][n * SROWB + qt];
                bfr[ni][1] = Bs[buf][n * SROWB + qt + 4];
            }
            #pragma unroll
            for (int mi = 0; mi < 4; ++mi)
                #pragma unroll
                for (int ni = 0; ni < 4; ++ni)
                    MMA_BF16(acc[mi][ni][0], acc[mi][ni][1], acc[mi][ni][2], acc[mi][ni][3],
                             af[mi][0], af[mi][1], af[mi][2], af[mi][3],
                             bfr[ni][0], bfr[ni][1]);
        }

        if (kt + 1 < HH / 16) {
            const int nb = buf ^ 1;
            uint2 u;
            u.x = pbf2(fmaxf(ar[0].x, 0.f), fmaxf(ar[0].y, 0.f));
            u.y = pbf2(fmaxf(ar[0].z, 0.f), fmaxf(ar[0].w, 0.f));
            *(uint2*)&As[nb][sm0 * SROWB + sw] = u;
            u.x = pbf2(fmaxf(ar[1].x, 0.f), fmaxf(ar[1].y, 0.f));
            u.y = pbf2(fmaxf(ar[1].z, 0.f), fmaxf(ar[1].w, 0.f));
            *(uint2*)&As[nb][sm1 * SROWB + sw] = u;
            u.x = pbf2(br[0].x, br[0].y); u.y = pbf2(br[0].z, br[0].w);
            *(uint2*)&Bs[nb][sm0 * SROWB + sw] = u;
            u.x = pbf2(br[1].x, br[1].y); u.y = pbf2(br[1].z, br[1].w);
            *(uint2*)&Bs[nb][sm1 * SROWB + sw] = u;
        }
        __syncthreads();
        buf ^= 1;
    }

    #pragma unroll
    for (int mi = 0; mi < 4; ++mi) {
        #pragma unroll
        for (int rr = 0; rr < 2; ++rr) {
            const int row = mtile + wm * 64 + mi * 16 + qg + rr * 8;   // m'
            const int n = (row & 63) * 128 + (row >> 6);               // out row
            #pragma unroll
            for (int ni = 0; ni < 4; ++ni) {
                #pragma unroll
                for (int cc = 0; cc < 2; ++cc) {
                    const int col = ntile + wn * 32 + ni * 8 + qt * 2 + cc;
                    if (col < VN)
                        out[(size_t)n * VN + col] = acc[mi][ni][rr * 2 + cc] + fb[col];
                    else if (col == VN)
                        out[K_LOC_ELEMS + n] = acc[mi][ni][rr * 2 + cc] + fb[col];
                }
            }
        }
    }
}

// ---------------------------------------------------------------------------
// Softmax: per-row log_softmax (row cached in smem, float4 I/O) + time sigmoid.
// ---------------------------------------------------------------------------
__global__ void __launch_bounds__(256)
k_softmax(float* __restrict__ out)
{
    extern __shared__ float row[];       // VN floats
    __shared__ float red[256];

    const int n = blockIdx.x;
    const int tid = threadIdx.x;
    float* base = out + (size_t)n * VN;
    const float4* b4 = (const float4*)base;
    float4* r4 = (float4*)row;
    const int NQ = VN / 4;               // 2500

    float mx = -1e30f;
    for (int i = tid; i < NQ; i += 256) {
        float4 v = b4[i];
        r4[i] = v;
        mx = fmaxf(mx, fmaxf(fmaxf(v.x, v.y), fmaxf(v.z, v.w)));
    }
    red[tid] = mx; __syncthreads();
    for (int s = 128; s > 0; s >>= 1) { if (tid < s) red[tid] = fmaxf(red[tid], red[tid + s]); __syncthreads(); }
    mx = red[0];
    __syncthreads();

    float sum = 0.f;
    for (int i = tid; i < NQ; i += 256) {
        float4 v = r4[i];
        sum += expf(v.x - mx) + expf(v.y - mx) + expf(v.z - mx) + expf(v.w - mx);
    }
    red[tid] = sum; __syncthreads();
    for (int s = 128; s > 0; s >>= 1) { if (tid < s) red[tid] += red[tid + s]; __syncthreads(); }
    float lse = mx + logf(red[0]);

    for (int i = tid; i < NQ; i += 256) {
        float4 v = r4[i];
        v.x -= lse; v.y -= lse; v.z -= lse; v.w -= lse;
        ((float4*)base)[i] = v;
    }

    if (tid == 0) {
        float tl = out[K_LOC_ELEMS + n];
        out[K_LOC_ELEMS + n] = 1.0f / (1.0f + expf(-tl));
    }
}

// ---------------------------------------------------------------------------
// Launch
// ---------------------------------------------------------------------------
extern "C" void kernel_launch(void* const* d_in, const int* in_sizes, int n_in,
                              void* d_out, int out_size)
{
    const int*   loc   = (const int*)  d_in[0];
    const float* times = (const float*)d_in[1];
    const float* emb   = (const float*)d_in[2];
    const float* w_ih0 = (const float*)d_in[3];
    const float* w_hh0 = (const float*)d_in[4];
    const float* b_ih0 = (const float*)d_in[5];
    const float* b_hh0 = (const float*)d_in[6];
    const float* w_ih1 = (const float*)d_in[7];
    const float* w_hh1 = (const float*)d_in[8];
    const float* b_ih1 = (const float*)d_in[9];
    const float* b_hh1 = (const float*)d_in[10];
    const float* fc_w  = (const float*)d_in[11];
    const float* fc_b  = (const float*)d_in[12];
    float* out = (float*)d_out;

    const int gru_smem = (NGR * SP3 + BH * SP3 + NGR * 33) * sizeof(float); // ~120 KB
    static int attr_done = 0;
    if (!attr_done) {
        cudaFuncSetAttribute(k_gru_tc, cudaFuncAttributeMaxDynamicSharedMemorySize, gru_smem);
        attr_done = 1;
    }

    // Layer 0
    k_proj0_tc<<<dim3(G3 / FBN, NR / FBM), 256>>>(loc, times, emb, w_ih0, b_ih0);
    k_zero_state<<<(BB * HH + 255) / 256, 256>>>();
    k_gru_tc<<<NCTA, 256, gru_smem>>>(w_hh0, b_hh0);

    // Layer 1
    k_proj1_tc<<<dim3(G3 / FBN, NR / FBM), 256>>>(w_ih1, b_ih1);
    k_zero_state<<<(BB * HH + 255) / 256, 256>>>();
    k_gru_tc<<<NCTA, 256, gru_smem>>>(w_hh1, b_hh1);

    // FC -> logits straight into d_out (tensor cores, bf16)
    k_fc_tc<<<dim3((VOUT + FBN - 1) / FBN, NR / FBM), 256>>>(fc_w, fc_b, out);

    // log_softmax + time sigmoid
    k_softmax<<<NR, 256, VN * sizeof(float)>>>(out);
}

// round 17
// speedup vs baseline: 3.1594x; 1.0126x over previous
#include <cuda_runtime.h>
#include <cuda_bf16.h>
#include <math.h>

// Problem constants
#define VN   10000
#define VOUT 10001
#define EE   256
#define HH   512
#define G3   1536
#define BB   64
#define TT   128
#define NR   8192            // BB*TT
#define K_LOC_ELEMS ((size_t)NR * VN)   // 81,920,000 floats of location logits

// Persistent recurrence config: 128 CTAs = 64 j-groups x 2 batch halves
#define NCTA 128
#define NHALF 64             // CTAs per independent batch-half chain
#define JH   8               // hidden dims per CTA
#define NGR  24              // gate rows per CTA (3 per dim)
#define BH   32              // batches per CTA
#define SP3  520             // frag-packed row stride (==8 mod 32: conflict-free)

// Tensor-core GEMM tiling (proj0/proj1 tf32)
#define FBM 128
#define FBN 128
#define FBK 16
#define SROW 20
// FC bf16 tiling
#define SROWB 12             // bf16x2 words per 16-k row (8 data + 4 pad); conflict-free frags

// Scratch (device globals; no allocations allowed)
// g_xp layout: [t][gate][j][b]  -> ((t*3+gate)*512 + j)*64 + b
__device__ float g_xp[(size_t)NR * G3];
// g_h layout: [m'=t*64+b][j]
__device__ float g_h [(size_t)NR * HH];
// bf16 copies for the FC GEMM (halved traffic)
__device__ __nv_bfloat16 g_hbf[(size_t)NR * HH];          // relu(g_h)
__device__ __nv_bfloat16 g_wbf[(size_t)VOUT * HH];        // fc_w
// packed state, PRODUCER-PERMUTED frag-pack layout: word at [b*512 + slot(k)]
__device__ unsigned g_state_p[BB * HH];
__device__ __align__(128) unsigned g_epochs[64];   // [0]=half0, [32]=half1 (separate lines)

__device__ __forceinline__ unsigned f2tf(float x) {
    unsigned u;
    asm("cvt.rna.tf32.f32 %0, %1;" : "=r"(u) : "f"(x));
    return u;
}

// pack two f32 -> bf16x2 (lo = first elem, hi = second)
__device__ __forceinline__ unsigned pbf2(float lo, float hi) {
    unsigned r;
    asm("cvt.rn.bf16x2.f32 %0, %1, %2;" : "=r"(r) : "f"(hi), "f"(lo));
    return r;
}

// pack state value: high 16 = bf16(s), low 16 = bf16(s - hi)
__device__ __forceinline__ unsigned pack_state(float s) {
    __nv_bfloat16 h = __float2bfloat16(s);
    float hf = __bfloat162float(h);
    __nv_bfloat16 l = __float2bfloat16(s - hf);
    return ((unsigned)__bfloat16_as_ushort(h) << 16) | (unsigned)__bfloat16_as_ushort(l);
}

#define MMA_TF32(c0,c1,c2,c3, a0,a1,a2,a3, b0,b1)                         \
    asm volatile(                                                          \
        "mma.sync.aligned.m16n8k8.row.col.f32.tf32.tf32.f32 "             \
        "{%0,%1,%2,%3}, {%4,%5,%6,%7}, {%8,%9}, {%0,%1,%2,%3};"           \
        : "+f"(c0), "+f"(c1), "+f"(c2), "+f"(c3)                           \
        : "r"(a0), "r"(a1), "r"(a2), "r"(a3), "r"(b0), "r"(b1))

#define MMA_BF16(c0,c1,c2,c3, a0,a1,a2,a3, b0,b1)                         \
    asm volatile(                                                          \
        "mma.sync.aligned.m16n8k16.row.col.f32.bf16.bf16.f32 "            \
        "{%0,%1,%2,%3}, {%4,%5,%6,%7}, {%8,%9}, {%0,%1,%2,%3};"           \
        : "+f"(c0), "+f"(c1), "+f"(c2), "+f"(c3)                           \
        : "r"(a0), "r"(a1), "r"(a2), "r"(a3), "r"(b0), "r"(b1))

// ---------------------------------------------------------------------------
__global__ void k_zero_state() {
    int i = blockIdx.x * blockDim.x + threadIdx.x;
    if (i < BB * HH) g_state_p[i] = 0u;
    if (i == 0) { g_epochs[0] = 0; g_epochs[32] = 0; }
}

// Half-grid barrier: release-arrive + acquire-poll (no MEMBAR.ALL.GPU).
__device__ __forceinline__ void half_bar(unsigned* ctr, unsigned target) {
    __syncthreads();
    if (threadIdx.x == 0) {
        asm volatile("red.release.gpu.add.u32 [%0], 1;" :: "l"(ctr) : "memory");
        unsigned v;
        do {
            asm volatile("ld.acquire.gpu.u32 %0, [%1];" : "=r"(v) : "l"(ctr) : "memory");
        } while (v < target);
    }
    __syncthreads();
}

// ---------------------------------------------------------------------------
// Pre-convert kernels for the FC GEMM (8 elems/thread)
// ---------------------------------------------------------------------------
__global__ void __launch_bounds__(256)
k_cvt_h()    // g_hbf = bf16(relu(g_h))
{
    const size_t i = ((size_t)blockIdx.x * 256 + threadIdx.x) * 8;
    if (i >= (size_t)NR * HH) return;
    float4 a = *(const float4*)&g_h[i];
    float4 b = *(const float4*)&g_h[i + 4];
    uint4 v;
    v.x = pbf2(fmaxf(a.x, 0.f), fmaxf(a.y, 0.f));
    v.y = pbf2(fmaxf(a.z, 0.f), fmaxf(a.w, 0.f));
    v.z = pbf2(fmaxf(b.x, 0.f), fmaxf(b.y, 0.f));
    v.w = pbf2(fmaxf(b.z, 0.f), fmaxf(b.w, 0.f));
    *(uint4*)&g_hbf[i] = v;
}

__global__ void __launch_bounds__(256)
k_cvt_w(const float* __restrict__ fw)    // g_wbf = bf16(fc_w)
{
    const size_t i = ((size_t)blockIdx.x * 256 + threadIdx.x) * 8;
    if (i >= (size_t)VOUT * HH) return;
    float4 a = *(const float4*)&fw[i];
    float4 b = *(const float4*)&fw[i + 4];
    uint4 v;
    v.x = pbf2(a.x, a.y);
    v.y = pbf2(a.z, a.w);
    v.z = pbf2(b.x, b.y);
    v.w = pbf2(b.z, b.w);
    *(uint4*)&g_wbf[i] = v;
}

// ---------------------------------------------------------------------------
// Persistent GRU via tf32 tensor cores (validated module, unchanged).
// ---------------------------------------------------------------------------
__global__ void __launch_bounds__(256)
k_gru_tc(const float* __restrict__ whh, const float* __restrict__ bhh)
{
    extern __shared__ float smem[];
    float*    Wh  = smem;                        // [24][520] tf32-rounded, frag-packed
    unsigned* SpU = (unsigned*)(Wh + NGR * SP3); // [32][520] packed state words
    float*    Cs  = (float*)(SpU + BH * SP3);    // [24][33]

    const int tid = threadIdx.x;
    const int cta = blockIdx.x;
    const int jg = cta >> 1, bhf = cta & 1;
    const int j0 = jg * JH;
    const int gb0 = bhf * BH;
    unsigned* ctr = &g_epochs[bhf * 32];

    // Load + round + pack weight tile once
    for (int i = tid; i < NGR * 512; i += 256) {
        const int g = i >> 9, k = i & 511;
        const int jj = g / 3, gate = g - 3 * (g / 3);
        float w = whh[(size_t)(gate * 512 + j0 + jj) * HH + k];
        const int slot = (k >> 3) * 8 + (k & 3) * 2 + ((k >> 2) & 1);
        Wh[g * SP3 + slot] = __uint_as_float(f2tf(w));
    }

    const int lane = tid & 31, warp = tid >> 5;
    const int qg = lane >> 2, qt = lane & 3;
    const int mi = warp >> 2, ni = warp & 3;
    const int m0 = mi * 8;
    const int n0 = ni * 8;

    // gate-phase coords: jj fast (8), bl slow (32) -> coalesced slot stores
    const int jj = tid & 7;
    const int bl = tid >> 3;
    const int gjg = j0 + jj;
    const int gb = gb0 + bl;
    const int hslot = (gjg >> 3) * 8 + (gjg & 3) * 2 + ((gjg >> 2) & 1);

    // biases: constant across steps
    const float bias_r = __ldg(&bhh[gjg]);
    const float bias_z = __ldg(&bhh[512 + gjg]);
    const float bias_n = __ldg(&bhh[1024 + gjg]);

    const float*    aP0 = &Wh[(m0 + qg) * SP3 + qt * 2];
    const float*    aP1 = &Wh[(m0 + 8 + qg) * SP3 + qt * 2];
    const unsigned* bP  = &SpU[(n0 + qg) * SP3 + qt * 2];

    unsigned target = NHALF;

    for (int t = 0; t < TT; ++t) {
        // Straight coalesced copy: global (already frag-packed) -> smem
        for (int i = tid; i < BH * 128; i += 256) {
            const int b = i >> 7, c = (i & 127) << 2;
            uint4 v = __ldcg((const uint4*)&g_state_p[(size_t)(gb0 + b) * HH + c]);
            *(uint4*)&SpU[b * SP3 + c] = v;
        }

        // Prefetch xp gate inputs (DRAM) so latency overlaps the mma phase
        const float xr = __ldg(&g_xp[((size_t)(t * 3 + 0) * 512 + gjg) * 64 + gb]);
        const float xz = __ldg(&g_xp[((size_t)(t * 3 + 1) * 512 + gjg) * 64 + gb]);
        const float xn = __ldg(&g_xp[((size_t)(t * 3 + 2) * 512 + gjg) * 64 + gb]);
        __syncthreads();

        // 2 independent accumulator chains: W_tf32 * (state_hi + state_lo)
        float h0=0.f,h1=0.f,h2=0.f,h3=0.f;     // W * hi
        float g0=0.f,g1=0.f,g2=0.f,g3=0.f;     // W * lo
        #pragma unroll 8
        for (int kt = 0; kt < 64; ++kt) {
            float2 aA = *(const float2*)(aP0 + kt * 8);   // a0 (k=qt), a2 (k=qt+4)
            float2 aB = *(const float2*)(aP1 + kt * 8);   // a1, a3
            uint2  bw = *(const uint2*)(bP  + kt * 8);    // packed s(qt), s(qt+4)
            unsigned bh0 = bw.x & 0xFFFF0000u;
            unsigned bl0 = bw.x << 16;
            unsigned bh1 = bw.y & 0xFFFF0000u;
            unsigned bl1 = bw.y << 16;
            MMA_TF32(h0, h1, h2, h3,
                     __float_as_uint(aA.x), __float_as_uint(aB.x),
                     __float_as_uint(aA.y), __float_as_uint(aB.y), bh0, bh1);
            MMA_TF32(g0, g1, g2, g3,
                     __float_as_uint(aA.x), __float_as_uint(aB.x),
                     __float_as_uint(aA.y), __float_as_uint(aB.y), bl0, bl1);
        }
        float c0 = h0 + g0;
        float c1 = h1 + g1;
        float c2 = h2 + g2;
        float c3 = h3 + g3;

        // Write C frags to Cs[gate_row][b]; mi=1 keeps only rows 16..23
        if (mi == 0) {
            Cs[qg * 33 + n0 + 2 * qt]         = c0;
            Cs[qg * 33 + n0 + 2 * qt + 1]     = c1;
            Cs[(qg + 8) * 33 + n0 + 2 * qt]   = c2;
            Cs[(qg + 8) * 33 + n0 + 2 * qt+1] = c3;
        } else {
            Cs[(16 + qg) * 33 + n0 + 2 * qt]     = c2;
            Cs[(16 + qg) * 33 + n0 + 2 * qt + 1] = c3;
        }
        __syncthreads();

        // Gate math
        {
            float sr = Cs[(jj * 3 + 0) * 33 + bl] + bias_r;
            float sz = Cs[(jj * 3 + 1) * 33 + bl] + bias_z;
            float sn = Cs[(jj * 3 + 2) * 33 + bl] + bias_n;

            float r  = 1.0f / (1.0f + expf(-(xr + sr)));
            float z  = 1.0f / (1.0f + expf(-(xz + sz)));
            float nn = tanhf(xn + r * sn);

            unsigned hw = SpU[bl * SP3 + hslot];
            float hold = __uint_as_float(hw & 0xFFFF0000u) + __uint_as_float(hw << 16);
            float hnew = (1.0f - z) * nn + z * hold;
            g_state_p[(size_t)gb * HH + hslot] = pack_state(hnew);   // producer-permuted
            g_h[((size_t)t * 64 + gb) * HH + gjg] = hnew;
        }

        half_bar(ctr, target);
        target += NHALF;
    }
}

// ---------------------------------------------------------------------------
// proj0 via tf32 TC (validated module, unchanged).
// ---------------------------------------------------------------------------
__global__ void __launch_bounds__(256)
k_proj0_tc(const int* __restrict__ loc, const float* __restrict__ times,
           const float* __restrict__ emb, const float* __restrict__ w0,
           const float* __restrict__ b0)
{
    __shared__ unsigned As[2][FBM * SROW];
    __shared__ unsigned Bs[2][FBN * SROW];
    __shared__ int locs[FBM];

    const int tid  = threadIdx.x;
    const int lane = tid & 31;
    const int warp = tid >> 5;
    const int wm = warp >> 2, wn = warp & 3;
    const int qg = lane >> 2, qt = lane & 3;

    const int mtile = blockIdx.y * FBM;
    const int ntile = blockIdx.x * FBN;

    if (tid < FBM) locs[tid] = loc[mtile + tid];
    __syncthreads();

    float acc[4][4][4];
    #pragma unroll
    for (int mi = 0; mi < 4; ++mi)
        #pragma unroll
        for (int ni = 0; ni < 4; ++ni)
            #pragma unroll
            for (int q = 0; q < 4; ++q) acc[mi][ni][q] = 0.0f;

    float4 ar[2], br[2];
    const int sm0 = tid >> 2, skq = (tid & 3) * 4;
    const int sm1 = (tid + 256) >> 2;
    const int rowA0 = locs[sm0], rowA1 = locs[sm1];
    const float* bptr0 = w0 + (size_t)(ntile + sm0) * 257;
    const float* bptr1 = w0 + (size_t)(ntile + sm1) * 257;

    {
        ar[0] = *(const float4*)&emb[(size_t)rowA0 * EE + skq];
        ar[1] = *(const float4*)&emb[(size_t)rowA1 * EE + skq];
        br[0].x = bptr0[skq]; br[0].y = bptr0[skq + 1]; br[0].z = bptr0[skq + 2]; br[0].w = bptr0[skq + 3];
        br[1].x = bptr1[skq]; br[1].y = bptr1[skq + 1]; br[1].z = bptr1[skq + 2]; br[1].w = bptr1[skq + 3];
    }
    {
        uint4 v;
        v.x = f2tf(ar[0].x); v.y = f2tf(ar[0].y); v.z = f2tf(ar[0].z); v.w = f2tf(ar[0].w);
        *(uint4*)&As[0][sm0 * SROW + skq] = v;
        v.x = f2tf(ar[1].x); v.y = f2tf(ar[1].y); v.z = f2tf(ar[1].z); v.w = f2tf(ar[1].w);
        *(uint4*)&As[0][sm1 * SROW + skq] = v;
        v.x = f2tf(br[0].x); v.y = f2tf(br[0].y); v.z = f2tf(br[0].z); v.w = f2tf(br[0].w);
        *(uint4*)&Bs[0][sm0 * SROW + skq] = v;
        v.x = f2tf(br[1].x); v.y = f2tf(br[1].y); v.z = f2tf(br[1].z); v.w = f2tf(br[1].w);
        *(uint4*)&Bs[0][sm1 * SROW + skq] = v;
    }
    __syncthreads();

    int buf = 0;
    const int NKT = EE / FBK;   // 16
    for (int kt = 0; kt < NKT; ++kt) {
        if (kt + 1 < NKT) {
            const int kk = (kt + 1) * FBK;
            ar[0] = *(const float4*)&emb[(size_t)rowA0 * EE + kk + skq];
            ar[1] = *(const float4*)&emb[(size_t)rowA1 * EE + kk + skq];
            br[0].x = bptr0[kk + skq]; br[0].y = bptr0[kk + skq + 1];
            br[0].z = bptr0[kk + skq + 2]; br[0].w = bptr0[kk + skq + 3];
            br[1].x = bptr1[kk + skq]; br[1].y = bptr1[kk + skq + 1];
            br[1].z = bptr1[kk + skq + 2]; br[1].w = bptr1[kk + skq + 3];
        }
        #pragma unroll
        for (int ks = 0; ks < FBK; ks += 8) {
            unsigned af[4][4];
            #pragma unroll
            for (int mi = 0; mi < 4; ++mi) {
                const int r = wm * 64 + mi * 16 + qg;
                af[mi][0] = As[buf][r * SROW + ks + qt];
                af[mi][1] = As[buf][(r + 8) * SROW + ks + qt];
                af[mi][2] = As[buf][r * SROW + ks + qt + 4];
                af[mi][3] = As[buf][(r + 8) * SROW + ks + qt + 4];
            }
            unsigned bf[4][2];
            #pragma unroll
            for (int ni = 0; ni < 4; ++ni) {
                const int n = wn * 32 + ni * 8 + qg;
                bf[ni][0] = Bs[buf][n * SROW + ks + qt];
                bf[ni][1] = Bs[buf][n * SROW + ks + qt + 4];
            }
            #pragma unroll
            for (int mi = 0; mi < 4; ++mi)
                #pragma unroll
                for (int ni = 0; ni < 4; ++ni)
                    MMA_TF32(acc[mi][ni][0], acc[mi][ni][1], acc[mi][ni][2], acc[mi][ni][3],
                             af[mi][0], af[mi][1], af[mi][2], af[mi][3],
                             bf[ni][0], bf[ni][1]);
        }
        if (kt + 1 < NKT) {
            const int nb = buf ^ 1;
            uint4 v;
            v.x = f2tf(ar[0].x); v.y = f2tf(ar[0].y); v.z = f2tf(ar[0].z); v.w = f2tf(ar[0].w);
            *(uint4*)&As[nb][sm0 * SROW + skq] = v;
            v.x = f2tf(ar[1].x); v.y = f2tf(ar[1].y); v.z = f2tf(ar[1].z); v.w = f2tf(ar[1].w);
            *(uint4*)&As[nb][sm1 * SROW + skq] = v;
            v.x = f2tf(br[0].x); v.y = f2tf(br[0].y); v.z = f2tf(br[0].z); v.w = f2tf(br[0].w);
            *(uint4*)&Bs[nb][sm0 * SROW + skq] = v;
            v.x = f2tf(br[1].x); v.y = f2tf(br[1].y); v.z = f2tf(br[1].z); v.w = f2tf(br[1].w);
            *(uint4*)&Bs[nb][sm1 * SROW + skq] = v;
        }
        __syncthreads();
        buf ^= 1;
    }

    // Epilogue -> transposed xp, + time * w0[:,256] + b0
    #pragma unroll
    for (int mi = 0; mi < 4; ++mi) {
        #pragma unroll
        for (int rr = 0; rr < 2; ++rr) {
            const int row = mtile + wm * 64 + mi * 16 + qg + rr * 8;   // n = b*128+t
            const int tt = row & 127, b = row >> 7;
            const float tm = __ldg(&times[row]);
            #pragma unroll
            for (int ni = 0; ni < 4; ++ni) {
                #pragma unroll
                for (int cc = 0; cc < 2; ++cc) {
                    const int col = ntile + wn * 32 + ni * 8 + qt * 2 + cc;
                    const int gate = col >> 9, jdim = col & 511;
                    g_xp[((size_t)(tt * 3 + gate) * 512 + jdim) * 64 + b] =
                        acc[mi][ni][rr * 2 + cc]
                        + tm * __ldg(&w0[(size_t)col * 257 + 256]) + __ldg(&b0[col]);
                }
            }
        }
    }
}

// ---------------------------------------------------------------------------
// proj1 via tf32 TC (validated module, unchanged).
// ---------------------------------------------------------------------------
__global__ void __launch_bounds__(256)
k_proj1_tc(const float* __restrict__ w1, const float* __restrict__ b1)
{
    __shared__ unsigned As[2][FBM * SROW];
    __shared__ unsigned Bs[2][FBN * SROW];

    const int tid  = threadIdx.x;
    const int lane = tid & 31;
    const int warp = tid >> 5;
    const int wm = warp >> 2, wn = warp & 3;
    const int qg = lane >> 2, qt = lane & 3;

    const int mtile = blockIdx.y * FBM;
    const int ntile = blockIdx.x * FBN;

    float acc[4][4][4];
    #pragma unroll
    for (int mi = 0; mi < 4; ++mi)
        #pragma unroll
        for (int ni = 0; ni < 4; ++ni)
            #pragma unroll
            for (int q = 0; q < 4; ++q) acc[mi][ni][q] = 0.0f;

    float4 ar[2], br[2];
    const int sm0 = tid >> 2, skq = (tid & 3) * 4;
    const int sm1 = (tid + 256) >> 2;

    {
        ar[0] = *(const float4*)&g_h[(size_t)(mtile + sm0) * HH + skq];
        ar[1] = *(const float4*)&g_h[(size_t)(mtile + sm1) * HH + skq];
        br[0] = *(const float4*)&w1[(size_t)(ntile + sm0) * HH + skq];
        br[1] = *(const float4*)&w1[(size_t)(ntile + sm1) * HH + skq];
    }
    {
        uint4 v;
        v.x = f2tf(ar[0].x); v.y = f2tf(ar[0].y); v.z = f2tf(ar[0].z); v.w = f2tf(ar[0].w);
        *(uint4*)&As[0][sm0 * SROW + skq] = v;
        v.x = f2tf(ar[1].x); v.y = f2tf(ar[1].y); v.z = f2tf(ar[1].z); v.w = f2tf(ar[1].w);
        *(uint4*)&As[0][sm1 * SROW + skq] = v;
        v.x = f2tf(br[0].x); v.y = f2tf(br[0].y); v.z = f2tf(br[0].z); v.w = f2tf(br[0].w);
        *(uint4*)&Bs[0][sm0 * SROW + skq] = v;
        v.x = f2tf(br[1].x); v.y = f2tf(br[1].y); v.z = f2tf(br[1].z); v.w = f2tf(br[1].w);
        *(uint4*)&Bs[0][sm1 * SROW + skq] = v;
    }
    __syncthreads();

    int buf = 0;
    for (int kt = 0; kt < HH / FBK; ++kt) {
        if (kt + 1 < HH / FBK) {
            const int kk = (kt + 1) * FBK;
            ar[0] = *(const float4*)&g_h[(size_t)(mtile + sm0) * HH + kk + skq];
            ar[1] = *(const float4*)&g_h[(size_t)(mtile + sm1) * HH + kk + skq];
            br[0] = *(const float4*)&w1[(size_t)(ntile + sm0) * HH + kk + skq];
            br[1] = *(const float4*)&w1[(size_t)(ntile + sm1) * HH + kk + skq];
        }
        #pragma unroll
        for (int ks = 0; ks < FBK; ks += 8) {
            unsigned af[4][4];
            #pragma unroll
            for (int mi = 0; mi < 4; ++mi) {
                const int r = wm * 64 + mi * 16 + qg;
                af[mi][0] = As[buf][r * SROW + ks + qt];
                af[mi][1] = As[buf][(r + 8) * SROW + ks + qt];
                af[mi][2] = As[buf][r * SROW + ks + qt + 4];
                af[mi][3] = As[buf][(r + 8) * SROW + ks + qt + 4];
            }
            unsigned bf[4][2];
            #pragma unroll
            for (int ni = 0; ni < 4; ++ni) {
                const int n = wn * 32 + ni * 8 + qg;
                bf[ni][0] = Bs[buf][n * SROW + ks + qt];
                bf[ni][1] = Bs[buf][n * SROW + ks + qt + 4];
            }
            #pragma unroll
            for (int mi = 0; mi < 4; ++mi)
                #pragma unroll
                for (int ni = 0; ni < 4; ++ni)
                    MMA_TF32(acc[mi][ni][0], acc[mi][ni][1], acc[mi][ni][2], acc[mi][ni][3],
                             af[mi][0], af[mi][1], af[mi][2], af[mi][3],
                             bf[ni][0], bf[ni][1]);
        }
        if (kt + 1 < HH / FBK) {
            const int nb = buf ^ 1;
            uint4 v;
            v.x = f2tf(ar[0].x); v.y = f2tf(ar[0].y); v.z = f2tf(ar[0].z); v.w = f2tf(ar[0].w);
            *(uint4*)&As[nb][sm0 * SROW + skq] = v;
            v.x = f2tf(ar[1].x); v.y = f2tf(ar[1].y); v.z = f2tf(ar[1].z); v.w = f2tf(ar[1].w);
            *(uint4*)&As[nb][sm1 * SROW + skq] = v;
            v.x = f2tf(br[0].x); v.y = f2tf(br[0].y); v.z = f2tf(br[0].z); v.w = f2tf(br[0].w);
            *(uint4*)&Bs[nb][sm0 * SROW + skq] = v;
            v.x = f2tf(br[1].x); v.y = f2tf(br[1].y); v.z = f2tf(br[1].z); v.w = f2tf(br[1].w);
            *(uint4*)&Bs[nb][sm1 * SROW + skq] = v;
        }
        __syncthreads();
        buf ^= 1;
    }

    // Epilogue -> transposed xp
    #pragma unroll
    for (int mi = 0; mi < 4; ++mi) {
        #pragma unroll
        for (int rr = 0; rr < 2; ++rr) {
            const int row = mtile + wm * 64 + mi * 16 + qg + rr * 8;   // m' = t*64+b
            const int tt = row >> 6, b = row & 63;
            #pragma unroll
            for (int ni = 0; ni < 4; ++ni) {
                #pragma unroll
                for (int cc = 0; cc < 2; ++cc) {
                    const int col = ntile + wn * 32 + ni * 8 + qt * 2 + cc;
                    const int gate = col >> 9, jdim = col & 511;
                    g_xp[((size_t)(tt * 3 + gate) * 512 + jdim) * 64 + b] =
                        acc[mi][ni][rr * 2 + cc] + b1[col];
                }
            }
        }
    }
}

// ---------------------------------------------------------------------------
// FC via bf16 TC (m16n8k16), inputs pre-converted to bf16 in g_hbf/g_wbf.
// Staging is a straight 16B copy per operand per kt.
// ---------------------------------------------------------------------------
__global__ void __launch_bounds__(256)
k_fc_tc(const float* __restrict__ fb, float* __restrict__ out)
{
    __shared__ unsigned As[2][FBM * SROWB];
    __shared__ unsigned Bs[2][FBN * SROWB];

    const int tid  = threadIdx.x;
    const int lane = tid & 31;
    const int warp = tid >> 5;
    const int wm = warp >> 2, wn = warp & 3;
    const int qg = lane >> 2, qt = lane & 3;

    const int mtile = blockIdx.y * FBM;
    const int ntile = blockIdx.x * FBN;

    float acc[4][4][4];
    #pragma unroll
    for (int mi = 0; mi < 4; ++mi)
        #pragma unroll
        for (int ni = 0; ni < 4; ++ni)
            #pragma unroll
            for (int q = 0; q < 4; ++q) acc[mi][ni][q] = 0.0f;

    // staging: 2 threads per row; each copies 8 bf16 = 16B
    const int sm = tid >> 1;               // 0..127 row
    const int hf = (tid & 1) * 8;          // bf16 offset within 16-k row
    const int hw4 = (tid & 1) * 4;         // word offset within smem row
    const int brow = (ntile + sm > VN) ? VN : ntile + sm;

    const __nv_bfloat16* aRow = &g_hbf[(size_t)(mtile + sm) * HH + hf];
    const __nv_bfloat16* bRow = &g_wbf[(size_t)brow * HH + hf];

    uint4 av, bv;
    av = *(const uint4*)aRow;
    bv = *(const uint4*)bRow;
    *(uint4*)&As[0][sm * SROWB + hw4] = av;
    *(uint4*)&Bs[0][sm * SROWB + hw4] = bv;
    __syncthreads();

    int buf = 0;
    for (int kt = 0; kt < HH / 16; ++kt) {
        if (kt + 1 < HH / 16) {
            const int kk = (kt + 1) * 16;
            av = *(const uint4*)(aRow + kk);
            bv = *(const uint4*)(bRow + kk);
        }

        {
            unsigned af[4][4];
            #pragma unroll
            for (int mi = 0; mi < 4; ++mi) {
                const int r = wm * 64 + mi * 16 + qg;
                af[mi][0] = As[buf][r * SROWB + qt];
                af[mi][1] = As[buf][(r + 8) * SROWB + qt];
                af[mi][2] = As[buf][r * SROWB + qt + 4];
                af[mi][3] = As[buf][(r + 8) * SROWB + qt + 4];
            }
            unsigned bfr[4][2];
            #pragma unroll
            for (int ni = 0; ni < 4; ++ni) {
                const int n = wn * 32 + ni * 8 + qg;
                bfr[ni][0] = Bs[buf][n * SROWB + qt];
                bfr[ni][1] = Bs[buf][n * SROWB + qt + 4];
            }
            #pragma unroll
            for (int mi = 0; mi < 4; ++mi)
                #pragma unroll
                for (int ni = 0; ni < 4; ++ni)
                    MMA_BF16(acc[mi][ni][0], acc[mi][ni][1], acc[mi][ni][2], acc[mi][ni][3],
                             af[mi][0], af[mi][1], af[mi][2], af[mi][3],
                             bfr[ni][0], bfr[ni][1]);
        }

        if (kt + 1 < HH / 16) {
            const int nb = buf ^ 1;
            *(uint4*)&As[nb][sm * SROWB + hw4] = av;
            *(uint4*)&Bs[nb][sm * SROWB + hw4] = bv;
        }
        __syncthreads();
        buf ^= 1;
    }

    #pragma unroll
    for (int mi = 0; mi < 4; ++mi) {
        #pragma unroll
        for (int rr = 0; rr < 2; ++rr) {
            const int row = mtile + wm * 64 + mi * 16 + qg + rr * 8;   // m'
            const int n = (row & 63) * 128 + (row >> 6);               // out row
            #pragma unroll
            for (int ni = 0; ni < 4; ++ni) {
                #pragma unroll
                for (int cc = 0; cc < 2; ++cc) {
                    const int col = ntile + wn * 32 + ni * 8 + qt * 2 + cc;
                    if (col < VN)
                        out[(size_t)n * VN + col] = acc[mi][ni][rr * 2 + cc] + fb[col];
                    else if (col == VN)
                        out[K_LOC_ELEMS + n] = acc[mi][ni][rr * 2 + cc] + fb[col];
                }
            }
        }
    }
}

// ---------------------------------------------------------------------------
// Softmax: per-row log_softmax (row cached in smem, float4 I/O) + time sigmoid.
// ---------------------------------------------------------------------------
__global__ void __launch_bounds__(256)
k_softmax(float* __restrict__ out)
{
    extern __shared__ float row[];       // VN floats
    __shared__ float red[256];

    const int n = blockIdx.x;
    const int tid = threadIdx.x;
    float* base = out + (size_t)n * VN;
    const float4* b4 = (const float4*)base;
    float4* r4 = (float4*)row;
    const int NQ = VN / 4;               // 2500

    float mx = -1e30f;
    for (int i = tid; i < NQ; i += 256) {
        float4 v = b4[i];
        r4[i] = v;
        mx = fmaxf(mx, fmaxf(fmaxf(v.x, v.y), fmaxf(v.z, v.w)));
    }
    red[tid] = mx; __syncthreads();
    for (int s = 128; s > 0; s >>= 1) { if (tid < s) red[tid] = fmaxf(red[tid], red[tid + s]); __syncthreads(); }
    mx = red[0];
    __syncthreads();

    float sum = 0.f;
    for (int i = tid; i < NQ; i += 256) {
        float4 v = r4[i];
        sum += expf(v.x - mx) + expf(v.y - mx) + expf(v.z - mx) + expf(v.w - mx);
    }
    red[tid] = sum; __syncthreads();
    for (int s = 128; s > 0; s >>= 1) { if (tid < s) red[tid] += red[tid + s]; __syncthreads(); }
    float lse = mx + logf(red[0]);

    for (int i = tid; i < NQ; i += 256) {
        float4 v = r4[i];
        v.x -= lse; v.y -= lse; v.z -= lse; v.w -= lse;
        ((float4*)base)[i] = v;
    }

    if (tid == 0) {
        float tl = out[K_LOC_ELEMS + n];
        out[K_LOC_ELEMS + n] = 1.0f / (1.0f + expf(-tl));
    }
}

// ---------------------------------------------------------------------------
// Launch
// ---------------------------------------------------------------------------
extern "C" void kernel_launch(void* const* d_in, const int* in_sizes, int n_in,
                              void* d_out, int out_size)
{
    const int*   loc   = (const int*)  d_in[0];
    const float* times = (const float*)d_in[1];
    const float* emb   = (const float*)d_in[2];
    const float* w_ih0 = (const float*)d_in[3];
    const float* w_hh0 = (const float*)d_in[4];
    const float* b_ih0 = (const float*)d_in[5];
    const float* b_hh0 = (const float*)d_in[6];
    const float* w_ih1 = (const float*)d_in[7];
    const float* w_hh1 = (const float*)d_in[8];
    const float* b_ih1 = (const float*)d_in[9];
    const float* b_hh1 = (const float*)d_in[10];
    const float* fc_w  = (const float*)d_in[11];
    const float* fc_b  = (const float*)d_in[12];
    float* out = (float*)d_out;

    const int gru_smem = (NGR * SP3 + BH * SP3 + NGR * 33) * sizeof(float); // ~120 KB
    static int attr_done = 0;
    if (!attr_done) {
        cudaFuncSetAttribute(k_gru_tc, cudaFuncAttributeMaxDynamicSharedMemorySize, gru_smem);
        attr_done = 1;
    }

    // fc_w -> bf16 early (off the dependent path tail)
    {
        const size_t nw = (size_t)VOUT * HH;
        k_cvt_w<<<(int)((nw / 8 + 255) / 256), 256>>>(fc_w);
    }

    // Layer 0
    k_proj0_tc<<<dim3(G3 / FBN, NR / FBM), 256>>>(loc, times, emb, w_ih0, b_ih0);
    k_zero_state<<<(BB * HH + 255) / 256, 256>>>();
    k_gru_tc<<<NCTA, 256, gru_smem>>>(w_hh0, b_hh0);

    // Layer 1
    k_proj1_tc<<<dim3(G3 / FBN, NR / FBM), 256>>>(w_ih1, b_ih1);
    k_zero_state<<<(BB * HH + 255) / 256, 256>>>();
    k_gru_tc<<<NCTA, 256, gru_smem>>>(w_hh1, b_hh1);

    // relu(g_h) -> bf16
    {
        const size_t nh = (size_t)NR * HH;
        k_cvt_h<<<(int)((nh / 8 + 255) / 256), 256>>>();
    }

    // FC -> logits straight into d_out (tensor cores, bf16, preconverted inputs)
    k_fc_tc<<<dim3((VOUT + FBN - 1) / FBN, NR / FBM), 256>>>(fc_b, out);

    // log_softmax + time sigmoid
    k_softmax<<<NR, 256, VN * sizeof(float)>>>(out);
}